// round 8
// baseline (speedup 1.0000x reference)
#include <cuda_runtime.h>
#include <cuda_bf16.h>
#include <cuda_fp16.h>
#include <cstdint>
#include <math.h>

// Problem constants
#define B_  2
#define S_  2048
#define HID 2048
#define NH  16
#define HD  128
#define HALF 64
#define ROWS (B_ * S_)            // 4096
#define QKV_W (3 * HID)           // 6144
#define EPS 1e-5f
#define SCALE 0.08838834764831845f   // 1/sqrt(128)

// Scratch (device-global; no runtime allocation allowed)
__device__ float g_qkv[(size_t)ROWS * QKV_W];            // gemm1 out (fp32)
__device__ float g_cos[S_ * HALF];
__device__ float g_sin[S_ * HALF];
__device__ __half g_a_hi[(size_t)ROWS * HID];            // gemm A hi plane (x; then O)
__device__ __half g_a_lo[(size_t)ROWS * HID];
__device__ __half g_b_hi[(size_t)QKV_W * HID];           // gemm B hi plane (w_in; then w_out)
__device__ __half g_b_lo[(size_t)QKV_W * HID];
__device__ __nv_bfloat16 g_q_hi[(size_t)ROWS * HID];
__device__ __nv_bfloat16 g_q_lo[(size_t)ROWS * HID];
__device__ __nv_bfloat16 g_k_hi[(size_t)ROWS * HID];
__device__ __nv_bfloat16 g_k_lo[(size_t)ROWS * HID];
__device__ __nv_bfloat16 g_vt_hi[(size_t)ROWS * HID];    // [b][h][d][s]
__device__ __nv_bfloat16 g_vt_lo[(size_t)ROWS * HID];

__device__ __forceinline__ uint32_t smem_u32(const void* p) {
    uint32_t a;
    asm("{ .reg .u64 t; cvta.to.shared.u64 t, %1; cvt.u32.u64 %0, t; }" : "=r"(a) : "l"(p));
    return a;
}
#define SWZ(x) ((x) ^ (((x) >> 3) & 0x70))

__device__ __forceinline__ void ldsm_x4(uint32_t* r, uint32_t addr) {
    asm volatile("ldmatrix.sync.aligned.m8n8.x4.shared.b16 {%0,%1,%2,%3}, [%4];"
                 : "=r"(r[0]), "=r"(r[1]), "=r"(r[2]), "=r"(r[3]) : "r"(addr));
}
// bf16 in, f32 acc (attention)
__device__ __forceinline__ void mma_bf16(float* c, const uint32_t* a,
                                         uint32_t b0, uint32_t b1) {
    asm volatile(
        "mma.sync.aligned.m16n8k16.row.col.f32.bf16.bf16.f32 "
        "{%0,%1,%2,%3}, {%4,%5,%6,%7}, {%8,%9}, {%0,%1,%2,%3};"
        : "+f"(c[0]), "+f"(c[1]), "+f"(c[2]), "+f"(c[3])
        : "r"(a[0]), "r"(a[1]), "r"(a[2]), "r"(a[3]), "r"(b0), "r"(b1));
}
// fp16 in, f32 acc (gemm main term)
__device__ __forceinline__ void mma_f16f32(float* c, const uint32_t* a,
                                           uint32_t b0, uint32_t b1) {
    asm volatile(
        "mma.sync.aligned.m16n8k16.row.col.f32.f16.f16.f32 "
        "{%0,%1,%2,%3}, {%4,%5,%6,%7}, {%8,%9}, {%0,%1,%2,%3};"
        : "+f"(c[0]), "+f"(c[1]), "+f"(c[2]), "+f"(c[3])
        : "r"(a[0]), "r"(a[1]), "r"(a[2]), "r"(a[3]), "r"(b0), "r"(b1));
}
// fp16 in, f16 acc (gemm correction terms; c = 2x f16x2 regs)
__device__ __forceinline__ void mma_f16f16(uint32_t* c, const uint32_t* a,
                                           uint32_t b0, uint32_t b1) {
    asm volatile(
        "mma.sync.aligned.m16n8k16.row.col.f16.f16.f16.f16 "
        "{%0,%1}, {%2,%3,%4,%5}, {%6,%7}, {%0,%1};"
        : "+r"(c[0]), "+r"(c[1])
        : "r"(a[0]), "r"(a[1]), "r"(a[2]), "r"(a[3]), "r"(b0), "r"(b1));
}
__device__ __forceinline__ uint32_t pack_bf16x2(float lo, float hi) {
    uint32_t r;
    asm("cvt.rn.bf16x2.f32 %0, %1, %2;" : "=r"(r) : "f"(hi), "f"(lo));
    return r;
}
__device__ __forceinline__ uint32_t pack_h2(float lo, float hi) {
    __half2 h = __floats2half2_rn(lo, hi);
    return *(uint32_t*)&h;
}

// ---------------------------------------------------------------------------
// RoPE table
// ---------------------------------------------------------------------------
__global__ void rope_table_kernel() {
    int idx = blockIdx.x * blockDim.x + threadIdx.x;
    if (idx >= S_ * HALF) return;
    int s = idx >> 6;
    int j = idx & 63;
    float freq = powf(10000.0f, -(float)j * (1.0f / 64.0f));
    float sn, cs;
    sincosf((float)s * freq, &sn, &cs);
    g_cos[idx] = cs;
    g_sin[idx] = sn;
}

// ---------------------------------------------------------------------------
// fp16 hi/lo split: fp32 -> two fp16 planes (flat)
// ---------------------------------------------------------------------------
__global__ void __launch_bounds__(256) split2h_kernel(
    const float* __restrict__ src, __half* __restrict__ hi,
    __half* __restrict__ lo, int n4)
{
    int i = blockIdx.x * blockDim.x + threadIdx.x;
    if (i >= n4) return;
    float4 v = ((const float4*)src)[i];
    float vv[4] = {v.x, v.y, v.z, v.w};
    uint64_t hp = 0, lp = 0;
#pragma unroll
    for (int q = 0; q < 4; q++) {
        __half h = __float2half_rn(vv[q]);
        __half l = __float2half_rn(vv[q] - __half2float(h));
        hp |= (uint64_t)__half_as_ushort(h) << (q * 16);
        lp |= (uint64_t)__half_as_ushort(l) << (q * 16);
    }
    *(uint64_t*)(hi + (size_t)i * 4) = hp;
    *(uint64_t*)(lo + (size_t)i * 4) = lp;
}

// ---------------------------------------------------------------------------
// 3-term fp16 split GEMM: C = Ah*Bh^T (f32 acc) + [Al*Bh^T + Ah*Bl^T] (f16 acc)
// Tile 128x128, BK=64, 3-stage cp.async (64KB/stage), 512 thr,
// 16 warps 4x4, warp tile 32x32.
// ---------------------------------------------------------------------------
#define BM 128
#define BN 128
#define BK 64
#define NK2 (HID / BK)            // 32
#define SAH 0
#define SAL 16384
#define SBH 32768
#define SBL 49152
#define STG3 65536
#define GEMM_SMEM (3 * STG3)      // 196608

__global__ void __launch_bounds__(512, 1) gemm_h3(
    const __half* __restrict__ Ah, const __half* __restrict__ Al,
    const __half* __restrict__ Bh, const __half* __restrict__ Bl,
    float* __restrict__ C, int M, int N)
{
    extern __shared__ char smem[];
    const uint32_t sb = smem_u32(smem);
    const int tid = threadIdx.x;
    const int wid = tid >> 5, lid = tid & 31;
    const int tiles_m = M / BM;
    const int m0 = (blockIdx.x % tiles_m) * BM;
    const int n0 = (blockIdx.x / tiles_m) * BN;
    const int wm = (wid & 3) * 32;
    const int wn = (wid >> 2) * 32;
    const int lrow = lid & 15;
    const int lhi = (lid >> 4) * 16;

#define LOAD_H3(st, kt) do {                                                   \
    uint32_t sbase = sb + (st) * STG3;                                         \
    _Pragma("unroll")                                                          \
    for (int u = 0; u < 8; u++) {                                              \
        int c = tid + u * 512;                                                 \
        const __half* gp;                                                      \
        uint32_t dst;                                                          \
        if (c < 2048) {                                                        \
            int plane = c >> 10;                                               \
            int cc = c & 1023;                                                 \
            int r = cc >> 3, c16 = cc & 7;                                     \
            gp = (plane ? Al : Ah) + (size_t)(m0 + r) * HID + (kt) * BK + c16 * 8; \
            dst = sbase + (plane ? SAL : SAH) + SWZ(r * 128 + c16 * 16);       \
        } else {                                                               \
            int cc = c - 2048;                                                 \
            int plane = cc >> 10;                                              \
            int c2 = cc & 1023;                                                \
            int r = c2 >> 3, c16 = c2 & 7;                                     \
            gp = (plane ? Bl : Bh) + (size_t)(n0 + r) * HID + (kt) * BK + c16 * 8; \
            dst = sbase + (plane ? SBL : SBH) + SWZ(r * 128 + c16 * 16);       \
        }                                                                      \
        asm volatile("cp.async.cg.shared.global [%0], [%1], 16;"               \
                     :: "r"(dst), "l"(gp) : "memory");                         \
    }                                                                          \
} while (0)

    LOAD_H3(0, 0);
    asm volatile("cp.async.commit_group;" ::: "memory");
    LOAD_H3(1, 1);
    asm volatile("cp.async.commit_group;" ::: "memory");

    float accF[2][4][4];
    uint32_t accC[2][4][2];
#pragma unroll
    for (int mt = 0; mt < 2; mt++)
#pragma unroll
        for (int nt = 0; nt < 4; nt++) {
#pragma unroll
            for (int q = 0; q < 4; q++) accF[mt][nt][q] = 0.0f;
            accC[mt][nt][0] = 0u; accC[mt][nt][1] = 0u;
        }

    for (int kt = 0; kt < NK2; kt++) {
        if (kt + 2 < NK2) LOAD_H3((kt + 2) % 3, kt + 2);
        asm volatile("cp.async.commit_group;" ::: "memory");
        asm volatile("cp.async.wait_group 2;" ::: "memory");
        __syncthreads();

        const uint32_t sbase = sb + (kt % 3) * STG3;

#pragma unroll
        for (int ks = 0; ks < 4; ks++) {
            const int cb = ks * 32 + lhi;
            uint32_t ahf[2][4], alf[2][4];
#pragma unroll
            for (int mt = 0; mt < 2; mt++) {
                int row = wm + mt * 16 + lrow;
                uint32_t off = row * 128 + (cb ^ ((row & 7) * 16));
                ldsm_x4(ahf[mt], sbase + SAH + off);
                ldsm_x4(alf[mt], sbase + SAL + off);
            }
#pragma unroll
            for (int np = 0; np < 2; np++) {
                int brow = wn + np * 16 + lrow;
                uint32_t boff = brow * 128 + (cb ^ ((brow & 7) * 16));
                uint32_t bh4[4], bl4[4];
                ldsm_x4(bh4, sbase + SBH + boff);
                ldsm_x4(bl4, sbase + SBL + boff);
#pragma unroll
                for (int mt = 0; mt < 2; mt++) {
                    mma_f16f32(accF[mt][np * 2 + 0], ahf[mt], bh4[0], bh4[2]);
                    mma_f16f32(accF[mt][np * 2 + 1], ahf[mt], bh4[1], bh4[3]);
                    mma_f16f16(accC[mt][np * 2 + 0], alf[mt], bh4[0], bh4[2]);
                    mma_f16f16(accC[mt][np * 2 + 1], alf[mt], bh4[1], bh4[3]);
                    mma_f16f16(accC[mt][np * 2 + 0], ahf[mt], bl4[0], bl4[2]);
                    mma_f16f16(accC[mt][np * 2 + 1], ahf[mt], bl4[1], bl4[3]);
                }
            }
        }
        __syncthreads();
    }

    const int er = m0 + wm + (lid >> 2);
    const int ec = n0 + wn + (lid & 3) * 2;
#pragma unroll
    for (int mt = 0; mt < 2; mt++)
#pragma unroll
        for (int nt = 0; nt < 4; nt++) {
            float2 c01 = __half22float2(*(__half2*)&accC[mt][nt][0]);  // row er
            float2 c23 = __half22float2(*(__half2*)&accC[mt][nt][1]);  // row er+8
            float* p0 = C + (size_t)(er + mt * 16) * N + ec + nt * 8;
            *(float2*)p0 = make_float2(accF[mt][nt][0] + c01.x,
                                       accF[mt][nt][1] + c01.y);
            float* p1 = p0 + 8 * N;
            *(float2*)p1 = make_float2(accF[mt][nt][2] + c23.x,
                                       accF[mt][nt][3] + c23.y);
        }
#undef LOAD_H3
}

// ---------------------------------------------------------------------------
// Fused qk RMSNorm + RoPE -> bf16 hi/lo planes. Q scaled by 1/sqrt(HD).
// ---------------------------------------------------------------------------
__global__ void __launch_bounds__(256) normrope_kernel(
    const float* __restrict__ qkv,
    const float* __restrict__ nw_q, const float* __restrict__ nw_k,
    __nv_bfloat16* __restrict__ qh, __nv_bfloat16* __restrict__ ql,
    __nv_bfloat16* __restrict__ kh, __nv_bfloat16* __restrict__ kl)
{
    __shared__ float buf[HID];
    __shared__ float warpred[8];

    const int row = blockIdx.x;
    const int s = row & (S_ - 1);
    const int tid = threadIdx.x;

#pragma unroll
    for (int part = 0; part < 2; part++) {
        const float* src = qkv + (size_t)row * QKV_W + part * HID;
        const float* w = (part == 0) ? nw_q : nw_k;
        __nv_bfloat16* dh = (part == 0) ? qh : kh;
        __nv_bfloat16* dl = (part == 0) ? ql : kl;

        float ss = 0.0f;
#pragma unroll
        for (int u = 0; u < 8; u++) {
            int idx = tid + u * 256;
            float v = src[idx];
            buf[idx] = v;
            ss += v * v;
        }
#pragma unroll
        for (int o = 16; o; o >>= 1) ss += __shfl_xor_sync(0xffffffffu, ss, o);
        if ((tid & 31) == 0) warpred[tid >> 5] = ss;
        __syncthreads();
        float tot = 0.0f;
#pragma unroll
        for (int wi = 0; wi < 8; wi++) tot += warpred[wi];
        float rn = rsqrtf(tot * (1.0f / (float)HID) + EPS);
        if (part == 0) rn *= SCALE;

#pragma unroll
        for (int u = 0; u < 4; u++) {
            int p = tid + u * 256;
            int hh = p >> 6;
            int j = p & 63;
            int i1 = hh * HD + j;
            int i2 = i1 + HALF;
            float x1 = buf[i1] * rn * w[i1];
            float x2 = buf[i2] * rn * w[i2];
            float cs = g_cos[s * HALF + j];
            float sn = g_sin[s * HALF + j];
            float o1 = x1 * cs - x2 * sn;
            float o2 = x2 * cs + x1 * sn;
            __nv_bfloat16 h1 = __float2bfloat16(o1);
            __nv_bfloat16 h2 = __float2bfloat16(o2);
            size_t base = (size_t)row * HID;
            dh[base + i1] = h1;
            dh[base + i2] = h2;
            dl[base + i1] = __float2bfloat16(o1 - __bfloat162float(h1));
            dl[base + i2] = __float2bfloat16(o2 - __bfloat162float(h2));
        }
        __syncthreads();
    }
}

// ---------------------------------------------------------------------------
// V transpose + split: g_qkv v cols -> vt_hi/vt_lo [b][h][d][s]
// ---------------------------------------------------------------------------
__global__ void __launch_bounds__(256) vtrans_kernel(
    const float* __restrict__ qkv,
    __nv_bfloat16* __restrict__ vth, __nv_bfloat16* __restrict__ vtl)
{
    __shared__ float t[32][33];
    const int row0 = blockIdx.x * 32;
    const int col0 = blockIdx.y * 32;
    const int tx = threadIdx.x & 31;
    const int ty = threadIdx.x >> 5;
#pragma unroll
    for (int i = 0; i < 4; i++) {
        int r = ty + i * 8;
        t[r][tx] = qkv[(size_t)(row0 + r) * QKV_W + 2 * HID + col0 + tx];
    }
    __syncthreads();
    const int b = row0 >> 11;
    const int s0 = row0 & 2047;
#pragma unroll
    for (int i = 0; i < 4; i++) {
        int c = ty + i * 8;
        float v = t[tx][c];
        __nv_bfloat16 h = __float2bfloat16(v);
        size_t o = ((size_t)(b * 2048 + col0 + c)) * 2048 + s0 + tx;
        vth[o] = h;
        vtl[o] = __float2bfloat16(v - __bfloat162float(h));
    }
}

// ---------------------------------------------------------------------------
// Flash attention, bf16 mma.sync, 3-term split with hoisted fragment reuse.
// Block: 128 q rows x one (b,h). 8 warps. 2-stage KV pipeline.
// Output -> fp16 g_a_hi / g_a_lo planes (gemm2 A operand).
// ---------------------------------------------------------------------------
#define SQH 0
#define SQL 32768
#define SKH(s) (65536 + (s) * 65536)
#define SKL(s) (SKH(s) + 16384)
#define SVH(s) (SKH(s) + 32768)
#define SVL(s) (SKH(s) + 49152)
#define ATTN_SMEM (65536 + 2 * 65536)   // 196608

__global__ void __launch_bounds__(256, 1) attn_mma(
    const __nv_bfloat16* __restrict__ qh, const __nv_bfloat16* __restrict__ ql,
    const __nv_bfloat16* __restrict__ kh, const __nv_bfloat16* __restrict__ kl,
    const __nv_bfloat16* __restrict__ vth, const __nv_bfloat16* __restrict__ vtl,
    __half* __restrict__ ohi, __half* __restrict__ olo)
{
    extern __shared__ char smem[];
    const uint32_t sb = smem_u32(smem);
    const int tid = threadIdx.x;
    const int wid = tid >> 5, lid = tid & 31;
    const int lrow = lid & 15;
    const int lhi = (lid >> 4) * 16;
    const int bh = blockIdx.y;
    const int b = bh >> 4, h = bh & 15;
    const int qt = gridDim.x - 1 - blockIdx.x;
    const int q0 = qt * 128;
    const int nkb = qt * 2 + 2;
    const int wm = wid * 16;

    // ---- load Q (hi+lo) into smem ----
#pragma unroll
    for (int u = 0; u < 16; u++) {
        int c = tid + u * 256;
        int plane = c >> 11;
        int cc = c & 2047;
        int r = cc >> 4, ch = cc & 15;
        int p = ch >> 3, c8 = ch & 7;
        const __nv_bfloat16* src = (plane ? ql : qh) +
            ((size_t)(b * 2048 + q0 + r) * HID + h * HD + ch * 8);
        uint32_t dst = sb + (plane ? SQL : SQH) + p * 16384 + SWZ(r * 128 + c8 * 16);
        asm volatile("cp.async.cg.shared.global [%0], [%1], 16;"
                     :: "r"(dst), "l"(src) : "memory");
    }
    asm volatile("cp.async.commit_group;" ::: "memory");

#define LOAD_KV(s, kt) do {                                                    \
    int k0 = (kt) * 64;                                                        \
    _Pragma("unroll")                                                          \
    for (int u = 0; u < 16; u++) {                                             \
        int c = tid + u * 256;                                                 \
        if (c < 2048) {                                                        \
            int plane = c >> 10;                                               \
            int cc = c & 1023;                                                 \
            int r = cc >> 4, ch = cc & 15;                                     \
            int p = ch >> 3, c8 = ch & 7;                                      \
            const __nv_bfloat16* src = (plane ? kl : kh) +                     \
                ((size_t)(b * 2048 + k0 + r) * HID + h * HD + ch * 8);         \
            uint32_t dst = sb + (plane ? SKL(s) : SKH(s)) + p * 8192 +         \
                           SWZ(r * 128 + c8 * 16);                             \
            asm volatile("cp.async.cg.shared.global [%0], [%1], 16;"           \
                         :: "r"(dst), "l"(src) : "memory");                    \
        } else {                                                               \
            int plane = (c >> 10) & 1;                                         \
            int cc = c & 1023;                                                 \
            int d = cc >> 3, c8 = cc & 7;                                      \
            const __nv_bfloat16* src = (plane ? vtl : vth) +                   \
                ((size_t)(b * 2048 + h * HD + d) * 2048 + k0 + c8 * 8);        \
            uint32_t dst = sb + (plane ? SVL(s) : SVH(s)) +                    \
                           SWZ(d * 128 + c8 * 16);                             \
            asm volatile("cp.async.cg.shared.global [%0], [%1], 16;"           \
                         :: "r"(dst), "l"(src) : "memory");                    \
        }                                                                      \
    }                                                                          \
} while (0)

    LOAD_KV(0, 0);
    asm volatile("cp.async.commit_group;" ::: "memory");

    float accO[16][4];
#pragma unroll
    for (int nt = 0; nt < 16; nt++)
#pragma unroll
        for (int q = 0; q < 4; q++) accO[nt][q] = 0.0f;
    float m0v = -1e30f, m1v = -1e30f, l0v = 0.0f, l1v = 0.0f;

    const int grow0 = q0 + wm + (lid >> 2);
    const int grow1 = grow0 + 8;

    for (int kt = 0; kt < nkb; kt++) {
        __syncthreads();
        if (kt + 1 < nkb) LOAD_KV((kt + 1) & 1, kt + 1);
        asm volatile("cp.async.commit_group;" ::: "memory");
        asm volatile("cp.async.wait_group 1;" ::: "memory");
        __syncthreads();

        const int s = kt & 1;

        // ---- S = Qh*Kh + Ql*Kh + Qh*Kl  (Qh, Kh frags reused) ----
        float sa[8][4];
#pragma unroll
        for (int nt = 0; nt < 8; nt++)
#pragma unroll
            for (int q = 0; q < 4; q++) sa[nt][q] = 0.0f;

#pragma unroll
        for (int kk = 0; kk < 8; kk++) {
            int p = kk >> 2;
            int cb = (kk & 3) * 32 + lhi;
            int arow = wm + lrow;
            uint32_t aoff = p * 16384 + arow * 128 + (cb ^ ((arow & 7) * 16));
            uint32_t qhf[4], qlf[4];
            ldsm_x4(qhf, sb + SQH + aoff);
            ldsm_x4(qlf, sb + SQL + aoff);
#pragma unroll
            for (int np = 0; np < 4; np++) {
                int brow = np * 16 + lrow;
                uint32_t boff = p * 8192 + brow * 128 + (cb ^ ((brow & 7) * 16));
                uint32_t khf[4];
                ldsm_x4(khf, sb + SKH(s) + boff);
                mma_bf16(sa[np * 2 + 0], qhf, khf[0], khf[2]);
                mma_bf16(sa[np * 2 + 1], qhf, khf[1], khf[3]);
                mma_bf16(sa[np * 2 + 0], qlf, khf[0], khf[2]);
                mma_bf16(sa[np * 2 + 1], qlf, khf[1], khf[3]);
                uint32_t klf[4];
                ldsm_x4(klf, sb + SKL(s) + boff);
                mma_bf16(sa[np * 2 + 0], qhf, klf[0], klf[2]);
                mma_bf16(sa[np * 2 + 1], qhf, klf[1], klf[3]);
            }
        }

        // ---- causal mask ----
        if ((kt + 1) * 64 - 1 > q0 + wm) {
            const int colb = kt * 64 + (lid & 3) * 2;
#pragma unroll
            for (int nt = 0; nt < 8; nt++) {
                int col = colb + nt * 8;
                if (col > grow0)     sa[nt][0] = -1e30f;
                if (col + 1 > grow0) sa[nt][1] = -1e30f;
                if (col > grow1)     sa[nt][2] = -1e30f;
                if (col + 1 > grow1) sa[nt][3] = -1e30f;
            }
        }

        // ---- online softmax ----
        float mx0 = m0v, mx1 = m1v;
#pragma unroll
        for (int nt = 0; nt < 8; nt++) {
            mx0 = fmaxf(mx0, fmaxf(sa[nt][0], sa[nt][1]));
            mx1 = fmaxf(mx1, fmaxf(sa[nt][2], sa[nt][3]));
        }
        mx0 = fmaxf(mx0, __shfl_xor_sync(0xffffffffu, mx0, 1));
        mx0 = fmaxf(mx0, __shfl_xor_sync(0xffffffffu, mx0, 2));
        mx1 = fmaxf(mx1, __shfl_xor_sync(0xffffffffu, mx1, 1));
        mx1 = fmaxf(mx1, __shfl_xor_sync(0xffffffffu, mx1, 2));
        float alpha0 = __expf(m0v - mx0);
        float alpha1 = __expf(m1v - mx1);
        m0v = mx0; m1v = mx1;

        float ls0 = 0.0f, ls1 = 0.0f;
#pragma unroll
        for (int nt = 0; nt < 8; nt++) {
            sa[nt][0] = __expf(sa[nt][0] - mx0);
            sa[nt][1] = __expf(sa[nt][1] - mx0);
            sa[nt][2] = __expf(sa[nt][2] - mx1);
            sa[nt][3] = __expf(sa[nt][3] - mx1);
            ls0 += sa[nt][0] + sa[nt][1];
            ls1 += sa[nt][2] + sa[nt][3];
        }
        ls0 += __shfl_xor_sync(0xffffffffu, ls0, 1);
        ls0 += __shfl_xor_sync(0xffffffffu, ls0, 2);
        ls1 += __shfl_xor_sync(0xffffffffu, ls1, 1);
        ls1 += __shfl_xor_sync(0xffffffffu, ls1, 2);
        l0v = l0v * alpha0 + ls0;
        l1v = l1v * alpha1 + ls1;

#pragma unroll
        for (int nt = 0; nt < 16; nt++) {
            accO[nt][0] *= alpha0; accO[nt][1] *= alpha0;
            accO[nt][2] *= alpha1; accO[nt][3] *= alpha1;
        }

        // ---- P split into bf16 hi/lo A-fragments ----
        uint32_t phA[8], phB[8], plA[8], plB[8];
#pragma unroll
        for (int nt = 0; nt < 8; nt++) {
            float h0 = __bfloat162float(__float2bfloat16(sa[nt][0]));
            float h1 = __bfloat162float(__float2bfloat16(sa[nt][1]));
            float h2 = __bfloat162float(__float2bfloat16(sa[nt][2]));
            float h3 = __bfloat162float(__float2bfloat16(sa[nt][3]));
            phA[nt] = pack_bf16x2(h0, h1);
            phB[nt] = pack_bf16x2(h2, h3);
            plA[nt] = pack_bf16x2(sa[nt][0] - h0, sa[nt][1] - h1);
            plB[nt] = pack_bf16x2(sa[nt][2] - h2, sa[nt][3] - h3);
        }

        // ---- O += Ph*Vh + Pl*Vh + Ph*Vl  (Vh frags reused) ----
#pragma unroll
        for (int ki = 0; ki < 4; ki++) {
            uint32_t aH[4] = {phA[2 * ki], phB[2 * ki], phA[2 * ki + 1], phB[2 * ki + 1]};
            uint32_t aL[4] = {plA[2 * ki], plB[2 * ki], plA[2 * ki + 1], plB[2 * ki + 1]};
            int cb = ki * 32 + lhi;
#pragma unroll
            for (int np = 0; np < 8; np++) {
                int brow = np * 16 + lrow;
                uint32_t boff = brow * 128 + (cb ^ ((brow & 7) * 16));
                uint32_t vhf[4];
                ldsm_x4(vhf, sb + SVH(s) + boff);
                mma_bf16(accO[np * 2 + 0], aH, vhf[0], vhf[2]);
                mma_bf16(accO[np * 2 + 1], aH, vhf[1], vhf[3]);
                mma_bf16(accO[np * 2 + 0], aL, vhf[0], vhf[2]);
                mma_bf16(accO[np * 2 + 1], aL, vhf[1], vhf[3]);
                uint32_t vlf[4];
                ldsm_x4(vlf, sb + SVL(s) + boff);
                mma_bf16(accO[np * 2 + 0], aH, vlf[0], vlf[2]);
                mma_bf16(accO[np * 2 + 1], aH, vlf[1], vlf[3]);
            }
        }
    }

    // ---- epilogue: O/l -> fp16 hi/lo planes ----
    float inv0 = 1.0f / l0v, inv1 = 1.0f / l1v;
#pragma unroll
    for (int nt = 0; nt < 16; nt++) {
        int col = h * HD + nt * 8 + (lid & 3) * 2;
        float o0 = accO[nt][0] * inv0, o1 = accO[nt][1] * inv0;
        float o2 = accO[nt][2] * inv1, o3 = accO[nt][3] * inv1;
        __half q0h = __float2half_rn(o0), q1h = __float2half_rn(o1);
        __half q2h = __float2half_rn(o2), q3h = __float2half_rn(o3);
        size_t r0 = (size_t)(b * 2048 + grow0) * HID + col;
        size_t r1 = (size_t)(b * 2048 + grow1) * HID + col;
        *(uint32_t*)(ohi + r0) = pack_h2(__half2float(q0h), __half2float(q1h));
        *(uint32_t*)(ohi + r1) = pack_h2(__half2float(q2h), __half2float(q3h));
        *(uint32_t*)(olo + r0) = pack_h2(o0 - __half2float(q0h), o1 - __half2float(q1h));
        *(uint32_t*)(olo + r1) = pack_h2(o2 - __half2float(q2h), o3 - __half2float(q3h));
    }
#undef LOAD_KV
}

// ---------------------------------------------------------------------------
// launch
// ---------------------------------------------------------------------------
extern "C" void kernel_launch(void* const* d_in, const int* in_sizes, int n_in,
                              void* d_out, int out_size)
{
    const float* x     = (const float*)d_in[0];
    const float* w_in  = (const float*)d_in[1];
    const float* w_out = (const float*)d_in[2];
    const float* qnw   = (const float*)d_in[3];
    const float* knw   = (const float*)d_in[4];
    float* out = (float*)d_out;

    float* qkv;  cudaGetSymbolAddress((void**)&qkv,  g_qkv);
    __half *ah, *al, *bhp, *blp;
    __nv_bfloat16 *qh, *ql, *kh, *kl, *vth, *vtl;
    cudaGetSymbolAddress((void**)&ah, g_a_hi);
    cudaGetSymbolAddress((void**)&al, g_a_lo);
    cudaGetSymbolAddress((void**)&bhp, g_b_hi);
    cudaGetSymbolAddress((void**)&blp, g_b_lo);
    cudaGetSymbolAddress((void**)&qh, g_q_hi);
    cudaGetSymbolAddress((void**)&ql, g_q_lo);
    cudaGetSymbolAddress((void**)&kh, g_k_hi);
    cudaGetSymbolAddress((void**)&kl, g_k_lo);
    cudaGetSymbolAddress((void**)&vth, g_vt_hi);
    cudaGetSymbolAddress((void**)&vtl, g_vt_lo);

    cudaFuncSetAttribute(gemm_h3, cudaFuncAttributeMaxDynamicSharedMemorySize, GEMM_SMEM);
    cudaFuncSetAttribute(attn_mma, cudaFuncAttributeMaxDynamicSharedMemorySize, ATTN_SMEM);

    // 1. split x -> a planes, w_in -> b planes (fp16)
    split2h_kernel<<<(ROWS * HID / 4 + 255) / 256, 256>>>(x, ah, al, ROWS * HID / 4);
    split2h_kernel<<<(QKV_W * HID / 4 + 255) / 256, 256>>>(w_in, bhp, blp, QKV_W * HID / 4);

    // 2. QKV = x @ w_in^T
    gemm_h3<<<(ROWS / BM) * (QKV_W / BN), 512, GEMM_SMEM>>>(ah, al, bhp, blp, qkv, ROWS, QKV_W);

    // 3. tables + norm/rope -> bf16 planes; V transpose/split
    rope_table_kernel<<<(S_ * HALF + 255) / 256, 256>>>();
    normrope_kernel<<<ROWS, 256>>>(qkv, qnw, knw, qh, ql, kh, kl);
    vtrans_kernel<<<dim3(ROWS / 32, HID / 32), 256>>>(qkv, vth, vtl);

    // 4. attention -> fp16 a planes (gemm2 A operand)
    attn_mma<<<dim3(S_ / 128, B_ * NH), 256, ATTN_SMEM>>>(qh, ql, kh, kl, vth, vtl, ah, al);

    // 5. w_out -> b planes; out = O @ w_out^T
    split2h_kernel<<<(HID * HID / 4 + 255) / 256, 256>>>(w_out, bhp, blp, HID * HID / 4);
    gemm_h3<<<(ROWS / BM) * (HID / BN), 512, GEMM_SMEM>>>(ah, al, bhp, blp, out, ROWS, HID);
}

// round 9
// speedup vs baseline: 1.0187x; 1.0187x over previous
#include <cuda_runtime.h>
#include <cuda_bf16.h>
#include <cuda_fp16.h>
#include <cstdint>
#include <math.h>

// Problem constants
#define B_  2
#define S_  2048
#define HID 2048
#define NH  16
#define HD  128
#define HALF 64
#define ROWS (B_ * S_)            // 4096
#define QKV_W (3 * HID)           // 6144
#define EPS 1e-5f
#define SCALE 0.08838834764831845f   // 1/sqrt(128)

// Scratch (device-global; no runtime allocation allowed)
__device__ float g_qkv[(size_t)ROWS * QKV_W];            // gemm1 out (fp32)
__device__ float g_cos[S_ * HALF];
__device__ float g_sin[S_ * HALF];
__device__ __half g_a_hi[(size_t)ROWS * HID];            // gemm A hi plane (x; then O)
__device__ __half g_a_lo[(size_t)ROWS * HID];
__device__ __half g_b_hi[(size_t)QKV_W * HID];           // gemm B hi plane (w_in; then w_out)
__device__ __half g_b_lo[(size_t)QKV_W * HID];
__device__ __nv_bfloat16 g_q_hi[(size_t)ROWS * HID];
__device__ __nv_bfloat16 g_q_lo[(size_t)ROWS * HID];
__device__ __nv_bfloat16 g_k_hi[(size_t)ROWS * HID];
__device__ __nv_bfloat16 g_k_lo[(size_t)ROWS * HID];
__device__ __nv_bfloat16 g_vt_hi[(size_t)ROWS * HID];    // [b][h][d][s]
__device__ __nv_bfloat16 g_vt_lo[(size_t)ROWS * HID];

__device__ __forceinline__ uint32_t smem_u32(const void* p) {
    uint32_t a;
    asm("{ .reg .u64 t; cvta.to.shared.u64 t, %1; cvt.u32.u64 %0, t; }" : "=r"(a) : "l"(p));
    return a;
}
#define SWZ(x) ((x) ^ (((x) >> 3) & 0x70))

__device__ __forceinline__ void ldsm_x4(uint32_t* r, uint32_t addr) {
    asm volatile("ldmatrix.sync.aligned.m8n8.x4.shared.b16 {%0,%1,%2,%3}, [%4];"
                 : "=r"(r[0]), "=r"(r[1]), "=r"(r[2]), "=r"(r[3]) : "r"(addr));
}
// bf16 in, f32 acc (attention)
__device__ __forceinline__ void mma_bf16(float* c, const uint32_t* a,
                                         uint32_t b0, uint32_t b1) {
    asm volatile(
        "mma.sync.aligned.m16n8k16.row.col.f32.bf16.bf16.f32 "
        "{%0,%1,%2,%3}, {%4,%5,%6,%7}, {%8,%9}, {%0,%1,%2,%3};"
        : "+f"(c[0]), "+f"(c[1]), "+f"(c[2]), "+f"(c[3])
        : "r"(a[0]), "r"(a[1]), "r"(a[2]), "r"(a[3]), "r"(b0), "r"(b1));
}
// fp16 in, f32 acc (gemm)
__device__ __forceinline__ void mma_f16f32(float* c, const uint32_t* a,
                                           uint32_t b0, uint32_t b1) {
    asm volatile(
        "mma.sync.aligned.m16n8k16.row.col.f32.f16.f16.f32 "
        "{%0,%1,%2,%3}, {%4,%5,%6,%7}, {%8,%9}, {%0,%1,%2,%3};"
        : "+f"(c[0]), "+f"(c[1]), "+f"(c[2]), "+f"(c[3])
        : "r"(a[0]), "r"(a[1]), "r"(a[2]), "r"(a[3]), "r"(b0), "r"(b1));
}
__device__ __forceinline__ uint32_t pack_bf16x2(float lo, float hi) {
    uint32_t r;
    asm("cvt.rn.bf16x2.f32 %0, %1, %2;" : "=r"(r) : "f"(hi), "f"(lo));
    return r;
}
__device__ __forceinline__ uint32_t pack_h2(float lo, float hi) {
    __half2 h = __floats2half2_rn(lo, hi);
    return *(uint32_t*)&h;
}

// ---------------------------------------------------------------------------
// RoPE table
// ---------------------------------------------------------------------------
__global__ void rope_table_kernel() {
    int idx = blockIdx.x * blockDim.x + threadIdx.x;
    if (idx >= S_ * HALF) return;
    int s = idx >> 6;
    int j = idx & 63;
    float freq = powf(10000.0f, -(float)j * (1.0f / 64.0f));
    float sn, cs;
    sincosf((float)s * freq, &sn, &cs);
    g_cos[idx] = cs;
    g_sin[idx] = sn;
}

// ---------------------------------------------------------------------------
// fp16 hi/lo split: fp32 -> two fp16 planes (flat)
// ---------------------------------------------------------------------------
__global__ void __launch_bounds__(256) split2h_kernel(
    const float* __restrict__ src, __half* __restrict__ hi,
    __half* __restrict__ lo, int n4)
{
    int i = blockIdx.x * blockDim.x + threadIdx.x;
    if (i >= n4) return;
    float4 v = ((const float4*)src)[i];
    float vv[4] = {v.x, v.y, v.z, v.w};
    uint64_t hp = 0, lp = 0;
#pragma unroll
    for (int q = 0; q < 4; q++) {
        __half h = __float2half_rn(vv[q]);
        __half l = __float2half_rn(vv[q] - __half2float(h));
        hp |= (uint64_t)__half_as_ushort(h) << (q * 16);
        lp |= (uint64_t)__half_as_ushort(l) << (q * 16);
    }
    *(uint64_t*)(hi + (size_t)i * 4) = hp;
    *(uint64_t*)(lo + (size_t)i * 4) = lp;
}

// ---------------------------------------------------------------------------
// 3-term fp16 split GEMM (f32 acc all terms):
//   C = Ah*Bh^T + Al*Bh^T + Ah*Bl^T
// Templated tile: BM = MT*64, BN = NP*64. 512 threads, 16 warps (4x4 grid),
// warp tile (MT*16) x (NP*16). BK=64, NSTG-stage cp.async pipeline.
// ---------------------------------------------------------------------------
template<int MT, int NP, int NSTG>
__global__ void __launch_bounds__(512, 1) gemm_t(
    const __half* __restrict__ Ah, const __half* __restrict__ Al,
    const __half* __restrict__ Bh, const __half* __restrict__ Bl,
    float* __restrict__ C, int M, int N, int tiles_m)
{
    constexpr int BM = MT * 64;
    constexpr int BN = NP * 64;
    constexpr int A_PLANE = BM * 128;
    constexpr int B_PLANE = BN * 128;
    constexpr int SAH = 0, SAL = A_PLANE;
    constexpr int SBH = 2 * A_PLANE, SBL = 2 * A_PLANE + B_PLANE;
    constexpr int STG = 2 * (A_PLANE + B_PLANE);
    constexpr int ACH = BM * 16;          // 16B chunks in A planes
    constexpr int BCH = BN * 16;
    constexpr int NLD = (ACH + BCH) / 512;
    constexpr int NKT = HID / 64;         // 32

    extern __shared__ char smem[];
    const uint32_t sb = smem_u32(smem);
    const int tid = threadIdx.x;
    const int wid = tid >> 5, lid = tid & 31;
    const int m0 = (blockIdx.x % tiles_m) * BM;
    const int n0 = (blockIdx.x / tiles_m) * BN;
    const int wm = (wid & 3) * (MT * 16);
    const int wn = (wid >> 2) * (NP * 16);
    const int lrow = lid & 15;
    const int lhi = (lid >> 4) * 16;

    auto load_stage = [&](int st, int kt) {
        uint32_t sbase = sb + st * STG;
#pragma unroll
        for (int u = 0; u < NLD; u++) {
            int c = tid + u * 512;
            const __half* gp;
            uint32_t dst;
            if (c < ACH) {
                int plane = c / (ACH / 2);
                int cc = c % (ACH / 2);
                int r = cc >> 3, c16 = cc & 7;
                gp = (plane ? Al : Ah) + (size_t)(m0 + r) * HID + kt * 64 + c16 * 8;
                dst = sbase + (plane ? SAL : SAH) + SWZ(r * 128 + c16 * 16);
            } else {
                int c2 = c - ACH;
                int plane = c2 / (BCH / 2);
                int cc = c2 % (BCH / 2);
                int r = cc >> 3, c16 = cc & 7;
                gp = (plane ? Bl : Bh) + (size_t)(n0 + r) * HID + kt * 64 + c16 * 8;
                dst = sbase + (plane ? SBL : SBH) + SWZ(r * 128 + c16 * 16);
            }
            asm volatile("cp.async.cg.shared.global [%0], [%1], 16;"
                         :: "r"(dst), "l"(gp) : "memory");
        }
    };

#pragma unroll
    for (int s = 0; s < NSTG - 1; s++) {
        load_stage(s, s);
        asm volatile("cp.async.commit_group;" ::: "memory");
    }

    float acc[MT][NP * 2][4];
#pragma unroll
    for (int mt = 0; mt < MT; mt++)
#pragma unroll
        for (int nt = 0; nt < NP * 2; nt++)
#pragma unroll
            for (int q = 0; q < 4; q++) acc[mt][nt][q] = 0.0f;

    for (int kt = 0; kt < NKT; kt++) {
        if (kt + NSTG - 1 < NKT) load_stage((kt + NSTG - 1) % NSTG, kt + NSTG - 1);
        asm volatile("cp.async.commit_group;" ::: "memory");
        asm volatile("cp.async.wait_group %0;" :: "n"(NSTG - 1) : "memory");
        __syncthreads();

        const uint32_t sbase = sb + (kt % NSTG) * STG;

#pragma unroll
        for (int ks = 0; ks < 4; ks++) {
            const int cb = ks * 32 + lhi;
            uint32_t ahf[MT][4], alf[MT][4];
#pragma unroll
            for (int mt = 0; mt < MT; mt++) {
                int row = wm + mt * 16 + lrow;
                uint32_t off = row * 128 + (cb ^ ((row & 7) * 16));
                ldsm_x4(ahf[mt], sbase + SAH + off);
                ldsm_x4(alf[mt], sbase + SAL + off);
            }
#pragma unroll
            for (int np = 0; np < NP; np++) {
                int brow = wn + np * 16 + lrow;
                uint32_t boff = brow * 128 + (cb ^ ((brow & 7) * 16));
                uint32_t bh4[4];
                ldsm_x4(bh4, sbase + SBH + boff);
#pragma unroll
                for (int mt = 0; mt < MT; mt++) {
                    mma_f16f32(acc[mt][np * 2 + 0], ahf[mt], bh4[0], bh4[2]);
                    mma_f16f32(acc[mt][np * 2 + 1], ahf[mt], bh4[1], bh4[3]);
                    mma_f16f32(acc[mt][np * 2 + 0], alf[mt], bh4[0], bh4[2]);
                    mma_f16f32(acc[mt][np * 2 + 1], alf[mt], bh4[1], bh4[3]);
                }
                uint32_t bl4[4];
                ldsm_x4(bl4, sbase + SBL + boff);
#pragma unroll
                for (int mt = 0; mt < MT; mt++) {
                    mma_f16f32(acc[mt][np * 2 + 0], ahf[mt], bl4[0], bl4[2]);
                    mma_f16f32(acc[mt][np * 2 + 1], ahf[mt], bl4[1], bl4[3]);
                }
            }
        }
        __syncthreads();
    }

    const int er = m0 + wm + (lid >> 2);
    const int ec = n0 + wn + (lid & 3) * 2;
#pragma unroll
    for (int mt = 0; mt < MT; mt++)
#pragma unroll
        for (int nt = 0; nt < NP * 2; nt++) {
            float* c0 = C + (size_t)(er + mt * 16) * N + ec + nt * 8;
            *(float2*)c0 = make_float2(acc[mt][nt][0], acc[mt][nt][1]);
            float* c1 = c0 + 8 * N;
            *(float2*)c1 = make_float2(acc[mt][nt][2], acc[mt][nt][3]);
        }
}

// gemm1: 128x192 tile, 2 stages (160KB). gemm2: 64x128 tile, 3 stages (144KB).
#define GEMM1_SMEM (2 * 2 * (128 * 128 + 192 * 128))   // 163840
#define GEMM2_SMEM (3 * 2 * (64 * 128 + 128 * 128))    // 147456

// ---------------------------------------------------------------------------
// Fused qk RMSNorm + RoPE -> bf16 hi/lo planes. Q scaled by 1/sqrt(HD).
// ---------------------------------------------------------------------------
__global__ void __launch_bounds__(256) normrope_kernel(
    const float* __restrict__ qkv,
    const float* __restrict__ nw_q, const float* __restrict__ nw_k,
    __nv_bfloat16* __restrict__ qh, __nv_bfloat16* __restrict__ ql,
    __nv_bfloat16* __restrict__ kh, __nv_bfloat16* __restrict__ kl)
{
    __shared__ float buf[HID];
    __shared__ float warpred[8];

    const int row = blockIdx.x;
    const int s = row & (S_ - 1);
    const int tid = threadIdx.x;

#pragma unroll
    for (int part = 0; part < 2; part++) {
        const float* src = qkv + (size_t)row * QKV_W + part * HID;
        const float* w = (part == 0) ? nw_q : nw_k;
        __nv_bfloat16* dh = (part == 0) ? qh : kh;
        __nv_bfloat16* dl = (part == 0) ? ql : kl;

        float ss = 0.0f;
#pragma unroll
        for (int u = 0; u < 8; u++) {
            int idx = tid + u * 256;
            float v = src[idx];
            buf[idx] = v;
            ss += v * v;
        }
#pragma unroll
        for (int o = 16; o; o >>= 1) ss += __shfl_xor_sync(0xffffffffu, ss, o);
        if ((tid & 31) == 0) warpred[tid >> 5] = ss;
        __syncthreads();
        float tot = 0.0f;
#pragma unroll
        for (int wi = 0; wi < 8; wi++) tot += warpred[wi];
        float rn = rsqrtf(tot * (1.0f / (float)HID) + EPS);
        if (part == 0) rn *= SCALE;

#pragma unroll
        for (int u = 0; u < 4; u++) {
            int p = tid + u * 256;
            int hh = p >> 6;
            int j = p & 63;
            int i1 = hh * HD + j;
            int i2 = i1 + HALF;
            float x1 = buf[i1] * rn * w[i1];
            float x2 = buf[i2] * rn * w[i2];
            float cs = g_cos[s * HALF + j];
            float sn = g_sin[s * HALF + j];
            float o1 = x1 * cs - x2 * sn;
            float o2 = x2 * cs + x1 * sn;
            __nv_bfloat16 h1 = __float2bfloat16(o1);
            __nv_bfloat16 h2 = __float2bfloat16(o2);
            size_t base = (size_t)row * HID;
            dh[base + i1] = h1;
            dh[base + i2] = h2;
            dl[base + i1] = __float2bfloat16(o1 - __bfloat162float(h1));
            dl[base + i2] = __float2bfloat16(o2 - __bfloat162float(h2));
        }
        __syncthreads();
    }
}

// ---------------------------------------------------------------------------
// V transpose + split: g_qkv v cols -> vt_hi/vt_lo [b][h][d][s]
// ---------------------------------------------------------------------------
__global__ void __launch_bounds__(256) vtrans_kernel(
    const float* __restrict__ qkv,
    __nv_bfloat16* __restrict__ vth, __nv_bfloat16* __restrict__ vtl)
{
    __shared__ float t[32][33];
    const int row0 = blockIdx.x * 32;
    const int col0 = blockIdx.y * 32;
    const int tx = threadIdx.x & 31;
    const int ty = threadIdx.x >> 5;
#pragma unroll
    for (int i = 0; i < 4; i++) {
        int r = ty + i * 8;
        t[r][tx] = qkv[(size_t)(row0 + r) * QKV_W + 2 * HID + col0 + tx];
    }
    __syncthreads();
    const int b = row0 >> 11;
    const int s0 = row0 & 2047;
#pragma unroll
    for (int i = 0; i < 4; i++) {
        int c = ty + i * 8;
        float v = t[tx][c];
        __nv_bfloat16 h = __float2bfloat16(v);
        size_t o = ((size_t)(b * 2048 + col0 + c)) * 2048 + s0 + tx;
        vth[o] = h;
        vtl[o] = __float2bfloat16(v - __bfloat162float(h));
    }
}

// ---------------------------------------------------------------------------
// Flash attention, bf16 mma.sync, 3-term split, hoisted Q fragments in regs,
// fully-masked-warp ktile skip. 128 q rows x (b,h), 8 warps, 2-stage KV.
// Output -> fp16 g_a_hi / g_a_lo planes (gemm2 A operand).
// ---------------------------------------------------------------------------
#define SQH 0
#define SQL 32768
#define SKH(s) (65536 + (s) * 65536)
#define SKL(s) (SKH(s) + 16384)
#define SVH(s) (SKH(s) + 32768)
#define SVL(s) (SKH(s) + 49152)
#define ATTN_SMEM (65536 + 2 * 65536)   // 196608

__global__ void __launch_bounds__(256, 1) attn_mma(
    const __nv_bfloat16* __restrict__ qh, const __nv_bfloat16* __restrict__ ql,
    const __nv_bfloat16* __restrict__ kh, const __nv_bfloat16* __restrict__ kl,
    const __nv_bfloat16* __restrict__ vth, const __nv_bfloat16* __restrict__ vtl,
    __half* __restrict__ ohi, __half* __restrict__ olo)
{
    extern __shared__ char smem[];
    const uint32_t sb = smem_u32(smem);
    const int tid = threadIdx.x;
    const int wid = tid >> 5, lid = tid & 31;
    const int lrow = lid & 15;
    const int lhi = (lid >> 4) * 16;
    const int bh = blockIdx.y;
    const int b = bh >> 4, h = bh & 15;
    const int qt = gridDim.x - 1 - blockIdx.x;
    const int q0 = qt * 128;
    const int nkb = qt * 2 + 2;
    const int wm = wid * 16;

    // ---- load Q (hi+lo) into smem ----
#pragma unroll
    for (int u = 0; u < 16; u++) {
        int c = tid + u * 256;
        int plane = c >> 11;
        int cc = c & 2047;
        int r = cc >> 4, ch = cc & 15;
        int p = ch >> 3, c8 = ch & 7;
        const __nv_bfloat16* src = (plane ? ql : qh) +
            ((size_t)(b * 2048 + q0 + r) * HID + h * HD + ch * 8);
        uint32_t dst = sb + (plane ? SQL : SQH) + p * 16384 + SWZ(r * 128 + c8 * 16);
        asm volatile("cp.async.cg.shared.global [%0], [%1], 16;"
                     :: "r"(dst), "l"(src) : "memory");
    }
    asm volatile("cp.async.commit_group;" ::: "memory");

#define LOAD_KV(s, kt) do {                                                    \
    int k0 = (kt) * 64;                                                        \
    _Pragma("unroll")                                                          \
    for (int u = 0; u < 16; u++) {                                             \
        int c = tid + u * 256;                                                 \
        if (c < 2048) {                                                        \
            int plane = c >> 10;                                               \
            int cc = c & 1023;                                                 \
            int r = cc >> 4, ch = cc & 15;                                     \
            int p = ch >> 3, c8 = ch & 7;                                      \
            const __nv_bfloat16* src = (plane ? kl : kh) +                     \
                ((size_t)(b * 2048 + k0 + r) * HID + h * HD + ch * 8);         \
            uint32_t dst = sb + (plane ? SKL(s) : SKH(s)) + p * 8192 +         \
                           SWZ(r * 128 + c8 * 16);                             \
            asm volatile("cp.async.cg.shared.global [%0], [%1], 16;"           \
                         :: "r"(dst), "l"(src) : "memory");                    \
        } else {                                                               \
            int plane = (c >> 10) & 1;                                         \
            int cc = c & 1023;                                                 \
            int d = cc >> 3, c8 = cc & 7;                                      \
            const __nv_bfloat16* src = (plane ? vtl : vth) +                   \
                ((size_t)(b * 2048 + h * HD + d) * 2048 + k0 + c8 * 8);        \
            uint32_t dst = sb + (plane ? SVL(s) : SVH(s)) +                    \
                           SWZ(d * 128 + c8 * 16);                             \
            asm volatile("cp.async.cg.shared.global [%0], [%1], 16;"           \
                         :: "r"(dst), "l"(src) : "memory");                    \
        }                                                                      \
    }                                                                          \
} while (0)

    LOAD_KV(0, 0);
    asm volatile("cp.async.commit_group;" ::: "memory");

    // ---- hoist Q fragments into registers (Q smem never rewritten) ----
    asm volatile("cp.async.wait_group 1;" ::: "memory");
    __syncthreads();
    uint32_t qhr[8][4], qlr[8][4];
#pragma unroll
    for (int kk = 0; kk < 8; kk++) {
        int p = kk >> 2;
        int cb = (kk & 3) * 32 + lhi;
        int arow = wm + lrow;
        uint32_t aoff = p * 16384 + arow * 128 + (cb ^ ((arow & 7) * 16));
        ldsm_x4(qhr[kk], sb + SQH + aoff);
        ldsm_x4(qlr[kk], sb + SQL + aoff);
    }

    float accO[16][4];
#pragma unroll
    for (int nt = 0; nt < 16; nt++)
#pragma unroll
        for (int q = 0; q < 4; q++) accO[nt][q] = 0.0f;
    float m0v = -1e30f, m1v = -1e30f, l0v = 0.0f, l1v = 0.0f;

    const int grow0 = q0 + wm + (lid >> 2);
    const int grow1 = grow0 + 8;

    for (int kt = 0; kt < nkb; kt++) {
        __syncthreads();
        if (kt + 1 < nkb) LOAD_KV((kt + 1) & 1, kt + 1);
        asm volatile("cp.async.commit_group;" ::: "memory");
        asm volatile("cp.async.wait_group 1;" ::: "memory");
        __syncthreads();

        // fully-masked ktile for this warp? (all cols > all rows)
        if (kt * 64 > q0 + wm + 15) continue;

        const int s = kt & 1;

        // ---- S = Qh*Kh + Ql*Kh + Qh*Kl  (Q frags from regs) ----
        float sa[8][4];
#pragma unroll
        for (int nt = 0; nt < 8; nt++)
#pragma unroll
            for (int q = 0; q < 4; q++) sa[nt][q] = 0.0f;

#pragma unroll
        for (int kk = 0; kk < 8; kk++) {
            int p = kk >> 2;
            int cb = (kk & 3) * 32 + lhi;
#pragma unroll
            for (int np = 0; np < 4; np++) {
                int brow = np * 16 + lrow;
                uint32_t boff = p * 8192 + brow * 128 + (cb ^ ((brow & 7) * 16));
                uint32_t khf[4];
                ldsm_x4(khf, sb + SKH(s) + boff);
                mma_bf16(sa[np * 2 + 0], qhr[kk], khf[0], khf[2]);
                mma_bf16(sa[np * 2 + 1], qhr[kk], khf[1], khf[3]);
                mma_bf16(sa[np * 2 + 0], qlr[kk], khf[0], khf[2]);
                mma_bf16(sa[np * 2 + 1], qlr[kk], khf[1], khf[3]);
                uint32_t klf[4];
                ldsm_x4(klf, sb + SKL(s) + boff);
                mma_bf16(sa[np * 2 + 0], qhr[kk], klf[0], klf[2]);
                mma_bf16(sa[np * 2 + 1], qhr[kk], klf[1], klf[3]);
            }
        }

        // ---- causal mask ----
        if ((kt + 1) * 64 - 1 > q0 + wm) {
            const int colb = kt * 64 + (lid & 3) * 2;
#pragma unroll
            for (int nt = 0; nt < 8; nt++) {
                int col = colb + nt * 8;
                if (col > grow0)     sa[nt][0] = -1e30f;
                if (col + 1 > grow0) sa[nt][1] = -1e30f;
                if (col > grow1)     sa[nt][2] = -1e30f;
                if (col + 1 > grow1) sa[nt][3] = -1e30f;
            }
        }

        // ---- online softmax ----
        float mx0 = m0v, mx1 = m1v;
#pragma unroll
        for (int nt = 0; nt < 8; nt++) {
            mx0 = fmaxf(mx0, fmaxf(sa[nt][0], sa[nt][1]));
            mx1 = fmaxf(mx1, fmaxf(sa[nt][2], sa[nt][3]));
        }
        mx0 = fmaxf(mx0, __shfl_xor_sync(0xffffffffu, mx0, 1));
        mx0 = fmaxf(mx0, __shfl_xor_sync(0xffffffffu, mx0, 2));
        mx1 = fmaxf(mx1, __shfl_xor_sync(0xffffffffu, mx1, 1));
        mx1 = fmaxf(mx1, __shfl_xor_sync(0xffffffffu, mx1, 2));
        float alpha0 = __expf(m0v - mx0);
        float alpha1 = __expf(m1v - mx1);
        m0v = mx0; m1v = mx1;

        float ls0 = 0.0f, ls1 = 0.0f;
#pragma unroll
        for (int nt = 0; nt < 8; nt++) {
            sa[nt][0] = __expf(sa[nt][0] - mx0);
            sa[nt][1] = __expf(sa[nt][1] - mx0);
            sa[nt][2] = __expf(sa[nt][2] - mx1);
            sa[nt][3] = __expf(sa[nt][3] - mx1);
            ls0 += sa[nt][0] + sa[nt][1];
            ls1 += sa[nt][2] + sa[nt][3];
        }
        ls0 += __shfl_xor_sync(0xffffffffu, ls0, 1);
        ls0 += __shfl_xor_sync(0xffffffffu, ls0, 2);
        ls1 += __shfl_xor_sync(0xffffffffu, ls1, 1);
        ls1 += __shfl_xor_sync(0xffffffffu, ls1, 2);
        l0v = l0v * alpha0 + ls0;
        l1v = l1v * alpha1 + ls1;

#pragma unroll
        for (int nt = 0; nt < 16; nt++) {
            accO[nt][0] *= alpha0; accO[nt][1] *= alpha0;
            accO[nt][2] *= alpha1; accO[nt][3] *= alpha1;
        }

        // ---- P split into bf16 hi/lo A-fragments ----
        uint32_t phA[8], phB[8], plA[8], plB[8];
#pragma unroll
        for (int nt = 0; nt < 8; nt++) {
            float h0 = __bfloat162float(__float2bfloat16(sa[nt][0]));
            float h1 = __bfloat162float(__float2bfloat16(sa[nt][1]));
            float h2 = __bfloat162float(__float2bfloat16(sa[nt][2]));
            float h3 = __bfloat162float(__float2bfloat16(sa[nt][3]));
            phA[nt] = pack_bf16x2(h0, h1);
            phB[nt] = pack_bf16x2(h2, h3);
            plA[nt] = pack_bf16x2(sa[nt][0] - h0, sa[nt][1] - h1);
            plB[nt] = pack_bf16x2(sa[nt][2] - h2, sa[nt][3] - h3);
        }

        // ---- O += Ph*Vh + Pl*Vh + Ph*Vl  (Vh frags reused) ----
#pragma unroll
        for (int ki = 0; ki < 4; ki++) {
            uint32_t aH[4] = {phA[2 * ki], phB[2 * ki], phA[2 * ki + 1], phB[2 * ki + 1]};
            uint32_t aL[4] = {plA[2 * ki], plB[2 * ki], plA[2 * ki + 1], plB[2 * ki + 1]};
            int cb = ki * 32 + lhi;
#pragma unroll
            for (int np = 0; np < 8; np++) {
                int brow = np * 16 + lrow;
                uint32_t boff = brow * 128 + (cb ^ ((brow & 7) * 16));
                uint32_t vhf[4];
                ldsm_x4(vhf, sb + SVH(s) + boff);
                mma_bf16(accO[np * 2 + 0], aH, vhf[0], vhf[2]);
                mma_bf16(accO[np * 2 + 1], aH, vhf[1], vhf[3]);
                mma_bf16(accO[np * 2 + 0], aL, vhf[0], vhf[2]);
                mma_bf16(accO[np * 2 + 1], aL, vhf[1], vhf[3]);
                uint32_t vlf[4];
                ldsm_x4(vlf, sb + SVL(s) + boff);
                mma_bf16(accO[np * 2 + 0], aH, vlf[0], vlf[2]);
                mma_bf16(accO[np * 2 + 1], aH, vlf[1], vlf[3]);
            }
        }
    }

    // ---- epilogue: O/l -> fp16 hi/lo planes ----
    float inv0 = 1.0f / l0v, inv1 = 1.0f / l1v;
#pragma unroll
    for (int nt = 0; nt < 16; nt++) {
        int col = h * HD + nt * 8 + (lid & 3) * 2;
        float o0 = accO[nt][0] * inv0, o1 = accO[nt][1] * inv0;
        float o2 = accO[nt][2] * inv1, o3 = accO[nt][3] * inv1;
        __half p0 = __float2half_rn(o0), p1 = __float2half_rn(o1);
        __half p2 = __float2half_rn(o2), p3 = __float2half_rn(o3);
        size_t r0 = (size_t)(b * 2048 + grow0) * HID + col;
        size_t r1 = (size_t)(b * 2048 + grow1) * HID + col;
        *(uint32_t*)(ohi + r0) = pack_h2(__half2float(p0), __half2float(p1));
        *(uint32_t*)(ohi + r1) = pack_h2(__half2float(p2), __half2float(p3));
        *(uint32_t*)(olo + r0) = pack_h2(o0 - __half2float(p0), o1 - __half2float(p1));
        *(uint32_t*)(olo + r1) = pack_h2(o2 - __half2float(p2), o3 - __half2float(p3));
    }
#undef LOAD_KV
}

// ---------------------------------------------------------------------------
// launch
// ---------------------------------------------------------------------------
extern "C" void kernel_launch(void* const* d_in, const int* in_sizes, int n_in,
                              void* d_out, int out_size)
{
    const float* x     = (const float*)d_in[0];
    const float* w_in  = (const float*)d_in[1];
    const float* w_out = (const float*)d_in[2];
    const float* qnw   = (const float*)d_in[3];
    const float* knw   = (const float*)d_in[4];
    float* out = (float*)d_out;

    float* qkv;  cudaGetSymbolAddress((void**)&qkv,  g_qkv);
    __half *ah, *al, *bhp, *blp;
    __nv_bfloat16 *qh, *ql, *kh, *kl, *vth, *vtl;
    cudaGetSymbolAddress((void**)&ah, g_a_hi);
    cudaGetSymbolAddress((void**)&al, g_a_lo);
    cudaGetSymbolAddress((void**)&bhp, g_b_hi);
    cudaGetSymbolAddress((void**)&blp, g_b_lo);
    cudaGetSymbolAddress((void**)&qh, g_q_hi);
    cudaGetSymbolAddress((void**)&ql, g_q_lo);
    cudaGetSymbolAddress((void**)&kh, g_k_hi);
    cudaGetSymbolAddress((void**)&kl, g_k_lo);
    cudaGetSymbolAddress((void**)&vth, g_vt_hi);
    cudaGetSymbolAddress((void**)&vtl, g_vt_lo);

    cudaFuncSetAttribute(gemm_t<2, 3, 2>, cudaFuncAttributeMaxDynamicSharedMemorySize, GEMM1_SMEM);
    cudaFuncSetAttribute(gemm_t<1, 2, 3>, cudaFuncAttributeMaxDynamicSharedMemorySize, GEMM2_SMEM);
    cudaFuncSetAttribute(attn_mma, cudaFuncAttributeMaxDynamicSharedMemorySize, ATTN_SMEM);

    // 1. split x -> a planes, w_in -> b planes (fp16)
    split2h_kernel<<<(ROWS * HID / 4 + 255) / 256, 256>>>(x, ah, al, ROWS * HID / 4);
    split2h_kernel<<<(QKV_W * HID / 4 + 255) / 256, 256>>>(w_in, bhp, blp, QKV_W * HID / 4);

    // 2. QKV = x @ w_in^T  (128x192 tiles -> 1024 CTAs, ~7 full waves)
    gemm_t<2, 3, 2><<<(ROWS / 128) * (QKV_W / 192), 512, GEMM1_SMEM>>>(
        ah, al, bhp, blp, qkv, ROWS, QKV_W, ROWS / 128);

    // 3. tables + norm/rope -> bf16 planes; V transpose/split
    rope_table_kernel<<<(S_ * HALF + 255) / 256, 256>>>();
    normrope_kernel<<<ROWS, 256>>>(qkv, qnw, knw, qh, ql, kh, kl);
    vtrans_kernel<<<dim3(ROWS / 32, HID / 32), 256>>>(qkv, vth, vtl);

    // 4. attention -> fp16 a planes (gemm2 A operand)
    attn_mma<<<dim3(S_ / 128, B_ * NH), 256, ATTN_SMEM>>>(qh, ql, kh, kl, vth, vtl, ah, al);

    // 5. w_out -> b planes; out = O @ w_out^T  (64x128 tiles -> 1024 CTAs)
    split2h_kernel<<<(HID * HID / 4 + 255) / 256, 256>>>(w_out, bhp, blp, HID * HID / 4);
    gemm_t<1, 2, 3><<<(ROWS / 64) * (HID / 128), 512, GEMM2_SMEM>>>(
        ah, al, bhp, blp, out, ROWS, HID, ROWS / 64);
}

// round 10
// speedup vs baseline: 1.3020x; 1.2781x over previous
#include <cuda_runtime.h>
#include <cuda_bf16.h>
#include <cuda_fp16.h>
#include <cstdint>
#include <math.h>

// Problem constants
#define B_  2
#define S_  2048
#define HID 2048
#define NH  16
#define HD  128
#define HALF 64
#define ROWS (B_ * S_)            // 4096
#define QKV_W (3 * HID)           // 6144
#define EPS 1e-5f
#define SCALE 0.08838834764831845f   // 1/sqrt(128)

// Scratch (device-global; no runtime allocation allowed)
__device__ float g_qkv[(size_t)ROWS * QKV_W];            // gemm1 out (fp32)
__device__ float g_cos[S_ * HALF];
__device__ float g_sin[S_ * HALF];
__device__ __half g_a_hi[(size_t)ROWS * HID];            // gemm A hi plane (x; then O)
__device__ __half g_a_lo[(size_t)ROWS * HID];
__device__ __half g_b_hi[(size_t)QKV_W * HID];           // gemm B plane (w_in; then w_out)
__device__ __nv_bfloat16 g_q_hi[(size_t)ROWS * HID];
__device__ __nv_bfloat16 g_q_lo[(size_t)ROWS * HID];
__device__ __nv_bfloat16 g_k_hi[(size_t)ROWS * HID];
__device__ __nv_bfloat16 g_k_lo[(size_t)ROWS * HID];
__device__ __nv_bfloat16 g_vt_hi[(size_t)ROWS * HID];    // [b][h][d][s]
__device__ __nv_bfloat16 g_vt_lo[(size_t)ROWS * HID];

__device__ __forceinline__ uint32_t smem_u32(const void* p) {
    uint32_t a;
    asm("{ .reg .u64 t; cvta.to.shared.u64 t, %1; cvt.u32.u64 %0, t; }" : "=r"(a) : "l"(p));
    return a;
}
#define SWZ(x) ((x) ^ (((x) >> 3) & 0x70))

__device__ __forceinline__ void ldsm_x4(uint32_t* r, uint32_t addr) {
    asm volatile("ldmatrix.sync.aligned.m8n8.x4.shared.b16 {%0,%1,%2,%3}, [%4];"
                 : "=r"(r[0]), "=r"(r[1]), "=r"(r[2]), "=r"(r[3]) : "r"(addr));
}
// bf16 in, f32 acc (attention)
__device__ __forceinline__ void mma_bf16(float* c, const uint32_t* a,
                                         uint32_t b0, uint32_t b1) {
    asm volatile(
        "mma.sync.aligned.m16n8k16.row.col.f32.bf16.bf16.f32 "
        "{%0,%1,%2,%3}, {%4,%5,%6,%7}, {%8,%9}, {%0,%1,%2,%3};"
        : "+f"(c[0]), "+f"(c[1]), "+f"(c[2]), "+f"(c[3])
        : "r"(a[0]), "r"(a[1]), "r"(a[2]), "r"(a[3]), "r"(b0), "r"(b1));
}
// fp16 in, f32 acc (gemm)
__device__ __forceinline__ void mma_f16f32(float* c, const uint32_t* a,
                                           uint32_t b0, uint32_t b1) {
    asm volatile(
        "mma.sync.aligned.m16n8k16.row.col.f32.f16.f16.f32 "
        "{%0,%1,%2,%3}, {%4,%5,%6,%7}, {%8,%9}, {%0,%1,%2,%3};"
        : "+f"(c[0]), "+f"(c[1]), "+f"(c[2]), "+f"(c[3])
        : "r"(a[0]), "r"(a[1]), "r"(a[2]), "r"(a[3]), "r"(b0), "r"(b1));
}
__device__ __forceinline__ uint32_t pack_bf16x2(float lo, float hi) {
    uint32_t r;
    asm("cvt.rn.bf16x2.f32 %0, %1, %2;" : "=r"(r) : "f"(hi), "f"(lo));
    return r;
}
__device__ __forceinline__ uint32_t pack_h2(float lo, float hi) {
    __half2 h = __floats2half2_rn(lo, hi);
    return *(uint32_t*)&h;
}

// ---------------------------------------------------------------------------
// RoPE table
// ---------------------------------------------------------------------------
__global__ void rope_table_kernel() {
    int idx = blockIdx.x * blockDim.x + threadIdx.x;
    if (idx >= S_ * HALF) return;
    int s = idx >> 6;
    int j = idx & 63;
    float freq = powf(10000.0f, -(float)j * (1.0f / 64.0f));
    float sn, cs;
    sincosf((float)s * freq, &sn, &cs);
    g_cos[idx] = cs;
    g_sin[idx] = sn;
}

// ---------------------------------------------------------------------------
// fp16 hi/lo split: fp32 -> two fp16 planes (flat)
// ---------------------------------------------------------------------------
__global__ void __launch_bounds__(256) split2h_kernel(
    const float* __restrict__ src, __half* __restrict__ hi,
    __half* __restrict__ lo, int n4)
{
    int i = blockIdx.x * blockDim.x + threadIdx.x;
    if (i >= n4) return;
    float4 v = ((const float4*)src)[i];
    float vv[4] = {v.x, v.y, v.z, v.w};
    uint64_t hp = 0, lp = 0;
#pragma unroll
    for (int q = 0; q < 4; q++) {
        __half h = __float2half_rn(vv[q]);
        __half l = __float2half_rn(vv[q] - __half2float(h));
        hp |= (uint64_t)__half_as_ushort(h) << (q * 16);
        lp |= (uint64_t)__half_as_ushort(l) << (q * 16);
    }
    *(uint64_t*)(hi + (size_t)i * 4) = hp;
    *(uint64_t*)(lo + (size_t)i * 4) = lp;
}

// fp32 -> fp16 single-plane round (B operand)
__global__ void __launch_bounds__(256) tohalf_kernel(
    const float* __restrict__ src, __half* __restrict__ dst, int n4)
{
    int i = blockIdx.x * blockDim.x + threadIdx.x;
    if (i >= n4) return;
    float4 v = ((const float4*)src)[i];
    uint64_t hp = 0;
    hp |= (uint64_t)__half_as_ushort(__float2half_rn(v.x));
    hp |= (uint64_t)__half_as_ushort(__float2half_rn(v.y)) << 16;
    hp |= (uint64_t)__half_as_ushort(__float2half_rn(v.z)) << 32;
    hp |= (uint64_t)__half_as_ushort(__float2half_rn(v.w)) << 48;
    *(uint64_t*)(dst + (size_t)i * 4) = hp;
}

// ---------------------------------------------------------------------------
// 2-term fp16 split GEMM (f32 acc):  C = Ah*Bh^T + Al*Bh^T
// Templated tile: BM = MT*64, BN = NP*64. 512 threads, 16 warps (4x4 grid),
// warp tile (MT*16) x (NP*16). BK=64, NSTG-stage cp.async pipeline.
// B is a single fp16 plane (its rounding error ~2^-12 is the dropped term).
// ---------------------------------------------------------------------------
template<int MT, int NP, int NSTG>
__global__ void __launch_bounds__(512, 1) gemm_t(
    const __half* __restrict__ Ah, const __half* __restrict__ Al,
    const __half* __restrict__ Bh,
    float* __restrict__ C, int M, int N, int tiles_m)
{
    constexpr int BM = MT * 64;
    constexpr int BN = NP * 64;
    constexpr int A_PLANE = BM * 128;
    constexpr int B_PLANE = BN * 128;
    constexpr int SAH = 0, SAL = A_PLANE;
    constexpr int SBH = 2 * A_PLANE;
    constexpr int STG = 2 * A_PLANE + B_PLANE;
    constexpr int ACH = BM * 16;          // 16B chunks across A hi+lo planes
    constexpr int BCH = BN * 8;           // 16B chunks in B plane
    constexpr int NLD = (ACH + BCH) / 512;
    static_assert((ACH + BCH) % 512 == 0, "loader divisibility");
    constexpr int NKT = HID / 64;         // 32

    extern __shared__ char smem[];
    const uint32_t sb = smem_u32(smem);
    const int tid = threadIdx.x;
    const int wid = tid >> 5, lid = tid & 31;
    const int m0 = (blockIdx.x % tiles_m) * BM;
    const int n0 = (blockIdx.x / tiles_m) * BN;
    const int wm = (wid & 3) * (MT * 16);
    const int wn = (wid >> 2) * (NP * 16);
    const int lrow = lid & 15;
    const int lhi = (lid >> 4) * 16;

    auto load_stage = [&](int st, int kt) {
        uint32_t sbase = sb + st * STG;
#pragma unroll
        for (int u = 0; u < NLD; u++) {
            int c = tid + u * 512;
            const __half* gp;
            uint32_t dst;
            if (c < ACH) {
                int plane = c / (ACH / 2);
                int cc = c % (ACH / 2);
                int r = cc >> 3, c16 = cc & 7;
                gp = (plane ? Al : Ah) + (size_t)(m0 + r) * HID + kt * 64 + c16 * 8;
                dst = sbase + (plane ? SAL : SAH) + SWZ(r * 128 + c16 * 16);
            } else {
                int cc = c - ACH;
                int r = cc >> 3, c16 = cc & 7;
                gp = Bh + (size_t)(n0 + r) * HID + kt * 64 + c16 * 8;
                dst = sbase + SBH + SWZ(r * 128 + c16 * 16);
            }
            asm volatile("cp.async.cg.shared.global [%0], [%1], 16;"
                         :: "r"(dst), "l"(gp) : "memory");
        }
    };

#pragma unroll
    for (int s = 0; s < NSTG - 1; s++) {
        load_stage(s, s);
        asm volatile("cp.async.commit_group;" ::: "memory");
    }

    float acc[MT][NP * 2][4];
#pragma unroll
    for (int mt = 0; mt < MT; mt++)
#pragma unroll
        for (int nt = 0; nt < NP * 2; nt++)
#pragma unroll
            for (int q = 0; q < 4; q++) acc[mt][nt][q] = 0.0f;

    for (int kt = 0; kt < NKT; kt++) {
        if (kt + NSTG - 1 < NKT) load_stage((kt + NSTG - 1) % NSTG, kt + NSTG - 1);
        asm volatile("cp.async.commit_group;" ::: "memory");
        asm volatile("cp.async.wait_group %0;" :: "n"(NSTG - 1) : "memory");
        __syncthreads();

        const uint32_t sbase = sb + (kt % NSTG) * STG;

#pragma unroll
        for (int ks = 0; ks < 4; ks++) {
            const int cb = ks * 32 + lhi;
            uint32_t ahf[MT][4], alf[MT][4];
#pragma unroll
            for (int mt = 0; mt < MT; mt++) {
                int row = wm + mt * 16 + lrow;
                uint32_t off = row * 128 + (cb ^ ((row & 7) * 16));
                ldsm_x4(ahf[mt], sbase + SAH + off);
                ldsm_x4(alf[mt], sbase + SAL + off);
            }
#pragma unroll
            for (int np = 0; np < NP; np++) {
                int brow = wn + np * 16 + lrow;
                uint32_t boff = brow * 128 + (cb ^ ((brow & 7) * 16));
                uint32_t bh4[4];
                ldsm_x4(bh4, sbase + SBH + boff);
#pragma unroll
                for (int mt = 0; mt < MT; mt++) {
                    mma_f16f32(acc[mt][np * 2 + 0], ahf[mt], bh4[0], bh4[2]);
                    mma_f16f32(acc[mt][np * 2 + 1], ahf[mt], bh4[1], bh4[3]);
                    mma_f16f32(acc[mt][np * 2 + 0], alf[mt], bh4[0], bh4[2]);
                    mma_f16f32(acc[mt][np * 2 + 1], alf[mt], bh4[1], bh4[3]);
                }
            }
        }
        __syncthreads();
    }

    const int er = m0 + wm + (lid >> 2);
    const int ec = n0 + wn + (lid & 3) * 2;
#pragma unroll
    for (int mt = 0; mt < MT; mt++)
#pragma unroll
        for (int nt = 0; nt < NP * 2; nt++) {
            float* c0 = C + (size_t)(er + mt * 16) * N + ec + nt * 8;
            *(float2*)c0 = make_float2(acc[mt][nt][0], acc[mt][nt][1]);
            float* c1 = c0 + 8 * N;
            *(float2*)c1 = make_float2(acc[mt][nt][2], acc[mt][nt][3]);
        }
}

// gemm1: 128x192 tile, 3 stages (168KB). gemm2: 64x128 tile, 4 stages (128KB).
#define GEMM1_SMEM (3 * (2 * 128 * 128 + 192 * 128))   // 172032
#define GEMM2_SMEM (4 * (2 * 64 * 128 + 128 * 128))    // 131072

// ---------------------------------------------------------------------------
// Fused qk RMSNorm + RoPE -> bf16 hi/lo planes. Q scaled by 1/sqrt(HD).
// ---------------------------------------------------------------------------
__global__ void __launch_bounds__(256) normrope_kernel(
    const float* __restrict__ qkv,
    const float* __restrict__ nw_q, const float* __restrict__ nw_k,
    __nv_bfloat16* __restrict__ qh, __nv_bfloat16* __restrict__ ql,
    __nv_bfloat16* __restrict__ kh, __nv_bfloat16* __restrict__ kl)
{
    __shared__ float buf[HID];
    __shared__ float warpred[8];

    const int row = blockIdx.x;
    const int s = row & (S_ - 1);
    const int tid = threadIdx.x;

#pragma unroll
    for (int part = 0; part < 2; part++) {
        const float* src = qkv + (size_t)row * QKV_W + part * HID;
        const float* w = (part == 0) ? nw_q : nw_k;
        __nv_bfloat16* dh = (part == 0) ? qh : kh;
        __nv_bfloat16* dl = (part == 0) ? ql : kl;

        float ss = 0.0f;
#pragma unroll
        for (int u = 0; u < 8; u++) {
            int idx = tid + u * 256;
            float v = src[idx];
            buf[idx] = v;
            ss += v * v;
        }
#pragma unroll
        for (int o = 16; o; o >>= 1) ss += __shfl_xor_sync(0xffffffffu, ss, o);
        if ((tid & 31) == 0) warpred[tid >> 5] = ss;
        __syncthreads();
        float tot = 0.0f;
#pragma unroll
        for (int wi = 0; wi < 8; wi++) tot += warpred[wi];
        float rn = rsqrtf(tot * (1.0f / (float)HID) + EPS);
        if (part == 0) rn *= SCALE;

#pragma unroll
        for (int u = 0; u < 4; u++) {
            int p = tid + u * 256;
            int hh = p >> 6;
            int j = p & 63;
            int i1 = hh * HD + j;
            int i2 = i1 + HALF;
            float x1 = buf[i1] * rn * w[i1];
            float x2 = buf[i2] * rn * w[i2];
            float cs = g_cos[s * HALF + j];
            float sn = g_sin[s * HALF + j];
            float o1 = x1 * cs - x2 * sn;
            float o2 = x2 * cs + x1 * sn;
            __nv_bfloat16 h1 = __float2bfloat16(o1);
            __nv_bfloat16 h2 = __float2bfloat16(o2);
            size_t base = (size_t)row * HID;
            dh[base + i1] = h1;
            dh[base + i2] = h2;
            dl[base + i1] = __float2bfloat16(o1 - __bfloat162float(h1));
            dl[base + i2] = __float2bfloat16(o2 - __bfloat162float(h2));
        }
        __syncthreads();
    }
}

// ---------------------------------------------------------------------------
// V transpose + split: g_qkv v cols -> vt_hi/vt_lo [b][h][d][s]
// ---------------------------------------------------------------------------
__global__ void __launch_bounds__(256) vtrans_kernel(
    const float* __restrict__ qkv,
    __nv_bfloat16* __restrict__ vth, __nv_bfloat16* __restrict__ vtl)
{
    __shared__ float t[32][33];
    const int row0 = blockIdx.x * 32;
    const int col0 = blockIdx.y * 32;
    const int tx = threadIdx.x & 31;
    const int ty = threadIdx.x >> 5;
#pragma unroll
    for (int i = 0; i < 4; i++) {
        int r = ty + i * 8;
        t[r][tx] = qkv[(size_t)(row0 + r) * QKV_W + 2 * HID + col0 + tx];
    }
    __syncthreads();
    const int b = row0 >> 11;
    const int s0 = row0 & 2047;
#pragma unroll
    for (int i = 0; i < 4; i++) {
        int c = ty + i * 8;
        float v = t[tx][c];
        __nv_bfloat16 h = __float2bfloat16(v);
        size_t o = ((size_t)(b * 2048 + col0 + c)) * 2048 + s0 + tx;
        vth[o] = h;
        vtl[o] = __float2bfloat16(v - __bfloat162float(h));
    }
}

// ---------------------------------------------------------------------------
// Flash attention, bf16 mma.sync, 3-term split, hoisted Q fragments in regs,
// fully-masked-warp ktile skip. 128 q rows x (b,h), 8 warps, 2-stage KV.
// Output -> fp16 g_a_hi / g_a_lo planes (gemm2 A operand).
// ---------------------------------------------------------------------------
#define SQH 0
#define SQL 32768
#define SKH(s) (65536 + (s) * 65536)
#define SKL(s) (SKH(s) + 16384)
#define SVH(s) (SKH(s) + 32768)
#define SVL(s) (SKH(s) + 49152)
#define ATTN_SMEM (65536 + 2 * 65536)   // 196608

__global__ void __launch_bounds__(256, 1) attn_mma(
    const __nv_bfloat16* __restrict__ qh, const __nv_bfloat16* __restrict__ ql,
    const __nv_bfloat16* __restrict__ kh, const __nv_bfloat16* __restrict__ kl,
    const __nv_bfloat16* __restrict__ vth, const __nv_bfloat16* __restrict__ vtl,
    __half* __restrict__ ohi, __half* __restrict__ olo)
{
    extern __shared__ char smem[];
    const uint32_t sb = smem_u32(smem);
    const int tid = threadIdx.x;
    const int wid = tid >> 5, lid = tid & 31;
    const int lrow = lid & 15;
    const int lhi = (lid >> 4) * 16;
    const int bh = blockIdx.y;
    const int b = bh >> 4, h = bh & 15;
    const int qt = gridDim.x - 1 - blockIdx.x;
    const int q0 = qt * 128;
    const int nkb = qt * 2 + 2;
    const int wm = wid * 16;

    // ---- load Q (hi+lo) into smem ----
#pragma unroll
    for (int u = 0; u < 16; u++) {
        int c = tid + u * 256;
        int plane = c >> 11;
        int cc = c & 2047;
        int r = cc >> 4, ch = cc & 15;
        int p = ch >> 3, c8 = ch & 7;
        const __nv_bfloat16* src = (plane ? ql : qh) +
            ((size_t)(b * 2048 + q0 + r) * HID + h * HD + ch * 8);
        uint32_t dst = sb + (plane ? SQL : SQH) + p * 16384 + SWZ(r * 128 + c8 * 16);
        asm volatile("cp.async.cg.shared.global [%0], [%1], 16;"
                     :: "r"(dst), "l"(src) : "memory");
    }
    asm volatile("cp.async.commit_group;" ::: "memory");

#define LOAD_KV(s, kt) do {                                                    \
    int k0 = (kt) * 64;                                                        \
    _Pragma("unroll")                                                          \
    for (int u = 0; u < 16; u++) {                                             \
        int c = tid + u * 256;                                                 \
        if (c < 2048) {                                                        \
            int plane = c >> 10;                                               \
            int cc = c & 1023;                                                 \
            int r = cc >> 4, ch = cc & 15;                                     \
            int p = ch >> 3, c8 = ch & 7;                                      \
            const __nv_bfloat16* src = (plane ? kl : kh) +                     \
                ((size_t)(b * 2048 + k0 + r) * HID + h * HD + ch * 8);         \
            uint32_t dst = sb + (plane ? SKL(s) : SKH(s)) + p * 8192 +         \
                           SWZ(r * 128 + c8 * 16);                             \
            asm volatile("cp.async.cg.shared.global [%0], [%1], 16;"           \
                         :: "r"(dst), "l"(src) : "memory");                    \
        } else {                                                               \
            int plane = (c >> 10) & 1;                                         \
            int cc = c & 1023;                                                 \
            int d = cc >> 3, c8 = cc & 7;                                      \
            const __nv_bfloat16* src = (plane ? vtl : vth) +                   \
                ((size_t)(b * 2048 + h * HD + d) * 2048 + k0 + c8 * 8);        \
            uint32_t dst = sb + (plane ? SVL(s) : SVH(s)) +                    \
                           SWZ(d * 128 + c8 * 16);                             \
            asm volatile("cp.async.cg.shared.global [%0], [%1], 16;"           \
                         :: "r"(dst), "l"(src) : "memory");                    \
        }                                                                      \
    }                                                                          \
} while (0)

    LOAD_KV(0, 0);
    asm volatile("cp.async.commit_group;" ::: "memory");

    // ---- hoist Q fragments into registers (Q smem never rewritten) ----
    asm volatile("cp.async.wait_group 1;" ::: "memory");
    __syncthreads();
    uint32_t qhr[8][4], qlr[8][4];
#pragma unroll
    for (int kk = 0; kk < 8; kk++) {
        int p = kk >> 2;
        int cb = (kk & 3) * 32 + lhi;
        int arow = wm + lrow;
        uint32_t aoff = p * 16384 + arow * 128 + (cb ^ ((arow & 7) * 16));
        ldsm_x4(qhr[kk], sb + SQH + aoff);
        ldsm_x4(qlr[kk], sb + SQL + aoff);
    }

    float accO[16][4];
#pragma unroll
    for (int nt = 0; nt < 16; nt++)
#pragma unroll
        for (int q = 0; q < 4; q++) accO[nt][q] = 0.0f;
    float m0v = -1e30f, m1v = -1e30f, l0v = 0.0f, l1v = 0.0f;

    const int grow0 = q0 + wm + (lid >> 2);
    const int grow1 = grow0 + 8;

    for (int kt = 0; kt < nkb; kt++) {
        __syncthreads();
        if (kt + 1 < nkb) LOAD_KV((kt + 1) & 1, kt + 1);
        asm volatile("cp.async.commit_group;" ::: "memory");
        asm volatile("cp.async.wait_group 1;" ::: "memory");
        __syncthreads();

        // fully-masked ktile for this warp? (all cols > all rows)
        if (kt * 64 > q0 + wm + 15) continue;

        const int s = kt & 1;

        // ---- S = Qh*Kh + Ql*Kh + Qh*Kl  (Q frags from regs) ----
        float sa[8][4];
#pragma unroll
        for (int nt = 0; nt < 8; nt++)
#pragma unroll
            for (int q = 0; q < 4; q++) sa[nt][q] = 0.0f;

#pragma unroll
        for (int kk = 0; kk < 8; kk++) {
            int p = kk >> 2;
            int cb = (kk & 3) * 32 + lhi;
#pragma unroll
            for (int np = 0; np < 4; np++) {
                int brow = np * 16 + lrow;
                uint32_t boff = p * 8192 + brow * 128 + (cb ^ ((brow & 7) * 16));
                uint32_t khf[4];
                ldsm_x4(khf, sb + SKH(s) + boff);
                mma_bf16(sa[np * 2 + 0], qhr[kk], khf[0], khf[2]);
                mma_bf16(sa[np * 2 + 1], qhr[kk], khf[1], khf[3]);
                mma_bf16(sa[np * 2 + 0], qlr[kk], khf[0], khf[2]);
                mma_bf16(sa[np * 2 + 1], qlr[kk], khf[1], khf[3]);
                uint32_t klf[4];
                ldsm_x4(klf, sb + SKL(s) + boff);
                mma_bf16(sa[np * 2 + 0], qhr[kk], klf[0], klf[2]);
                mma_bf16(sa[np * 2 + 1], qhr[kk], klf[1], klf[3]);
            }
        }

        // ---- causal mask ----
        if ((kt + 1) * 64 - 1 > q0 + wm) {
            const int colb = kt * 64 + (lid & 3) * 2;
#pragma unroll
            for (int nt = 0; nt < 8; nt++) {
                int col = colb + nt * 8;
                if (col > grow0)     sa[nt][0] = -1e30f;
                if (col + 1 > grow0) sa[nt][1] = -1e30f;
                if (col > grow1)     sa[nt][2] = -1e30f;
                if (col + 1 > grow1) sa[nt][3] = -1e30f;
            }
        }

        // ---- online softmax ----
        float mx0 = m0v, mx1 = m1v;
#pragma unroll
        for (int nt = 0; nt < 8; nt++) {
            mx0 = fmaxf(mx0, fmaxf(sa[nt][0], sa[nt][1]));
            mx1 = fmaxf(mx1, fmaxf(sa[nt][2], sa[nt][3]));
        }
        mx0 = fmaxf(mx0, __shfl_xor_sync(0xffffffffu, mx0, 1));
        mx0 = fmaxf(mx0, __shfl_xor_sync(0xffffffffu, mx0, 2));
        mx1 = fmaxf(mx1, __shfl_xor_sync(0xffffffffu, mx1, 1));
        mx1 = fmaxf(mx1, __shfl_xor_sync(0xffffffffu, mx1, 2));
        float alpha0 = __expf(m0v - mx0);
        float alpha1 = __expf(m1v - mx1);
        m0v = mx0; m1v = mx1;

        float ls0 = 0.0f, ls1 = 0.0f;
#pragma unroll
        for (int nt = 0; nt < 8; nt++) {
            sa[nt][0] = __expf(sa[nt][0] - mx0);
            sa[nt][1] = __expf(sa[nt][1] - mx0);
            sa[nt][2] = __expf(sa[nt][2] - mx1);
            sa[nt][3] = __expf(sa[nt][3] - mx1);
            ls0 += sa[nt][0] + sa[nt][1];
            ls1 += sa[nt][2] + sa[nt][3];
        }
        ls0 += __shfl_xor_sync(0xffffffffu, ls0, 1);
        ls0 += __shfl_xor_sync(0xffffffffu, ls0, 2);
        ls1 += __shfl_xor_sync(0xffffffffu, ls1, 1);
        ls1 += __shfl_xor_sync(0xffffffffu, ls1, 2);
        l0v = l0v * alpha0 + ls0;
        l1v = l1v * alpha1 + ls1;

#pragma unroll
        for (int nt = 0; nt < 16; nt++) {
            accO[nt][0] *= alpha0; accO[nt][1] *= alpha0;
            accO[nt][2] *= alpha1; accO[nt][3] *= alpha1;
        }

        // ---- P split into bf16 hi/lo A-fragments ----
        uint32_t phA[8], phB[8], plA[8], plB[8];
#pragma unroll
        for (int nt = 0; nt < 8; nt++) {
            float h0 = __bfloat162float(__float2bfloat16(sa[nt][0]));
            float h1 = __bfloat162float(__float2bfloat16(sa[nt][1]));
            float h2 = __bfloat162float(__float2bfloat16(sa[nt][2]));
            float h3 = __bfloat162float(__float2bfloat16(sa[nt][3]));
            phA[nt] = pack_bf16x2(h0, h1);
            phB[nt] = pack_bf16x2(h2, h3);
            plA[nt] = pack_bf16x2(sa[nt][0] - h0, sa[nt][1] - h1);
            plB[nt] = pack_bf16x2(sa[nt][2] - h2, sa[nt][3] - h3);
        }

        // ---- O += Ph*Vh + Pl*Vh + Ph*Vl  (Vh frags reused) ----
#pragma unroll
        for (int ki = 0; ki < 4; ki++) {
            uint32_t aH[4] = {phA[2 * ki], phB[2 * ki], phA[2 * ki + 1], phB[2 * ki + 1]};
            uint32_t aL[4] = {plA[2 * ki], plB[2 * ki], plA[2 * ki + 1], plB[2 * ki + 1]};
            int cb = ki * 32 + lhi;
#pragma unroll
            for (int np = 0; np < 8; np++) {
                int brow = np * 16 + lrow;
                uint32_t boff = brow * 128 + (cb ^ ((brow & 7) * 16));
                uint32_t vhf[4];
                ldsm_x4(vhf, sb + SVH(s) + boff);
                mma_bf16(accO[np * 2 + 0], aH, vhf[0], vhf[2]);
                mma_bf16(accO[np * 2 + 1], aH, vhf[1], vhf[3]);
                mma_bf16(accO[np * 2 + 0], aL, vhf[0], vhf[2]);
                mma_bf16(accO[np * 2 + 1], aL, vhf[1], vhf[3]);
                uint32_t vlf[4];
                ldsm_x4(vlf, sb + SVL(s) + boff);
                mma_bf16(accO[np * 2 + 0], aH, vlf[0], vlf[2]);
                mma_bf16(accO[np * 2 + 1], aH, vlf[1], vlf[3]);
            }
        }
    }

    // ---- epilogue: O/l -> fp16 hi/lo planes ----
    float inv0 = 1.0f / l0v, inv1 = 1.0f / l1v;
#pragma unroll
    for (int nt = 0; nt < 16; nt++) {
        int col = h * HD + nt * 8 + (lid & 3) * 2;
        float o0 = accO[nt][0] * inv0, o1 = accO[nt][1] * inv0;
        float o2 = accO[nt][2] * inv1, o3 = accO[nt][3] * inv1;
        __half p0 = __float2half_rn(o0), p1 = __float2half_rn(o1);
        __half p2 = __float2half_rn(o2), p3 = __float2half_rn(o3);
        size_t r0 = (size_t)(b * 2048 + grow0) * HID + col;
        size_t r1 = (size_t)(b * 2048 + grow1) * HID + col;
        *(uint32_t*)(ohi + r0) = pack_h2(__half2float(p0), __half2float(p1));
        *(uint32_t*)(ohi + r1) = pack_h2(__half2float(p2), __half2float(p3));
        *(uint32_t*)(olo + r0) = pack_h2(o0 - __half2float(p0), o1 - __half2float(p1));
        *(uint32_t*)(olo + r1) = pack_h2(o2 - __half2float(p2), o3 - __half2float(p3));
    }
#undef LOAD_KV
}

// ---------------------------------------------------------------------------
// launch
// ---------------------------------------------------------------------------
extern "C" void kernel_launch(void* const* d_in, const int* in_sizes, int n_in,
                              void* d_out, int out_size)
{
    const float* x     = (const float*)d_in[0];
    const float* w_in  = (const float*)d_in[1];
    const float* w_out = (const float*)d_in[2];
    const float* qnw   = (const float*)d_in[3];
    const float* knw   = (const float*)d_in[4];
    float* out = (float*)d_out;

    float* qkv;  cudaGetSymbolAddress((void**)&qkv,  g_qkv);
    __half *ah, *al, *bhp;
    __nv_bfloat16 *qh, *ql, *kh, *kl, *vth, *vtl;
    cudaGetSymbolAddress((void**)&ah, g_a_hi);
    cudaGetSymbolAddress((void**)&al, g_a_lo);
    cudaGetSymbolAddress((void**)&bhp, g_b_hi);
    cudaGetSymbolAddress((void**)&qh, g_q_hi);
    cudaGetSymbolAddress((void**)&ql, g_q_lo);
    cudaGetSymbolAddress((void**)&kh, g_k_hi);
    cudaGetSymbolAddress((void**)&kl, g_k_lo);
    cudaGetSymbolAddress((void**)&vth, g_vt_hi);
    cudaGetSymbolAddress((void**)&vtl, g_vt_lo);

    cudaFuncSetAttribute(gemm_t<2, 3, 3>, cudaFuncAttributeMaxDynamicSharedMemorySize, GEMM1_SMEM);
    cudaFuncSetAttribute(gemm_t<1, 2, 4>, cudaFuncAttributeMaxDynamicSharedMemorySize, GEMM2_SMEM);
    cudaFuncSetAttribute(attn_mma, cudaFuncAttributeMaxDynamicSharedMemorySize, ATTN_SMEM);

    // 1. split x -> a planes (hi/lo), round w_in -> b plane
    split2h_kernel<<<(ROWS * HID / 4 + 255) / 256, 256>>>(x, ah, al, ROWS * HID / 4);
    tohalf_kernel<<<(QKV_W * HID / 4 + 255) / 256, 256>>>(w_in, bhp, QKV_W * HID / 4);

    // 2. QKV = x @ w_in^T  (2-term split, 128x192 tiles, 1024 CTAs)
    gemm_t<2, 3, 3><<<(ROWS / 128) * (QKV_W / 192), 512, GEMM1_SMEM>>>(
        ah, al, bhp, qkv, ROWS, QKV_W, ROWS / 128);

    // 3. tables + norm/rope -> bf16 planes; V transpose/split
    rope_table_kernel<<<(S_ * HALF + 255) / 256, 256>>>();
    normrope_kernel<<<ROWS, 256>>>(qkv, qnw, knw, qh, ql, kh, kl);
    vtrans_kernel<<<dim3(ROWS / 32, HID / 32), 256>>>(qkv, vth, vtl);

    // 4. attention (3-term bf16, unchanged) -> fp16 a planes
    attn_mma<<<dim3(S_ / 128, B_ * NH), 256, ATTN_SMEM>>>(qh, ql, kh, kl, vth, vtl, ah, al);

    // 5. round w_out -> b plane; out = O @ w_out^T  (64x128 tiles, 1024 CTAs)
    tohalf_kernel<<<(HID * HID / 4 + 255) / 256, 256>>>(w_out, bhp, HID * HID / 4);
    gemm_t<1, 2, 4><<<(ROWS / 64) * (HID / 128), 512, GEMM2_SMEM>>>(
        ah, al, bhp, out, ROWS, HID, ROWS / 64);
}

// round 11
// speedup vs baseline: 1.4287x; 1.0973x over previous
#include <cuda_runtime.h>
#include <cuda_bf16.h>
#include <cuda_fp16.h>
#include <cstdint>
#include <math.h>

// Problem constants
#define B_  2
#define S_  2048
#define HID 2048
#define NH  16
#define HD  128
#define HALF 64
#define ROWS (B_ * S_)            // 4096
#define QKV_W (3 * HID)           // 6144
#define EPS 1e-5f
#define SCALE 0.08838834764831845f   // 1/sqrt(128)

// Scratch (device-global; no runtime allocation allowed)
__device__ float g_qkv[(size_t)ROWS * QKV_W];            // gemm1 out (fp32)
__device__ float g_cos[S_ * HALF];
__device__ float g_sin[S_ * HALF];
__device__ __half g_a_hi[(size_t)ROWS * HID];            // gemm A hi plane (x; then O)
__device__ __half g_a_lo[(size_t)ROWS * HID];
__device__ __half g_b_hi[(size_t)QKV_W * HID];           // gemm B plane (w_in; then w_out)
__device__ __half g_q_hi[(size_t)ROWS * HID];
__device__ __half g_q_lo[(size_t)ROWS * HID];
__device__ __half g_k_hi[(size_t)ROWS * HID];
__device__ __half g_k_lo[(size_t)ROWS * HID];
__device__ __half g_vt[(size_t)ROWS * HID];              // [b][h][d][s] single plane

__device__ __forceinline__ uint32_t smem_u32(const void* p) {
    uint32_t a;
    asm("{ .reg .u64 t; cvta.to.shared.u64 t, %1; cvt.u32.u64 %0, t; }" : "=r"(a) : "l"(p));
    return a;
}
#define SWZ(x) ((x) ^ (((x) >> 3) & 0x70))

__device__ __forceinline__ void ldsm_x4(uint32_t* r, uint32_t addr) {
    asm volatile("ldmatrix.sync.aligned.m8n8.x4.shared.b16 {%0,%1,%2,%3}, [%4];"
                 : "=r"(r[0]), "=r"(r[1]), "=r"(r[2]), "=r"(r[3]) : "r"(addr));
}
// fp16 in, f32 acc
__device__ __forceinline__ void mma_f16f32(float* c, const uint32_t* a,
                                           uint32_t b0, uint32_t b1) {
    asm volatile(
        "mma.sync.aligned.m16n8k16.row.col.f32.f16.f16.f32 "
        "{%0,%1,%2,%3}, {%4,%5,%6,%7}, {%8,%9}, {%0,%1,%2,%3};"
        : "+f"(c[0]), "+f"(c[1]), "+f"(c[2]), "+f"(c[3])
        : "r"(a[0]), "r"(a[1]), "r"(a[2]), "r"(a[3]), "r"(b0), "r"(b1));
}
__device__ __forceinline__ uint32_t pack_h2(float lo, float hi) {
    __half2 h = __floats2half2_rn(lo, hi);
    return *(uint32_t*)&h;
}

// ---------------------------------------------------------------------------
// RoPE table
// ---------------------------------------------------------------------------
__global__ void rope_table_kernel() {
    int idx = blockIdx.x * blockDim.x + threadIdx.x;
    if (idx >= S_ * HALF) return;
    int s = idx >> 6;
    int j = idx & 63;
    float freq = powf(10000.0f, -(float)j * (1.0f / 64.0f));
    float sn, cs;
    sincosf((float)s * freq, &sn, &cs);
    g_cos[idx] = cs;
    g_sin[idx] = sn;
}

// ---------------------------------------------------------------------------
// fp16 hi/lo split: fp32 -> two fp16 planes (flat)
// ---------------------------------------------------------------------------
__global__ void __launch_bounds__(256) split2h_kernel(
    const float* __restrict__ src, __half* __restrict__ hi,
    __half* __restrict__ lo, int n4)
{
    int i = blockIdx.x * blockDim.x + threadIdx.x;
    if (i >= n4) return;
    float4 v = ((const float4*)src)[i];
    float vv[4] = {v.x, v.y, v.z, v.w};
    uint64_t hp = 0, lp = 0;
#pragma unroll
    for (int q = 0; q < 4; q++) {
        __half h = __float2half_rn(vv[q]);
        __half l = __float2half_rn(vv[q] - __half2float(h));
        hp |= (uint64_t)__half_as_ushort(h) << (q * 16);
        lp |= (uint64_t)__half_as_ushort(l) << (q * 16);
    }
    *(uint64_t*)(hi + (size_t)i * 4) = hp;
    *(uint64_t*)(lo + (size_t)i * 4) = lp;
}

// fp32 -> fp16 single-plane round (B operand)
__global__ void __launch_bounds__(256) tohalf_kernel(
    const float* __restrict__ src, __half* __restrict__ dst, int n4)
{
    int i = blockIdx.x * blockDim.x + threadIdx.x;
    if (i >= n4) return;
    float4 v = ((const float4*)src)[i];
    uint64_t hp = 0;
    hp |= (uint64_t)__half_as_ushort(__float2half_rn(v.x));
    hp |= (uint64_t)__half_as_ushort(__float2half_rn(v.y)) << 16;
    hp |= (uint64_t)__half_as_ushort(__float2half_rn(v.z)) << 32;
    hp |= (uint64_t)__half_as_ushort(__float2half_rn(v.w)) << 48;
    *(uint64_t*)(dst + (size_t)i * 4) = hp;
}

// ---------------------------------------------------------------------------
// 2-term fp16 split GEMM (f32 acc):  C = Ah*Bh^T + Al*Bh^T
// Templated tile: BM = MT*64, BN = NP*64. 512 threads, 16 warps (4x4 grid),
// warp tile (MT*16) x (NP*16). BK=64, NSTG-stage cp.async pipeline.
// ---------------------------------------------------------------------------
template<int MT, int NP, int NSTG>
__global__ void __launch_bounds__(512, 1) gemm_t(
    const __half* __restrict__ Ah, const __half* __restrict__ Al,
    const __half* __restrict__ Bh,
    float* __restrict__ C, int M, int N, int tiles_m)
{
    constexpr int BM = MT * 64;
    constexpr int BN = NP * 64;
    constexpr int A_PLANE = BM * 128;
    constexpr int B_PLANE = BN * 128;
    constexpr int SAH = 0, SAL = A_PLANE;
    constexpr int SBH = 2 * A_PLANE;
    constexpr int STG = 2 * A_PLANE + B_PLANE;
    constexpr int ACH = BM * 16;
    constexpr int BCH = BN * 8;
    constexpr int NLD = (ACH + BCH) / 512;
    static_assert((ACH + BCH) % 512 == 0, "loader divisibility");
    constexpr int NKT = HID / 64;

    extern __shared__ char smem[];
    const uint32_t sb = smem_u32(smem);
    const int tid = threadIdx.x;
    const int wid = tid >> 5, lid = tid & 31;
    const int m0 = (blockIdx.x % tiles_m) * BM;
    const int n0 = (blockIdx.x / tiles_m) * BN;
    const int wm = (wid & 3) * (MT * 16);
    const int wn = (wid >> 2) * (NP * 16);
    const int lrow = lid & 15;
    const int lhi = (lid >> 4) * 16;

    auto load_stage = [&](int st, int kt) {
        uint32_t sbase = sb + st * STG;
#pragma unroll
        for (int u = 0; u < NLD; u++) {
            int c = tid + u * 512;
            const __half* gp;
            uint32_t dst;
            if (c < ACH) {
                int plane = c / (ACH / 2);
                int cc = c % (ACH / 2);
                int r = cc >> 3, c16 = cc & 7;
                gp = (plane ? Al : Ah) + (size_t)(m0 + r) * HID + kt * 64 + c16 * 8;
                dst = sbase + (plane ? SAL : SAH) + SWZ(r * 128 + c16 * 16);
            } else {
                int cc = c - ACH;
                int r = cc >> 3, c16 = cc & 7;
                gp = Bh + (size_t)(n0 + r) * HID + kt * 64 + c16 * 8;
                dst = sbase + SBH + SWZ(r * 128 + c16 * 16);
            }
            asm volatile("cp.async.cg.shared.global [%0], [%1], 16;"
                         :: "r"(dst), "l"(gp) : "memory");
        }
    };

#pragma unroll
    for (int s = 0; s < NSTG - 1; s++) {
        load_stage(s, s);
        asm volatile("cp.async.commit_group;" ::: "memory");
    }

    float acc[MT][NP * 2][4];
#pragma unroll
    for (int mt = 0; mt < MT; mt++)
#pragma unroll
        for (int nt = 0; nt < NP * 2; nt++)
#pragma unroll
            for (int q = 0; q < 4; q++) acc[mt][nt][q] = 0.0f;

    for (int kt = 0; kt < NKT; kt++) {
        if (kt + NSTG - 1 < NKT) load_stage((kt + NSTG - 1) % NSTG, kt + NSTG - 1);
        asm volatile("cp.async.commit_group;" ::: "memory");
        asm volatile("cp.async.wait_group %0;" :: "n"(NSTG - 1) : "memory");
        __syncthreads();

        const uint32_t sbase = sb + (kt % NSTG) * STG;

#pragma unroll
        for (int ks = 0; ks < 4; ks++) {
            const int cb = ks * 32 + lhi;
            uint32_t ahf[MT][4], alf[MT][4];
#pragma unroll
            for (int mt = 0; mt < MT; mt++) {
                int row = wm + mt * 16 + lrow;
                uint32_t off = row * 128 + (cb ^ ((row & 7) * 16));
                ldsm_x4(ahf[mt], sbase + SAH + off);
                ldsm_x4(alf[mt], sbase + SAL + off);
            }
#pragma unroll
            for (int np = 0; np < NP; np++) {
                int brow = wn + np * 16 + lrow;
                uint32_t boff = brow * 128 + (cb ^ ((brow & 7) * 16));
                uint32_t bh4[4];
                ldsm_x4(bh4, sbase + SBH + boff);
#pragma unroll
                for (int mt = 0; mt < MT; mt++) {
                    mma_f16f32(acc[mt][np * 2 + 0], ahf[mt], bh4[0], bh4[2]);
                    mma_f16f32(acc[mt][np * 2 + 1], ahf[mt], bh4[1], bh4[3]);
                    mma_f16f32(acc[mt][np * 2 + 0], alf[mt], bh4[0], bh4[2]);
                    mma_f16f32(acc[mt][np * 2 + 1], alf[mt], bh4[1], bh4[3]);
                }
            }
        }
        __syncthreads();
    }

    const int er = m0 + wm + (lid >> 2);
    const int ec = n0 + wn + (lid & 3) * 2;
#pragma unroll
    for (int mt = 0; mt < MT; mt++)
#pragma unroll
        for (int nt = 0; nt < NP * 2; nt++) {
            float* c0 = C + (size_t)(er + mt * 16) * N + ec + nt * 8;
            *(float2*)c0 = make_float2(acc[mt][nt][0], acc[mt][nt][1]);
            float* c1 = c0 + 8 * N;
            *(float2*)c1 = make_float2(acc[mt][nt][2], acc[mt][nt][3]);
        }
}

// gemm1: 128x192 tile, 3 stages (168KB). gemm2: 64x128 tile, 4 stages (128KB).
#define GEMM1_SMEM (3 * (2 * 128 * 128 + 192 * 128))   // 172032
#define GEMM2_SMEM (4 * (2 * 64 * 128 + 128 * 128))    // 131072

// ---------------------------------------------------------------------------
// Fused qk RMSNorm + RoPE -> fp16 hi/lo planes. Q scaled by 1/sqrt(HD).
// ---------------------------------------------------------------------------
__global__ void __launch_bounds__(256) normrope_kernel(
    const float* __restrict__ qkv,
    const float* __restrict__ nw_q, const float* __restrict__ nw_k,
    __half* __restrict__ qh, __half* __restrict__ ql,
    __half* __restrict__ kh, __half* __restrict__ kl)
{
    __shared__ float buf[HID];
    __shared__ float warpred[8];

    const int row = blockIdx.x;
    const int s = row & (S_ - 1);
    const int tid = threadIdx.x;

#pragma unroll
    for (int part = 0; part < 2; part++) {
        const float* src = qkv + (size_t)row * QKV_W + part * HID;
        const float* w = (part == 0) ? nw_q : nw_k;
        __half* dh = (part == 0) ? qh : kh;
        __half* dl = (part == 0) ? ql : kl;

        float ss = 0.0f;
#pragma unroll
        for (int u = 0; u < 8; u++) {
            int idx = tid + u * 256;
            float v = src[idx];
            buf[idx] = v;
            ss += v * v;
        }
#pragma unroll
        for (int o = 16; o; o >>= 1) ss += __shfl_xor_sync(0xffffffffu, ss, o);
        if ((tid & 31) == 0) warpred[tid >> 5] = ss;
        __syncthreads();
        float tot = 0.0f;
#pragma unroll
        for (int wi = 0; wi < 8; wi++) tot += warpred[wi];
        float rn = rsqrtf(tot * (1.0f / (float)HID) + EPS);
        if (part == 0) rn *= SCALE;

#pragma unroll
        for (int u = 0; u < 4; u++) {
            int p = tid + u * 256;
            int hh = p >> 6;
            int j = p & 63;
            int i1 = hh * HD + j;
            int i2 = i1 + HALF;
            float x1 = buf[i1] * rn * w[i1];
            float x2 = buf[i2] * rn * w[i2];
            float cs = g_cos[s * HALF + j];
            float sn = g_sin[s * HALF + j];
            float o1 = x1 * cs - x2 * sn;
            float o2 = x2 * cs + x1 * sn;
            __half h1 = __float2half_rn(o1);
            __half h2 = __float2half_rn(o2);
            size_t base = (size_t)row * HID;
            dh[base + i1] = h1;
            dh[base + i2] = h2;
            dl[base + i1] = __float2half_rn(o1 - __half2float(h1));
            dl[base + i2] = __float2half_rn(o2 - __half2float(h2));
        }
        __syncthreads();
    }
}

// ---------------------------------------------------------------------------
// V transpose: g_qkv v cols -> single fp16 plane vt [b][h][d][s]
// ---------------------------------------------------------------------------
__global__ void __launch_bounds__(256) vtrans_kernel(
    const float* __restrict__ qkv, __half* __restrict__ vt)
{
    __shared__ float t[32][33];
    const int row0 = blockIdx.x * 32;
    const int col0 = blockIdx.y * 32;
    const int tx = threadIdx.x & 31;
    const int ty = threadIdx.x >> 5;
#pragma unroll
    for (int i = 0; i < 4; i++) {
        int r = ty + i * 8;
        t[r][tx] = qkv[(size_t)(row0 + r) * QKV_W + 2 * HID + col0 + tx];
    }
    __syncthreads();
    const int b = row0 >> 11;
    const int s0 = row0 & 2047;
#pragma unroll
    for (int i = 0; i < 4; i++) {
        int c = ty + i * 8;
        float v = t[tx][c];
        size_t o = ((size_t)(b * 2048 + col0 + c)) * 2048 + s0 + tx;
        vt[o] = __float2half_rn(v);
    }
}

// ---------------------------------------------------------------------------
// Flash attention, fp16 mma.sync: QK 3-term (Qh,Ql x Kh,Kl), PV 1-term.
// 128 q rows x (b,h), 8 warps, 2-stage KV pipeline (48KB/stage).
// Output -> fp16 g_a_hi / g_a_lo planes (gemm2 A operand).
// ---------------------------------------------------------------------------
#define SQH 0
#define SQL 32768
#define KVSTG 49152
#define SKH(s) (65536 + (s) * KVSTG)
#define SKL(s) (SKH(s) + 16384)
#define SVH(s) (SKH(s) + 32768)
#define ATTN_SMEM (65536 + 2 * KVSTG)   // 163840

__global__ void __launch_bounds__(256, 1) attn_mma(
    const __half* __restrict__ qh, const __half* __restrict__ ql,
    const __half* __restrict__ kh, const __half* __restrict__ kl,
    const __half* __restrict__ vt,
    __half* __restrict__ ohi, __half* __restrict__ olo)
{
    extern __shared__ char smem[];
    const uint32_t sb = smem_u32(smem);
    const int tid = threadIdx.x;
    const int wid = tid >> 5, lid = tid & 31;
    const int lrow = lid & 15;
    const int lhi = (lid >> 4) * 16;
    const int bh = blockIdx.y;
    const int b = bh >> 4, h = bh & 15;
    const int qt = gridDim.x - 1 - blockIdx.x;
    const int q0 = qt * 128;
    const int nkb = qt * 2 + 2;
    const int wm = wid * 16;

    // ---- load Q (hi+lo) into smem ----
#pragma unroll
    for (int u = 0; u < 16; u++) {
        int c = tid + u * 256;
        int plane = c >> 11;
        int cc = c & 2047;
        int r = cc >> 4, ch = cc & 15;
        int p = ch >> 3, c8 = ch & 7;
        const __half* src = (plane ? ql : qh) +
            ((size_t)(b * 2048 + q0 + r) * HID + h * HD + ch * 8);
        uint32_t dst = sb + (plane ? SQL : SQH) + p * 16384 + SWZ(r * 128 + c8 * 16);
        asm volatile("cp.async.cg.shared.global [%0], [%1], 16;"
                     :: "r"(dst), "l"(src) : "memory");
    }
    asm volatile("cp.async.commit_group;" ::: "memory");

// 3072 16B-chunks per stage: K hi (1024) + K lo (1024) + V (1024)
#define LOAD_KV(s, kt) do {                                                    \
    int k0 = (kt) * 64;                                                        \
    _Pragma("unroll")                                                          \
    for (int u = 0; u < 12; u++) {                                             \
        int c = tid + u * 256;                                                 \
        if (c < 2048) {                                                        \
            int plane = c >> 10;                                               \
            int cc = c & 1023;                                                 \
            int r = cc >> 4, ch = cc & 15;                                     \
            int p = ch >> 3, c8 = ch & 7;                                      \
            const __half* src = (plane ? kl : kh) +                            \
                ((size_t)(b * 2048 + k0 + r) * HID + h * HD + ch * 8);         \
            uint32_t dst = sb + (plane ? SKL(s) : SKH(s)) + p * 8192 +         \
                           SWZ(r * 128 + c8 * 16);                             \
            asm volatile("cp.async.cg.shared.global [%0], [%1], 16;"           \
                         :: "r"(dst), "l"(src) : "memory");                    \
        } else {                                                               \
            int cc = c - 2048;                                                 \
            int d = cc >> 3, c8 = cc & 7;                                      \
            const __half* src = vt +                                           \
                ((size_t)(b * 2048 + h * HD + d) * 2048 + k0 + c8 * 8);        \
            uint32_t dst = sb + SVH(s) + SWZ(d * 128 + c8 * 16);               \
            asm volatile("cp.async.cg.shared.global [%0], [%1], 16;"           \
                         :: "r"(dst), "l"(src) : "memory");                    \
        }                                                                      \
    }                                                                          \
} while (0)

    LOAD_KV(0, 0);
    asm volatile("cp.async.commit_group;" ::: "memory");

    // ---- hoist Q fragments into registers (Q smem never rewritten) ----
    asm volatile("cp.async.wait_group 1;" ::: "memory");
    __syncthreads();
    uint32_t qhr[8][4], qlr[8][4];
#pragma unroll
    for (int kk = 0; kk < 8; kk++) {
        int p = kk >> 2;
        int cb = (kk & 3) * 32 + lhi;
        int arow = wm + lrow;
        uint32_t aoff = p * 16384 + arow * 128 + (cb ^ ((arow & 7) * 16));
        ldsm_x4(qhr[kk], sb + SQH + aoff);
        ldsm_x4(qlr[kk], sb + SQL + aoff);
    }

    float accO[16][4];
#pragma unroll
    for (int nt = 0; nt < 16; nt++)
#pragma unroll
        for (int q = 0; q < 4; q++) accO[nt][q] = 0.0f;
    float m0v = -1e30f, m1v = -1e30f, l0v = 0.0f, l1v = 0.0f;

    const int grow0 = q0 + wm + (lid >> 2);
    const int grow1 = grow0 + 8;

    for (int kt = 0; kt < nkb; kt++) {
        __syncthreads();
        if (kt + 1 < nkb) LOAD_KV((kt + 1) & 1, kt + 1);
        asm volatile("cp.async.commit_group;" ::: "memory");
        asm volatile("cp.async.wait_group 1;" ::: "memory");
        __syncthreads();

        // fully-masked ktile for this warp?
        if (kt * 64 > q0 + wm + 15) continue;

        const int s = kt & 1;

        // ---- S = Qh*Kh + Ql*Kh + Qh*Kl  (fp16, Q frags from regs) ----
        float sa[8][4];
#pragma unroll
        for (int nt = 0; nt < 8; nt++)
#pragma unroll
            for (int q = 0; q < 4; q++) sa[nt][q] = 0.0f;

#pragma unroll
        for (int kk = 0; kk < 8; kk++) {
            int p = kk >> 2;
            int cb = (kk & 3) * 32 + lhi;
#pragma unroll
            for (int np = 0; np < 4; np++) {
                int brow = np * 16 + lrow;
                uint32_t boff = p * 8192 + brow * 128 + (cb ^ ((brow & 7) * 16));
                uint32_t khf[4];
                ldsm_x4(khf, sb + SKH(s) + boff);
                mma_f16f32(sa[np * 2 + 0], qhr[kk], khf[0], khf[2]);
                mma_f16f32(sa[np * 2 + 1], qhr[kk], khf[1], khf[3]);
                mma_f16f32(sa[np * 2 + 0], qlr[kk], khf[0], khf[2]);
                mma_f16f32(sa[np * 2 + 1], qlr[kk], khf[1], khf[3]);
                uint32_t klf[4];
                ldsm_x4(klf, sb + SKL(s) + boff);
                mma_f16f32(sa[np * 2 + 0], qhr[kk], klf[0], klf[2]);
                mma_f16f32(sa[np * 2 + 1], qhr[kk], klf[1], klf[3]);
            }
        }

        // ---- causal mask ----
        if ((kt + 1) * 64 - 1 > q0 + wm) {
            const int colb = kt * 64 + (lid & 3) * 2;
#pragma unroll
            for (int nt = 0; nt < 8; nt++) {
                int col = colb + nt * 8;
                if (col > grow0)     sa[nt][0] = -1e30f;
                if (col + 1 > grow0) sa[nt][1] = -1e30f;
                if (col > grow1)     sa[nt][2] = -1e30f;
                if (col + 1 > grow1) sa[nt][3] = -1e30f;
            }
        }

        // ---- online softmax ----
        float mx0 = m0v, mx1 = m1v;
#pragma unroll
        for (int nt = 0; nt < 8; nt++) {
            mx0 = fmaxf(mx0, fmaxf(sa[nt][0], sa[nt][1]));
            mx1 = fmaxf(mx1, fmaxf(sa[nt][2], sa[nt][3]));
        }
        mx0 = fmaxf(mx0, __shfl_xor_sync(0xffffffffu, mx0, 1));
        mx0 = fmaxf(mx0, __shfl_xor_sync(0xffffffffu, mx0, 2));
        mx1 = fmaxf(mx1, __shfl_xor_sync(0xffffffffu, mx1, 1));
        mx1 = fmaxf(mx1, __shfl_xor_sync(0xffffffffu, mx1, 2));
        float alpha0 = __expf(m0v - mx0);
        float alpha1 = __expf(m1v - mx1);
        m0v = mx0; m1v = mx1;

        float ls0 = 0.0f, ls1 = 0.0f;
#pragma unroll
        for (int nt = 0; nt < 8; nt++) {
            sa[nt][0] = __expf(sa[nt][0] - mx0);
            sa[nt][1] = __expf(sa[nt][1] - mx0);
            sa[nt][2] = __expf(sa[nt][2] - mx1);
            sa[nt][3] = __expf(sa[nt][3] - mx1);
            ls0 += sa[nt][0] + sa[nt][1];
            ls1 += sa[nt][2] + sa[nt][3];
        }
        ls0 += __shfl_xor_sync(0xffffffffu, ls0, 1);
        ls0 += __shfl_xor_sync(0xffffffffu, ls0, 2);
        ls1 += __shfl_xor_sync(0xffffffffu, ls1, 1);
        ls1 += __shfl_xor_sync(0xffffffffu, ls1, 2);
        l0v = l0v * alpha0 + ls0;
        l1v = l1v * alpha1 + ls1;

#pragma unroll
        for (int nt = 0; nt < 16; nt++) {
            accO[nt][0] *= alpha0; accO[nt][1] *= alpha0;
            accO[nt][2] *= alpha1; accO[nt][3] *= alpha1;
        }

        // ---- P -> fp16 A-fragments (single plane) ----
        uint32_t phA[8], phB[8];
#pragma unroll
        for (int nt = 0; nt < 8; nt++) {
            phA[nt] = pack_h2(sa[nt][0], sa[nt][1]);
            phB[nt] = pack_h2(sa[nt][2], sa[nt][3]);
        }

        // ---- O += P*V  (1-term fp16) ----
#pragma unroll
        for (int ki = 0; ki < 4; ki++) {
            uint32_t aH[4] = {phA[2 * ki], phB[2 * ki], phA[2 * ki + 1], phB[2 * ki + 1]};
            int cb = ki * 32 + lhi;
#pragma unroll
            for (int np = 0; np < 8; np++) {
                int brow = np * 16 + lrow;
                uint32_t boff = brow * 128 + (cb ^ ((brow & 7) * 16));
                uint32_t vhf[4];
                ldsm_x4(vhf, sb + SVH(s) + boff);
                mma_f16f32(accO[np * 2 + 0], aH, vhf[0], vhf[2]);
                mma_f16f32(accO[np * 2 + 1], aH, vhf[1], vhf[3]);
            }
        }
    }

    // ---- epilogue: O/l -> fp16 hi/lo planes ----
    float inv0 = 1.0f / l0v, inv1 = 1.0f / l1v;
#pragma unroll
    for (int nt = 0; nt < 16; nt++) {
        int col = h * HD + nt * 8 + (lid & 3) * 2;
        float o0 = accO[nt][0] * inv0, o1 = accO[nt][1] * inv0;
        float o2 = accO[nt][2] * inv1, o3 = accO[nt][3] * inv1;
        __half p0 = __float2half_rn(o0), p1 = __float2half_rn(o1);
        __half p2 = __float2half_rn(o2), p3 = __float2half_rn(o3);
        size_t r0 = (size_t)(b * 2048 + grow0) * HID + col;
        size_t r1 = (size_t)(b * 2048 + grow1) * HID + col;
        *(uint32_t*)(ohi + r0) = pack_h2(__half2float(p0), __half2float(p1));
        *(uint32_t*)(ohi + r1) = pack_h2(__half2float(p2), __half2float(p3));
        *(uint32_t*)(olo + r0) = pack_h2(o0 - __half2float(p0), o1 - __half2float(p1));
        *(uint32_t*)(olo + r1) = pack_h2(o2 - __half2float(p2), o3 - __half2float(p3));
    }
#undef LOAD_KV
}

// ---------------------------------------------------------------------------
// launch
// ---------------------------------------------------------------------------
extern "C" void kernel_launch(void* const* d_in, const int* in_sizes, int n_in,
                              void* d_out, int out_size)
{
    const float* x     = (const float*)d_in[0];
    const float* w_in  = (const float*)d_in[1];
    const float* w_out = (const float*)d_in[2];
    const float* qnw   = (const float*)d_in[3];
    const float* knw   = (const float*)d_in[4];
    float* out = (float*)d_out;

    float* qkv;  cudaGetSymbolAddress((void**)&qkv,  g_qkv);
    __half *ah, *al, *bhp, *qh, *ql, *kh, *kl, *vt;
    cudaGetSymbolAddress((void**)&ah, g_a_hi);
    cudaGetSymbolAddress((void**)&al, g_a_lo);
    cudaGetSymbolAddress((void**)&bhp, g_b_hi);
    cudaGetSymbolAddress((void**)&qh, g_q_hi);
    cudaGetSymbolAddress((void**)&ql, g_q_lo);
    cudaGetSymbolAddress((void**)&kh, g_k_hi);
    cudaGetSymbolAddress((void**)&kl, g_k_lo);
    cudaGetSymbolAddress((void**)&vt, g_vt);

    cudaFuncSetAttribute(gemm_t<2, 3, 3>, cudaFuncAttributeMaxDynamicSharedMemorySize, GEMM1_SMEM);
    cudaFuncSetAttribute(gemm_t<1, 2, 4>, cudaFuncAttributeMaxDynamicSharedMemorySize, GEMM2_SMEM);
    cudaFuncSetAttribute(attn_mma, cudaFuncAttributeMaxDynamicSharedMemorySize, ATTN_SMEM);

    // 1. split x -> a planes (hi/lo), round w_in -> b plane
    split2h_kernel<<<(ROWS * HID / 4 + 255) / 256, 256>>>(x, ah, al, ROWS * HID / 4);
    tohalf_kernel<<<(QKV_W * HID / 4 + 255) / 256, 256>>>(w_in, bhp, QKV_W * HID / 4);

    // 2. QKV = x @ w_in^T  (2-term split, 128x192 tiles, 1024 CTAs)
    gemm_t<2, 3, 3><<<(ROWS / 128) * (QKV_W / 192), 512, GEMM1_SMEM>>>(
        ah, al, bhp, qkv, ROWS, QKV_W, ROWS / 128);

    // 3. tables + norm/rope -> fp16 planes; V transpose (single fp16 plane)
    rope_table_kernel<<<(S_ * HALF + 255) / 256, 256>>>();
    normrope_kernel<<<ROWS, 256>>>(qkv, qnw, knw, qh, ql, kh, kl);
    vtrans_kernel<<<dim3(ROWS / 32, HID / 32), 256>>>(qkv, vt);

    // 4. attention (QK 3-term fp16, PV 1-term fp16) -> fp16 a planes
    attn_mma<<<dim3(S_ / 128, B_ * NH), 256, ATTN_SMEM>>>(qh, ql, kh, kl, vt, ah, al);

    // 5. round w_out -> b plane; out = O @ w_out^T  (64x128 tiles, 1024 CTAs)
    tohalf_kernel<<<(HID * HID / 4 + 255) / 256, 256>>>(w_out, bhp, HID * HID / 4);
    gemm_t<1, 2, 4><<<(ROWS / 64) * (HID / 128), 512, GEMM2_SMEM>>>(
        ah, al, bhp, out, ROWS, HID, ROWS / 64);
}

// round 12
// speedup vs baseline: 2.0340x; 1.4236x over previous
#include <cuda_runtime.h>
#include <cuda_bf16.h>
#include <cuda_fp16.h>
#include <cstdint>
#include <math.h>

// Problem constants
#define B_  2
#define S_  2048
#define HID 2048
#define NH  16
#define HD  128
#define HALF 64
#define ROWS (B_ * S_)            // 4096
#define QKV_W (3 * HID)           // 6144
#define EPS 1e-5f
#define SCALE 0.08838834764831845f   // 1/sqrt(128)

// Scratch (device-global; no runtime allocation allowed)
__device__ float g_qkv[(size_t)ROWS * QKV_W];            // gemm1 out (fp32)
__device__ float g_cos[S_ * HALF];
__device__ float g_sin[S_ * HALF];
__device__ __half g_a_hi[(size_t)ROWS * HID];            // gemm A plane (x; then O)
__device__ __half g_b_hi[(size_t)QKV_W * HID];           // gemm B plane (w_in; then w_out)
__device__ __half g_q_hi[(size_t)ROWS * HID];
__device__ __half g_q_lo[(size_t)ROWS * HID];
__device__ __half g_k_hi[(size_t)ROWS * HID];
__device__ __half g_k_lo[(size_t)ROWS * HID];
__device__ __half g_vt[(size_t)ROWS * HID];              // [b][h][d][s] single plane

__device__ __forceinline__ uint32_t smem_u32(const void* p) {
    uint32_t a;
    asm("{ .reg .u64 t; cvta.to.shared.u64 t, %1; cvt.u32.u64 %0, t; }" : "=r"(a) : "l"(p));
    return a;
}
#define SWZ(x) ((x) ^ (((x) >> 3) & 0x70))

__device__ __forceinline__ void ldsm_x4(uint32_t* r, uint32_t addr) {
    asm volatile("ldmatrix.sync.aligned.m8n8.x4.shared.b16 {%0,%1,%2,%3}, [%4];"
                 : "=r"(r[0]), "=r"(r[1]), "=r"(r[2]), "=r"(r[3]) : "r"(addr));
}
// fp16 in, f32 acc
__device__ __forceinline__ void mma_f16f32(float* c, const uint32_t* a,
                                           uint32_t b0, uint32_t b1) {
    asm volatile(
        "mma.sync.aligned.m16n8k16.row.col.f32.f16.f16.f32 "
        "{%0,%1,%2,%3}, {%4,%5,%6,%7}, {%8,%9}, {%0,%1,%2,%3};"
        : "+f"(c[0]), "+f"(c[1]), "+f"(c[2]), "+f"(c[3])
        : "r"(a[0]), "r"(a[1]), "r"(a[2]), "r"(a[3]), "r"(b0), "r"(b1));
}
__device__ __forceinline__ uint32_t pack_h2(float lo, float hi) {
    __half2 h = __floats2half2_rn(lo, hi);
    return *(uint32_t*)&h;
}

// ---------------------------------------------------------------------------
// RoPE table
// ---------------------------------------------------------------------------
__global__ void rope_table_kernel() {
    int idx = blockIdx.x * blockDim.x + threadIdx.x;
    if (idx >= S_ * HALF) return;
    int s = idx >> 6;
    int j = idx & 63;
    float freq = powf(10000.0f, -(float)j * (1.0f / 64.0f));
    float sn, cs;
    sincosf((float)s * freq, &sn, &cs);
    g_cos[idx] = cs;
    g_sin[idx] = sn;
}

// fp32 -> fp16 single-plane round
__global__ void __launch_bounds__(256) tohalf_kernel(
    const float* __restrict__ src, __half* __restrict__ dst, int n4)
{
    int i = blockIdx.x * blockDim.x + threadIdx.x;
    if (i >= n4) return;
    float4 v = ((const float4*)src)[i];
    uint64_t hp = 0;
    hp |= (uint64_t)__half_as_ushort(__float2half_rn(v.x));
    hp |= (uint64_t)__half_as_ushort(__float2half_rn(v.y)) << 16;
    hp |= (uint64_t)__half_as_ushort(__float2half_rn(v.z)) << 32;
    hp |= (uint64_t)__half_as_ushort(__float2half_rn(v.w)) << 48;
    *(uint64_t*)(dst + (size_t)i * 4) = hp;
}

// ---------------------------------------------------------------------------
// 1-term fp16 GEMM (f32 acc):  C = A*B^T
// Templated tile: BM = MT*64, BN = NP*64. 512 threads, 16 warps (4x4 grid),
// warp tile (MT*16) x (NP*16). BK=64, NSTG-stage cp.async pipeline.
// ---------------------------------------------------------------------------
template<int MT, int NP, int NSTG>
__global__ void __launch_bounds__(512, 1) gemm_t(
    const __half* __restrict__ A, const __half* __restrict__ B,
    float* __restrict__ C, int M, int N, int tiles_m)
{
    constexpr int BM = MT * 64;
    constexpr int BN = NP * 64;
    constexpr int A_PLANE = BM * 128;
    constexpr int B_PLANE = BN * 128;
    constexpr int SA = 0, SB = A_PLANE;
    constexpr int STG = A_PLANE + B_PLANE;
    constexpr int ACH = BM * 8;           // 16B chunks in A plane
    constexpr int BCH = BN * 8;
    constexpr int NLD = (ACH + BCH) / 512;
    static_assert((ACH + BCH) % 512 == 0, "loader divisibility");
    constexpr int NKT = HID / 64;

    extern __shared__ char smem[];
    const uint32_t sb = smem_u32(smem);
    const int tid = threadIdx.x;
    const int wid = tid >> 5, lid = tid & 31;
    const int m0 = (blockIdx.x % tiles_m) * BM;
    const int n0 = (blockIdx.x / tiles_m) * BN;
    const int wm = (wid & 3) * (MT * 16);
    const int wn = (wid >> 2) * (NP * 16);
    const int lrow = lid & 15;
    const int lhi = (lid >> 4) * 16;

    auto load_stage = [&](int st, int kt) {
        uint32_t sbase = sb + st * STG;
#pragma unroll
        for (int u = 0; u < NLD; u++) {
            int c = tid + u * 512;
            const __half* gp;
            uint32_t dst;
            if (c < ACH) {
                int r = c >> 3, c16 = c & 7;
                gp = A + (size_t)(m0 + r) * HID + kt * 64 + c16 * 8;
                dst = sbase + SA + SWZ(r * 128 + c16 * 16);
            } else {
                int cc = c - ACH;
                int r = cc >> 3, c16 = cc & 7;
                gp = B + (size_t)(n0 + r) * HID + kt * 64 + c16 * 8;
                dst = sbase + SB + SWZ(r * 128 + c16 * 16);
            }
            asm volatile("cp.async.cg.shared.global [%0], [%1], 16;"
                         :: "r"(dst), "l"(gp) : "memory");
        }
    };

#pragma unroll
    for (int s = 0; s < NSTG - 1; s++) {
        load_stage(s, s);
        asm volatile("cp.async.commit_group;" ::: "memory");
    }

    float acc[MT][NP * 2][4];
#pragma unroll
    for (int mt = 0; mt < MT; mt++)
#pragma unroll
        for (int nt = 0; nt < NP * 2; nt++)
#pragma unroll
            for (int q = 0; q < 4; q++) acc[mt][nt][q] = 0.0f;

    for (int kt = 0; kt < NKT; kt++) {
        if (kt + NSTG - 1 < NKT) load_stage((kt + NSTG - 1) % NSTG, kt + NSTG - 1);
        asm volatile("cp.async.commit_group;" ::: "memory");
        asm volatile("cp.async.wait_group %0;" :: "n"(NSTG - 1) : "memory");
        __syncthreads();

        const uint32_t sbase = sb + (kt % NSTG) * STG;

#pragma unroll
        for (int ks = 0; ks < 4; ks++) {
            const int cb = ks * 32 + lhi;
            uint32_t af[MT][4];
#pragma unroll
            for (int mt = 0; mt < MT; mt++) {
                int row = wm + mt * 16 + lrow;
                ldsm_x4(af[mt], sbase + SA + row * 128 + (cb ^ ((row & 7) * 16)));
            }
#pragma unroll
            for (int np = 0; np < NP; np++) {
                int brow = wn + np * 16 + lrow;
                uint32_t bh4[4];
                ldsm_x4(bh4, sbase + SB + brow * 128 + (cb ^ ((brow & 7) * 16)));
#pragma unroll
                for (int mt = 0; mt < MT; mt++) {
                    mma_f16f32(acc[mt][np * 2 + 0], af[mt], bh4[0], bh4[2]);
                    mma_f16f32(acc[mt][np * 2 + 1], af[mt], bh4[1], bh4[3]);
                }
            }
        }
        __syncthreads();
    }

    const int er = m0 + wm + (lid >> 2);
    const int ec = n0 + wn + (lid & 3) * 2;
#pragma unroll
    for (int mt = 0; mt < MT; mt++)
#pragma unroll
        for (int nt = 0; nt < NP * 2; nt++) {
            float* c0 = C + (size_t)(er + mt * 16) * N + ec + nt * 8;
            *(float2*)c0 = make_float2(acc[mt][nt][0], acc[mt][nt][1]);
            float* c1 = c0 + 8 * N;
            *(float2*)c1 = make_float2(acc[mt][nt][2], acc[mt][nt][3]);
        }
}

// gemm1: 128x192 tile, 4 stages (160KB). gemm2: 64x128 tile, 4 stages (96KB).
#define GEMM1_SMEM (4 * (128 * 128 + 192 * 128))   // 163840
#define GEMM2_SMEM (4 * (64 * 128 + 128 * 128))    // 98304

// ---------------------------------------------------------------------------
// Fused qk RMSNorm + RoPE -> fp16 hi/lo planes. Q scaled by 1/sqrt(HD).
// ---------------------------------------------------------------------------
__global__ void __launch_bounds__(256) normrope_kernel(
    const float* __restrict__ qkv,
    const float* __restrict__ nw_q, const float* __restrict__ nw_k,
    __half* __restrict__ qh, __half* __restrict__ ql,
    __half* __restrict__ kh, __half* __restrict__ kl)
{
    __shared__ float buf[HID];
    __shared__ float warpred[8];

    const int row = blockIdx.x;
    const int s = row & (S_ - 1);
    const int tid = threadIdx.x;

#pragma unroll
    for (int part = 0; part < 2; part++) {
        const float* src = qkv + (size_t)row * QKV_W + part * HID;
        const float* w = (part == 0) ? nw_q : nw_k;
        __half* dh = (part == 0) ? qh : kh;
        __half* dl = (part == 0) ? ql : kl;

        float ss = 0.0f;
#pragma unroll
        for (int u = 0; u < 8; u++) {
            int idx = tid + u * 256;
            float v = src[idx];
            buf[idx] = v;
            ss += v * v;
        }
#pragma unroll
        for (int o = 16; o; o >>= 1) ss += __shfl_xor_sync(0xffffffffu, ss, o);
        if ((tid & 31) == 0) warpred[tid >> 5] = ss;
        __syncthreads();
        float tot = 0.0f;
#pragma unroll
        for (int wi = 0; wi < 8; wi++) tot += warpred[wi];
        float rn = rsqrtf(tot * (1.0f / (float)HID) + EPS);
        if (part == 0) rn *= SCALE;

#pragma unroll
        for (int u = 0; u < 4; u++) {
            int p = tid + u * 256;
            int hh = p >> 6;
            int j = p & 63;
            int i1 = hh * HD + j;
            int i2 = i1 + HALF;
            float x1 = buf[i1] * rn * w[i1];
            float x2 = buf[i2] * rn * w[i2];
            float cs = g_cos[s * HALF + j];
            float sn = g_sin[s * HALF + j];
            float o1 = x1 * cs - x2 * sn;
            float o2 = x2 * cs + x1 * sn;
            __half h1 = __float2half_rn(o1);
            __half h2 = __float2half_rn(o2);
            size_t base = (size_t)row * HID;
            dh[base + i1] = h1;
            dh[base + i2] = h2;
            dl[base + i1] = __float2half_rn(o1 - __half2float(h1));
            dl[base + i2] = __float2half_rn(o2 - __half2float(h2));
        }
        __syncthreads();
    }
}

// ---------------------------------------------------------------------------
// V transpose: g_qkv v cols -> single fp16 plane vt [b][h][d][s]
// ---------------------------------------------------------------------------
__global__ void __launch_bounds__(256) vtrans_kernel(
    const float* __restrict__ qkv, __half* __restrict__ vt)
{
    __shared__ float t[32][33];
    const int row0 = blockIdx.x * 32;
    const int col0 = blockIdx.y * 32;
    const int tx = threadIdx.x & 31;
    const int ty = threadIdx.x >> 5;
#pragma unroll
    for (int i = 0; i < 4; i++) {
        int r = ty + i * 8;
        t[r][tx] = qkv[(size_t)(row0 + r) * QKV_W + 2 * HID + col0 + tx];
    }
    __syncthreads();
    const int b = row0 >> 11;
    const int s0 = row0 & 2047;
#pragma unroll
    for (int i = 0; i < 4; i++) {
        int c = ty + i * 8;
        float v = t[tx][c];
        size_t o = ((size_t)(b * 2048 + col0 + c)) * 2048 + s0 + tx;
        vt[o] = __float2half_rn(v);
    }
}

// ---------------------------------------------------------------------------
// Flash attention, fp16 mma.sync: QK 3-term (Qh,Ql x Kh,Kl), PV 1-term.
// 128 q rows x (b,h), 8 warps, 2-stage KV pipeline (48KB/stage).
// Output -> single fp16 O plane (gemm2 A operand).
// ---------------------------------------------------------------------------
#define SQH 0
#define SQL 32768
#define KVSTG 49152
#define SKH(s) (65536 + (s) * KVSTG)
#define SKL(s) (SKH(s) + 16384)
#define SVH(s) (SKH(s) + 32768)
#define ATTN_SMEM (65536 + 2 * KVSTG)   // 163840

__global__ void __launch_bounds__(256, 1) attn_mma(
    const __half* __restrict__ qh, const __half* __restrict__ ql,
    const __half* __restrict__ kh, const __half* __restrict__ kl,
    const __half* __restrict__ vt,
    __half* __restrict__ ohi)
{
    extern __shared__ char smem[];
    const uint32_t sb = smem_u32(smem);
    const int tid = threadIdx.x;
    const int wid = tid >> 5, lid = tid & 31;
    const int lrow = lid & 15;
    const int lhi = (lid >> 4) * 16;
    const int bh = blockIdx.y;
    const int b = bh >> 4, h = bh & 15;
    const int qt = gridDim.x - 1 - blockIdx.x;
    const int q0 = qt * 128;
    const int nkb = qt * 2 + 2;
    const int wm = wid * 16;

    // ---- load Q (hi+lo) into smem ----
#pragma unroll
    for (int u = 0; u < 16; u++) {
        int c = tid + u * 256;
        int plane = c >> 11;
        int cc = c & 2047;
        int r = cc >> 4, ch = cc & 15;
        int p = ch >> 3, c8 = ch & 7;
        const __half* src = (plane ? ql : qh) +
            ((size_t)(b * 2048 + q0 + r) * HID + h * HD + ch * 8);
        uint32_t dst = sb + (plane ? SQL : SQH) + p * 16384 + SWZ(r * 128 + c8 * 16);
        asm volatile("cp.async.cg.shared.global [%0], [%1], 16;"
                     :: "r"(dst), "l"(src) : "memory");
    }
    asm volatile("cp.async.commit_group;" ::: "memory");

// 3072 16B-chunks per stage: K hi (1024) + K lo (1024) + V (1024)
#define LOAD_KV(s, kt) do {                                                    \
    int k0 = (kt) * 64;                                                        \
    _Pragma("unroll")                                                          \
    for (int u = 0; u < 12; u++) {                                             \
        int c = tid + u * 256;                                                 \
        if (c < 2048) {                                                        \
            int plane = c >> 10;                                               \
            int cc = c & 1023;                                                 \
            int r = cc >> 4, ch = cc & 15;                                     \
            int p = ch >> 3, c8 = ch & 7;                                      \
            const __half* src = (plane ? kl : kh) +                            \
                ((size_t)(b * 2048 + k0 + r) * HID + h * HD + ch * 8);         \
            uint32_t dst = sb + (plane ? SKL(s) : SKH(s)) + p * 8192 +         \
                           SWZ(r * 128 + c8 * 16);                             \
            asm volatile("cp.async.cg.shared.global [%0], [%1], 16;"           \
                         :: "r"(dst), "l"(src) : "memory");                    \
        } else {                                                               \
            int cc = c - 2048;                                                 \
            int d = cc >> 3, c8 = cc & 7;                                      \
            const __half* src = vt +                                           \
                ((size_t)(b * 2048 + h * HD + d) * 2048 + k0 + c8 * 8);        \
            uint32_t dst = sb + SVH(s) + SWZ(d * 128 + c8 * 16);               \
            asm volatile("cp.async.cg.shared.global [%0], [%1], 16;"           \
                         :: "r"(dst), "l"(src) : "memory");                    \
        }                                                                      \
    }                                                                          \
} while (0)

    LOAD_KV(0, 0);
    asm volatile("cp.async.commit_group;" ::: "memory");

    // ---- hoist Q fragments into registers (Q smem never rewritten) ----
    asm volatile("cp.async.wait_group 1;" ::: "memory");
    __syncthreads();
    uint32_t qhr[8][4], qlr[8][4];
#pragma unroll
    for (int kk = 0; kk < 8; kk++) {
        int p = kk >> 2;
        int cb = (kk & 3) * 32 + lhi;
        int arow = wm + lrow;
        uint32_t aoff = p * 16384 + arow * 128 + (cb ^ ((arow & 7) * 16));
        ldsm_x4(qhr[kk], sb + SQH + aoff);
        ldsm_x4(qlr[kk], sb + SQL + aoff);
    }

    float accO[16][4];
#pragma unroll
    for (int nt = 0; nt < 16; nt++)
#pragma unroll
        for (int q = 0; q < 4; q++) accO[nt][q] = 0.0f;
    float m0v = -1e30f, m1v = -1e30f, l0v = 0.0f, l1v = 0.0f;

    const int grow0 = q0 + wm + (lid >> 2);
    const int grow1 = grow0 + 8;

    for (int kt = 0; kt < nkb; kt++) {
        __syncthreads();
        if (kt + 1 < nkb) LOAD_KV((kt + 1) & 1, kt + 1);
        asm volatile("cp.async.commit_group;" ::: "memory");
        asm volatile("cp.async.wait_group 1;" ::: "memory");
        __syncthreads();

        // fully-masked ktile for this warp?
        if (kt * 64 > q0 + wm + 15) continue;

        const int s = kt & 1;

        // ---- S = Qh*Kh + Ql*Kh + Qh*Kl  (fp16, Q frags from regs) ----
        float sa[8][4];
#pragma unroll
        for (int nt = 0; nt < 8; nt++)
#pragma unroll
            for (int q = 0; q < 4; q++) sa[nt][q] = 0.0f;

#pragma unroll
        for (int kk = 0; kk < 8; kk++) {
            int p = kk >> 2;
            int cb = (kk & 3) * 32 + lhi;
#pragma unroll
            for (int np = 0; np < 4; np++) {
                int brow = np * 16 + lrow;
                uint32_t boff = p * 8192 + brow * 128 + (cb ^ ((brow & 7) * 16));
                uint32_t khf[4];
                ldsm_x4(khf, sb + SKH(s) + boff);
                mma_f16f32(sa[np * 2 + 0], qhr[kk], khf[0], khf[2]);
                mma_f16f32(sa[np * 2 + 1], qhr[kk], khf[1], khf[3]);
                mma_f16f32(sa[np * 2 + 0], qlr[kk], khf[0], khf[2]);
                mma_f16f32(sa[np * 2 + 1], qlr[kk], khf[1], khf[3]);
                uint32_t klf[4];
                ldsm_x4(klf, sb + SKL(s) + boff);
                mma_f16f32(sa[np * 2 + 0], qhr[kk], klf[0], klf[2]);
                mma_f16f32(sa[np * 2 + 1], qhr[kk], klf[1], klf[3]);
            }
        }

        // ---- causal mask ----
        if ((kt + 1) * 64 - 1 > q0 + wm) {
            const int colb = kt * 64 + (lid & 3) * 2;
#pragma unroll
            for (int nt = 0; nt < 8; nt++) {
                int col = colb + nt * 8;
                if (col > grow0)     sa[nt][0] = -1e30f;
                if (col + 1 > grow0) sa[nt][1] = -1e30f;
                if (col > grow1)     sa[nt][2] = -1e30f;
                if (col + 1 > grow1) sa[nt][3] = -1e30f;
            }
        }

        // ---- online softmax ----
        float mx0 = m0v, mx1 = m1v;
#pragma unroll
        for (int nt = 0; nt < 8; nt++) {
            mx0 = fmaxf(mx0, fmaxf(sa[nt][0], sa[nt][1]));
            mx1 = fmaxf(mx1, fmaxf(sa[nt][2], sa[nt][3]));
        }
        mx0 = fmaxf(mx0, __shfl_xor_sync(0xffffffffu, mx0, 1));
        mx0 = fmaxf(mx0, __shfl_xor_sync(0xffffffffu, mx0, 2));
        mx1 = fmaxf(mx1, __shfl_xor_sync(0xffffffffu, mx1, 1));
        mx1 = fmaxf(mx1, __shfl_xor_sync(0xffffffffu, mx1, 2));
        float alpha0 = __expf(m0v - mx0);
        float alpha1 = __expf(m1v - mx1);
        m0v = mx0; m1v = mx1;

        float ls0 = 0.0f, ls1 = 0.0f;
#pragma unroll
        for (int nt = 0; nt < 8; nt++) {
            sa[nt][0] = __expf(sa[nt][0] - mx0);
            sa[nt][1] = __expf(sa[nt][1] - mx0);
            sa[nt][2] = __expf(sa[nt][2] - mx1);
            sa[nt][3] = __expf(sa[nt][3] - mx1);
            ls0 += sa[nt][0] + sa[nt][1];
            ls1 += sa[nt][2] + sa[nt][3];
        }
        ls0 += __shfl_xor_sync(0xffffffffu, ls0, 1);
        ls0 += __shfl_xor_sync(0xffffffffu, ls0, 2);
        ls1 += __shfl_xor_sync(0xffffffffu, ls1, 1);
        ls1 += __shfl_xor_sync(0xffffffffu, ls1, 2);
        l0v = l0v * alpha0 + ls0;
        l1v = l1v * alpha1 + ls1;

#pragma unroll
        for (int nt = 0; nt < 16; nt++) {
            accO[nt][0] *= alpha0; accO[nt][1] *= alpha0;
            accO[nt][2] *= alpha1; accO[nt][3] *= alpha1;
        }

        // ---- P -> fp16 A-fragments (single plane) ----
        uint32_t phA[8], phB[8];
#pragma unroll
        for (int nt = 0; nt < 8; nt++) {
            phA[nt] = pack_h2(sa[nt][0], sa[nt][1]);
            phB[nt] = pack_h2(sa[nt][2], sa[nt][3]);
        }

        // ---- O += P*V  (1-term fp16) ----
#pragma unroll
        for (int ki = 0; ki < 4; ki++) {
            uint32_t aH[4] = {phA[2 * ki], phB[2 * ki], phA[2 * ki + 1], phB[2 * ki + 1]};
            int cb = ki * 32 + lhi;
#pragma unroll
            for (int np = 0; np < 8; np++) {
                int brow = np * 16 + lrow;
                uint32_t boff = brow * 128 + (cb ^ ((brow & 7) * 16));
                uint32_t vhf[4];
                ldsm_x4(vhf, sb + SVH(s) + boff);
                mma_f16f32(accO[np * 2 + 0], aH, vhf[0], vhf[2]);
                mma_f16f32(accO[np * 2 + 1], aH, vhf[1], vhf[3]);
            }
        }
    }

    // ---- epilogue: O/l -> single fp16 plane ----
    float inv0 = 1.0f / l0v, inv1 = 1.0f / l1v;
#pragma unroll
    for (int nt = 0; nt < 16; nt++) {
        int col = h * HD + nt * 8 + (lid & 3) * 2;
        size_t r0 = (size_t)(b * 2048 + grow0) * HID + col;
        size_t r1 = (size_t)(b * 2048 + grow1) * HID + col;
        *(uint32_t*)(ohi + r0) = pack_h2(accO[nt][0] * inv0, accO[nt][1] * inv0);
        *(uint32_t*)(ohi + r1) = pack_h2(accO[nt][2] * inv1, accO[nt][3] * inv1);
    }
#undef LOAD_KV
}

// ---------------------------------------------------------------------------
// launch
// ---------------------------------------------------------------------------
extern "C" void kernel_launch(void* const* d_in, const int* in_sizes, int n_in,
                              void* d_out, int out_size)
{
    const float* x     = (const float*)d_in[0];
    const float* w_in  = (const float*)d_in[1];
    const float* w_out = (const float*)d_in[2];
    const float* qnw   = (const float*)d_in[3];
    const float* knw   = (const float*)d_in[4];
    float* out = (float*)d_out;

    float* qkv;  cudaGetSymbolAddress((void**)&qkv,  g_qkv);
    __half *ah, *bhp, *qh, *ql, *kh, *kl, *vt;
    cudaGetSymbolAddress((void**)&ah, g_a_hi);
    cudaGetSymbolAddress((void**)&bhp, g_b_hi);
    cudaGetSymbolAddress((void**)&qh, g_q_hi);
    cudaGetSymbolAddress((void**)&ql, g_q_lo);
    cudaGetSymbolAddress((void**)&kh, g_k_hi);
    cudaGetSymbolAddress((void**)&kl, g_k_lo);
    cudaGetSymbolAddress((void**)&vt, g_vt);

    cudaFuncSetAttribute(gemm_t<2, 3, 4>, cudaFuncAttributeMaxDynamicSharedMemorySize, GEMM1_SMEM);
    cudaFuncSetAttribute(gemm_t<1, 2, 4>, cudaFuncAttributeMaxDynamicSharedMemorySize, GEMM2_SMEM);
    cudaFuncSetAttribute(attn_mma, cudaFuncAttributeMaxDynamicSharedMemorySize, ATTN_SMEM);

    // 1. round x -> a plane, w_in -> b plane (fp16)
    tohalf_kernel<<<(ROWS * HID / 4 + 255) / 256, 256>>>(x, ah, ROWS * HID / 4);
    tohalf_kernel<<<(QKV_W * HID / 4 + 255) / 256, 256>>>(w_in, bhp, QKV_W * HID / 4);

    // 2. QKV = x @ w_in^T  (1-term fp16, 128x192 tiles, 1024 CTAs)
    gemm_t<2, 3, 4><<<(ROWS / 128) * (QKV_W / 192), 512, GEMM1_SMEM>>>(
        ah, bhp, qkv, ROWS, QKV_W, ROWS / 128);

    // 3. tables + norm/rope -> fp16 planes; V transpose (single fp16 plane)
    rope_table_kernel<<<(S_ * HALF + 255) / 256, 256>>>();
    normrope_kernel<<<ROWS, 256>>>(qkv, qnw, knw, qh, ql, kh, kl);
    vtrans_kernel<<<dim3(ROWS / 32, HID / 32), 256>>>(qkv, vt);

    // 4. attention (QK 3-term fp16, PV 1-term fp16) -> fp16 O plane
    attn_mma<<<dim3(S_ / 128, B_ * NH), 256, ATTN_SMEM>>>(qh, ql, kh, kl, vt, ah);

    // 5. round w_out -> b plane; out = O @ w_out^T  (1-term, 64x128 tiles)
    tohalf_kernel<<<(HID * HID / 4 + 255) / 256, 256>>>(w_out, bhp, HID * HID / 4);
    gemm_t<1, 2, 4><<<(ROWS / 64) * (HID / 128), 512, GEMM2_SMEM>>>(
        ah, bhp, out, ROWS, HID, ROWS / 64);
}

// round 13
// speedup vs baseline: 2.2426x; 1.1025x over previous
#include <cuda_runtime.h>
#include <cuda_bf16.h>
#include <cuda_fp16.h>
#include <cstdint>
#include <math.h>

// Problem constants
#define B_  2
#define S_  2048
#define HID 2048
#define NH  16
#define HD  128
#define HALF 64
#define ROWS (B_ * S_)            // 4096
#define QKV_W (3 * HID)           // 6144
#define EPS 1e-5f
#define SCALE 0.08838834764831845f   // 1/sqrt(128)

// Scratch (device-global; no runtime allocation allowed)
__device__ float g_qkv[(size_t)ROWS * QKV_W];            // gemm1 out (fp32)
__device__ float g_cos[S_ * HALF];
__device__ float g_sin[S_ * HALF];
__device__ __half g_a_hi[(size_t)ROWS * HID];            // gemm A plane (x; then O)
__device__ __half g_b_hi[(size_t)QKV_W * HID];           // gemm B plane (w_in; then w_out)
__device__ __half g_q_hi[(size_t)ROWS * HID];
__device__ __half g_q_lo[(size_t)ROWS * HID];
__device__ __half g_k_hi[(size_t)ROWS * HID];
__device__ __half g_vt[(size_t)ROWS * HID];              // [b][h][d][s] single plane

__device__ __forceinline__ uint32_t smem_u32(const void* p) {
    uint32_t a;
    asm("{ .reg .u64 t; cvta.to.shared.u64 t, %1; cvt.u32.u64 %0, t; }" : "=r"(a) : "l"(p));
    return a;
}
#define SWZ(x) ((x) ^ (((x) >> 3) & 0x70))

__device__ __forceinline__ void ldsm_x4(uint32_t* r, uint32_t addr) {
    asm volatile("ldmatrix.sync.aligned.m8n8.x4.shared.b16 {%0,%1,%2,%3}, [%4];"
                 : "=r"(r[0]), "=r"(r[1]), "=r"(r[2]), "=r"(r[3]) : "r"(addr));
}
// fp16 in, f32 acc
__device__ __forceinline__ void mma_f16f32(float* c, const uint32_t* a,
                                           uint32_t b0, uint32_t b1) {
    asm volatile(
        "mma.sync.aligned.m16n8k16.row.col.f32.f16.f16.f32 "
        "{%0,%1,%2,%3}, {%4,%5,%6,%7}, {%8,%9}, {%0,%1,%2,%3};"
        : "+f"(c[0]), "+f"(c[1]), "+f"(c[2]), "+f"(c[3])
        : "r"(a[0]), "r"(a[1]), "r"(a[2]), "r"(a[3]), "r"(b0), "r"(b1));
}
__device__ __forceinline__ uint32_t pack_h2(float lo, float hi) {
    __half2 h = __floats2half2_rn(lo, hi);
    return *(uint32_t*)&h;
}

// ---------------------------------------------------------------------------
// RoPE table
// ---------------------------------------------------------------------------
__global__ void rope_table_kernel() {
    int idx = blockIdx.x * blockDim.x + threadIdx.x;
    if (idx >= S_ * HALF) return;
    int s = idx >> 6;
    int j = idx & 63;
    float freq = powf(10000.0f, -(float)j * (1.0f / 64.0f));
    float sn, cs;
    sincosf((float)s * freq, &sn, &cs);
    g_cos[idx] = cs;
    g_sin[idx] = sn;
}

// fp32 -> fp16 single-plane round
__global__ void __launch_bounds__(256) tohalf_kernel(
    const float* __restrict__ src, __half* __restrict__ dst, int n4)
{
    int i = blockIdx.x * blockDim.x + threadIdx.x;
    if (i >= n4) return;
    float4 v = ((const float4*)src)[i];
    uint64_t hp = 0;
    hp |= (uint64_t)__half_as_ushort(__float2half_rn(v.x));
    hp |= (uint64_t)__half_as_ushort(__float2half_rn(v.y)) << 16;
    hp |= (uint64_t)__half_as_ushort(__float2half_rn(v.z)) << 32;
    hp |= (uint64_t)__half_as_ushort(__float2half_rn(v.w)) << 48;
    *(uint64_t*)(dst + (size_t)i * 4) = hp;
}

// ---------------------------------------------------------------------------
// 1-term fp16 GEMM (f32 acc):  C = A*B^T   (unchanged from R12)
// ---------------------------------------------------------------------------
template<int MT, int NP, int NSTG>
__global__ void __launch_bounds__(512, 1) gemm_t(
    const __half* __restrict__ A, const __half* __restrict__ B,
    float* __restrict__ C, int M, int N, int tiles_m)
{
    constexpr int BM = MT * 64;
    constexpr int BN = NP * 64;
    constexpr int A_PLANE = BM * 128;
    constexpr int B_PLANE = BN * 128;
    constexpr int SA = 0, SB = A_PLANE;
    constexpr int STG = A_PLANE + B_PLANE;
    constexpr int ACH = BM * 8;
    constexpr int BCH = BN * 8;
    constexpr int NLD = (ACH + BCH) / 512;
    static_assert((ACH + BCH) % 512 == 0, "loader divisibility");
    constexpr int NKT = HID / 64;

    extern __shared__ char smem[];
    const uint32_t sb = smem_u32(smem);
    const int tid = threadIdx.x;
    const int wid = tid >> 5, lid = tid & 31;
    const int m0 = (blockIdx.x % tiles_m) * BM;
    const int n0 = (blockIdx.x / tiles_m) * BN;
    const int wm = (wid & 3) * (MT * 16);
    const int wn = (wid >> 2) * (NP * 16);
    const int lrow = lid & 15;
    const int lhi = (lid >> 4) * 16;

    auto load_stage = [&](int st, int kt) {
        uint32_t sbase = sb + st * STG;
#pragma unroll
        for (int u = 0; u < NLD; u++) {
            int c = tid + u * 512;
            const __half* gp;
            uint32_t dst;
            if (c < ACH) {
                int r = c >> 3, c16 = c & 7;
                gp = A + (size_t)(m0 + r) * HID + kt * 64 + c16 * 8;
                dst = sbase + SA + SWZ(r * 128 + c16 * 16);
            } else {
                int cc = c - ACH;
                int r = cc >> 3, c16 = cc & 7;
                gp = B + (size_t)(n0 + r) * HID + kt * 64 + c16 * 8;
                dst = sbase + SB + SWZ(r * 128 + c16 * 16);
            }
            asm volatile("cp.async.cg.shared.global [%0], [%1], 16;"
                         :: "r"(dst), "l"(gp) : "memory");
        }
    };

#pragma unroll
    for (int s = 0; s < NSTG - 1; s++) {
        load_stage(s, s);
        asm volatile("cp.async.commit_group;" ::: "memory");
    }

    float acc[MT][NP * 2][4];
#pragma unroll
    for (int mt = 0; mt < MT; mt++)
#pragma unroll
        for (int nt = 0; nt < NP * 2; nt++)
#pragma unroll
            for (int q = 0; q < 4; q++) acc[mt][nt][q] = 0.0f;

    for (int kt = 0; kt < NKT; kt++) {
        if (kt + NSTG - 1 < NKT) load_stage((kt + NSTG - 1) % NSTG, kt + NSTG - 1);
        asm volatile("cp.async.commit_group;" ::: "memory");
        asm volatile("cp.async.wait_group %0;" :: "n"(NSTG - 1) : "memory");
        __syncthreads();

        const uint32_t sbase = sb + (kt % NSTG) * STG;

#pragma unroll
        for (int ks = 0; ks < 4; ks++) {
            const int cb = ks * 32 + lhi;
            uint32_t af[MT][4];
#pragma unroll
            for (int mt = 0; mt < MT; mt++) {
                int row = wm + mt * 16 + lrow;
                ldsm_x4(af[mt], sbase + SA + row * 128 + (cb ^ ((row & 7) * 16)));
            }
#pragma unroll
            for (int np = 0; np < NP; np++) {
                int brow = wn + np * 16 + lrow;
                uint32_t bh4[4];
                ldsm_x4(bh4, sbase + SB + brow * 128 + (cb ^ ((brow & 7) * 16)));
#pragma unroll
                for (int mt = 0; mt < MT; mt++) {
                    mma_f16f32(acc[mt][np * 2 + 0], af[mt], bh4[0], bh4[2]);
                    mma_f16f32(acc[mt][np * 2 + 1], af[mt], bh4[1], bh4[3]);
                }
            }
        }
        __syncthreads();
    }

    const int er = m0 + wm + (lid >> 2);
    const int ec = n0 + wn + (lid & 3) * 2;
#pragma unroll
    for (int mt = 0; mt < MT; mt++)
#pragma unroll
        for (int nt = 0; nt < NP * 2; nt++) {
            float* c0 = C + (size_t)(er + mt * 16) * N + ec + nt * 8;
            *(float2*)c0 = make_float2(acc[mt][nt][0], acc[mt][nt][1]);
            float* c1 = c0 + 8 * N;
            *(float2*)c1 = make_float2(acc[mt][nt][2], acc[mt][nt][3]);
        }
}

#define GEMM1_SMEM (4 * (128 * 128 + 192 * 128))   // 163840
#define GEMM2_SMEM (4 * (64 * 128 + 128 * 128))    // 98304

// ---------------------------------------------------------------------------
// Fused qk RMSNorm + RoPE: Q -> fp16 hi/lo planes, K -> fp16 hi plane only.
// Q scaled by 1/sqrt(HD).
// ---------------------------------------------------------------------------
__global__ void __launch_bounds__(256) normrope_kernel(
    const float* __restrict__ qkv,
    const float* __restrict__ nw_q, const float* __restrict__ nw_k,
    __half* __restrict__ qh, __half* __restrict__ ql,
    __half* __restrict__ kh)
{
    __shared__ float buf[HID];
    __shared__ float warpred[8];

    const int row = blockIdx.x;
    const int s = row & (S_ - 1);
    const int tid = threadIdx.x;

#pragma unroll
    for (int part = 0; part < 2; part++) {
        const float* src = qkv + (size_t)row * QKV_W + part * HID;
        const float* w = (part == 0) ? nw_q : nw_k;

        float ss = 0.0f;
#pragma unroll
        for (int u = 0; u < 8; u++) {
            int idx = tid + u * 256;
            float v = src[idx];
            buf[idx] = v;
            ss += v * v;
        }
#pragma unroll
        for (int o = 16; o; o >>= 1) ss += __shfl_xor_sync(0xffffffffu, ss, o);
        if ((tid & 31) == 0) warpred[tid >> 5] = ss;
        __syncthreads();
        float tot = 0.0f;
#pragma unroll
        for (int wi = 0; wi < 8; wi++) tot += warpred[wi];
        float rn = rsqrtf(tot * (1.0f / (float)HID) + EPS);
        if (part == 0) rn *= SCALE;

#pragma unroll
        for (int u = 0; u < 4; u++) {
            int p = tid + u * 256;
            int hh = p >> 6;
            int j = p & 63;
            int i1 = hh * HD + j;
            int i2 = i1 + HALF;
            float x1 = buf[i1] * rn * w[i1];
            float x2 = buf[i2] * rn * w[i2];
            float cs = g_cos[s * HALF + j];
            float sn = g_sin[s * HALF + j];
            float o1 = x1 * cs - x2 * sn;
            float o2 = x2 * cs + x1 * sn;
            size_t base = (size_t)row * HID;
            if (part == 0) {
                __half h1 = __float2half_rn(o1);
                __half h2 = __float2half_rn(o2);
                qh[base + i1] = h1;
                qh[base + i2] = h2;
                ql[base + i1] = __float2half_rn(o1 - __half2float(h1));
                ql[base + i2] = __float2half_rn(o2 - __half2float(h2));
            } else {
                kh[base + i1] = __float2half_rn(o1);
                kh[base + i2] = __float2half_rn(o2);
            }
        }
        __syncthreads();
    }
}

// ---------------------------------------------------------------------------
// V transpose: g_qkv v cols -> single fp16 plane vt [b][h][d][s]
// ---------------------------------------------------------------------------
__global__ void __launch_bounds__(256) vtrans_kernel(
    const float* __restrict__ qkv, __half* __restrict__ vt)
{
    __shared__ float t[32][33];
    const int row0 = blockIdx.x * 32;
    const int col0 = blockIdx.y * 32;
    const int tx = threadIdx.x & 31;
    const int ty = threadIdx.x >> 5;
#pragma unroll
    for (int i = 0; i < 4; i++) {
        int r = ty + i * 8;
        t[r][tx] = qkv[(size_t)(row0 + r) * QKV_W + 2 * HID + col0 + tx];
    }
    __syncthreads();
    const int b = row0 >> 11;
    const int s0 = row0 & 2047;
#pragma unroll
    for (int i = 0; i < 4; i++) {
        int c = ty + i * 8;
        float v = t[tx][c];
        size_t o = ((size_t)(b * 2048 + col0 + c)) * 2048 + s0 + tx;
        vt[o] = __float2half_rn(v);
    }
}

// ---------------------------------------------------------------------------
// Flash attention, fp16 mma.sync: QK 2-term (Qh+Ql vs Kh), PV 1-term.
// 64 q rows x (b,h), 128 threads / 4 warps (16 rows each), 2-stage KV.
// smem 96KB -> 2 CTAs/SM (cross-CTA latency hiding).
// Output -> single fp16 O plane (gemm2 A operand).
// ---------------------------------------------------------------------------
#define SQH 0
#define SQL 16384
#define KVSTG 32768
#define SK(s) (32768 + (s) * KVSTG)
#define SV(s) (SK(s) + 16384)
#define ATTN_SMEM (32768 + 2 * KVSTG)   // 98304

__global__ void __launch_bounds__(128) attn_mma(
    const __half* __restrict__ qh, const __half* __restrict__ ql,
    const __half* __restrict__ kh, const __half* __restrict__ vt,
    __half* __restrict__ ohi)
{
    extern __shared__ char smem[];
    const uint32_t sb = smem_u32(smem);
    const int tid = threadIdx.x;
    const int wid = tid >> 5, lid = tid & 31;
    const int lrow = lid & 15;
    const int lhi = (lid >> 4) * 16;
    const int bh = blockIdx.y;
    const int b = bh >> 4, h = bh & 15;
    const int qt = gridDim.x - 1 - blockIdx.x;   // heavy tiles first
    const int q0 = qt * 64;
    const int nkb = qt + 1;
    const int wm = wid * 16;

    // ---- load Q (hi+lo, 64 rows) into smem: 2048 16B-chunks ----
#pragma unroll
    for (int u = 0; u < 16; u++) {
        int c = tid + u * 128;
        int plane = c >> 10;
        int cc = c & 1023;
        int r = cc >> 4, ch = cc & 15;
        int p = ch >> 3, c8 = ch & 7;
        const __half* src = (plane ? ql : qh) +
            ((size_t)(b * 2048 + q0 + r) * HID + h * HD + ch * 8);
        uint32_t dst = sb + (plane ? SQL : SQH) + p * 8192 + SWZ(r * 128 + c8 * 16);
        asm volatile("cp.async.cg.shared.global [%0], [%1], 16;"
                     :: "r"(dst), "l"(src) : "memory");
    }
    asm volatile("cp.async.commit_group;" ::: "memory");

// 2048 16B-chunks per stage: K (1024) + V (1024)
#define LOAD_KV(s, kt) do {                                                    \
    int k0 = (kt) * 64;                                                        \
    _Pragma("unroll")                                                          \
    for (int u = 0; u < 16; u++) {                                             \
        int c = tid + u * 128;                                                 \
        if (c < 1024) {                                                        \
            int r = c >> 4, ch = c & 15;                                       \
            int p = ch >> 3, c8 = ch & 7;                                      \
            const __half* src = kh +                                           \
                ((size_t)(b * 2048 + k0 + r) * HID + h * HD + ch * 8);         \
            uint32_t dst = sb + SK(s) + p * 8192 + SWZ(r * 128 + c8 * 16);     \
            asm volatile("cp.async.cg.shared.global [%0], [%1], 16;"           \
                         :: "r"(dst), "l"(src) : "memory");                    \
        } else {                                                               \
            int cc = c - 1024;                                                 \
            int d = cc >> 3, c8 = cc & 7;                                      \
            const __half* src = vt +                                           \
                ((size_t)(b * 2048 + h * HD + d) * 2048 + k0 + c8 * 8);        \
            uint32_t dst = sb + SV(s) + SWZ(d * 128 + c8 * 16);                \
            asm volatile("cp.async.cg.shared.global [%0], [%1], 16;"           \
                         :: "r"(dst), "l"(src) : "memory");                    \
        }                                                                      \
    }                                                                          \
} while (0)

    LOAD_KV(0, 0);
    asm volatile("cp.async.commit_group;" ::: "memory");

    // ---- hoist Q fragments into registers (Q smem never rewritten) ----
    asm volatile("cp.async.wait_group 1;" ::: "memory");
    __syncthreads();
    uint32_t qhr[8][4], qlr[8][4];
#pragma unroll
    for (int kk = 0; kk < 8; kk++) {
        int p = kk >> 2;
        int cb = (kk & 3) * 32 + lhi;
        int arow = wm + lrow;
        uint32_t aoff = p * 8192 + arow * 128 + (cb ^ ((arow & 7) * 16));
        ldsm_x4(qhr[kk], sb + SQH + aoff);
        ldsm_x4(qlr[kk], sb + SQL + aoff);
    }

    float accO[16][4];
#pragma unroll
    for (int nt = 0; nt < 16; nt++)
#pragma unroll
        for (int q = 0; q < 4; q++) accO[nt][q] = 0.0f;
    float m0v = -1e30f, m1v = -1e30f, l0v = 0.0f, l1v = 0.0f;

    const int grow0 = q0 + wm + (lid >> 2);
    const int grow1 = grow0 + 8;

    for (int kt = 0; kt < nkb; kt++) {
        __syncthreads();
        if (kt + 1 < nkb) LOAD_KV((kt + 1) & 1, kt + 1);
        asm volatile("cp.async.commit_group;" ::: "memory");
        asm volatile("cp.async.wait_group 1;" ::: "memory");
        __syncthreads();

        // fully-masked ktile for this warp?
        if (kt * 64 > q0 + wm + 15) continue;

        const int s = kt & 1;

        // ---- S = Qh*Kh + Ql*Kh  (fp16, Q frags from regs) ----
        float sa[8][4];
#pragma unroll
        for (int nt = 0; nt < 8; nt++)
#pragma unroll
            for (int q = 0; q < 4; q++) sa[nt][q] = 0.0f;

#pragma unroll
        for (int kk = 0; kk < 8; kk++) {
            int p = kk >> 2;
            int cb = (kk & 3) * 32 + lhi;
#pragma unroll
            for (int np = 0; np < 4; np++) {
                int brow = np * 16 + lrow;
                uint32_t boff = p * 8192 + brow * 128 + (cb ^ ((brow & 7) * 16));
                uint32_t khf[4];
                ldsm_x4(khf, sb + SK(s) + boff);
                mma_f16f32(sa[np * 2 + 0], qhr[kk], khf[0], khf[2]);
                mma_f16f32(sa[np * 2 + 1], qhr[kk], khf[1], khf[3]);
                mma_f16f32(sa[np * 2 + 0], qlr[kk], khf[0], khf[2]);
                mma_f16f32(sa[np * 2 + 1], qlr[kk], khf[1], khf[3]);
            }
        }

        // ---- causal mask ----
        if ((kt + 1) * 64 - 1 > q0 + wm) {
            const int colb = kt * 64 + (lid & 3) * 2;
#pragma unroll
            for (int nt = 0; nt < 8; nt++) {
                int col = colb + nt * 8;
                if (col > grow0)     sa[nt][0] = -1e30f;
                if (col + 1 > grow0) sa[nt][1] = -1e30f;
                if (col > grow1)     sa[nt][2] = -1e30f;
                if (col + 1 > grow1) sa[nt][3] = -1e30f;
            }
        }

        // ---- online softmax ----
        float mx0 = m0v, mx1 = m1v;
#pragma unroll
        for (int nt = 0; nt < 8; nt++) {
            mx0 = fmaxf(mx0, fmaxf(sa[nt][0], sa[nt][1]));
            mx1 = fmaxf(mx1, fmaxf(sa[nt][2], sa[nt][3]));
        }
        mx0 = fmaxf(mx0, __shfl_xor_sync(0xffffffffu, mx0, 1));
        mx0 = fmaxf(mx0, __shfl_xor_sync(0xffffffffu, mx0, 2));
        mx1 = fmaxf(mx1, __shfl_xor_sync(0xffffffffu, mx1, 1));
        mx1 = fmaxf(mx1, __shfl_xor_sync(0xffffffffu, mx1, 2));
        float alpha0 = __expf(m0v - mx0);
        float alpha1 = __expf(m1v - mx1);
        m0v = mx0; m1v = mx1;

        float ls0 = 0.0f, ls1 = 0.0f;
#pragma unroll
        for (int nt = 0; nt < 8; nt++) {
            sa[nt][0] = __expf(sa[nt][0] - mx0);
            sa[nt][1] = __expf(sa[nt][1] - mx0);
            sa[nt][2] = __expf(sa[nt][2] - mx1);
            sa[nt][3] = __expf(sa[nt][3] - mx1);
            ls0 += sa[nt][0] + sa[nt][1];
            ls1 += sa[nt][2] + sa[nt][3];
        }
        ls0 += __shfl_xor_sync(0xffffffffu, ls0, 1);
        ls0 += __shfl_xor_sync(0xffffffffu, ls0, 2);
        ls1 += __shfl_xor_sync(0xffffffffu, ls1, 1);
        ls1 += __shfl_xor_sync(0xffffffffu, ls1, 2);
        l0v = l0v * alpha0 + ls0;
        l1v = l1v * alpha1 + ls1;

#pragma unroll
        for (int nt = 0; nt < 16; nt++) {
            accO[nt][0] *= alpha0; accO[nt][1] *= alpha0;
            accO[nt][2] *= alpha1; accO[nt][3] *= alpha1;
        }

        // ---- P -> fp16 A-fragments ----
        uint32_t phA[8], phB[8];
#pragma unroll
        for (int nt = 0; nt < 8; nt++) {
            phA[nt] = pack_h2(sa[nt][0], sa[nt][1]);
            phB[nt] = pack_h2(sa[nt][2], sa[nt][3]);
        }

        // ---- O += P*V  (1-term fp16) ----
#pragma unroll
        for (int ki = 0; ki < 4; ki++) {
            uint32_t aH[4] = {phA[2 * ki], phB[2 * ki], phA[2 * ki + 1], phB[2 * ki + 1]};
            int cb = ki * 32 + lhi;
#pragma unroll
            for (int np = 0; np < 8; np++) {
                int brow = np * 16 + lrow;
                uint32_t boff = brow * 128 + (cb ^ ((brow & 7) * 16));
                uint32_t vhf[4];
                ldsm_x4(vhf, sb + SV(s) + boff);
                mma_f16f32(accO[np * 2 + 0], aH, vhf[0], vhf[2]);
                mma_f16f32(accO[np * 2 + 1], aH, vhf[1], vhf[3]);
            }
        }
    }

    // ---- epilogue: O/l -> single fp16 plane ----
    float inv0 = 1.0f / l0v, inv1 = 1.0f / l1v;
#pragma unroll
    for (int nt = 0; nt < 16; nt++) {
        int col = h * HD + nt * 8 + (lid & 3) * 2;
        size_t r0 = (size_t)(b * 2048 + grow0) * HID + col;
        size_t r1 = (size_t)(b * 2048 + grow1) * HID + col;
        *(uint32_t*)(ohi + r0) = pack_h2(accO[nt][0] * inv0, accO[nt][1] * inv0);
        *(uint32_t*)(ohi + r1) = pack_h2(accO[nt][2] * inv1, accO[nt][3] * inv1);
    }
#undef LOAD_KV
}

// ---------------------------------------------------------------------------
// launch
// ---------------------------------------------------------------------------
extern "C" void kernel_launch(void* const* d_in, const int* in_sizes, int n_in,
                              void* d_out, int out_size)
{
    const float* x     = (const float*)d_in[0];
    const float* w_in  = (const float*)d_in[1];
    const float* w_out = (const float*)d_in[2];
    const float* qnw   = (const float*)d_in[3];
    const float* knw   = (const float*)d_in[4];
    float* out = (float*)d_out;

    float* qkv;  cudaGetSymbolAddress((void**)&qkv,  g_qkv);
    __half *ah, *bhp, *qh, *ql, *kh, *vt;
    cudaGetSymbolAddress((void**)&ah, g_a_hi);
    cudaGetSymbolAddress((void**)&bhp, g_b_hi);
    cudaGetSymbolAddress((void**)&qh, g_q_hi);
    cudaGetSymbolAddress((void**)&ql, g_q_lo);
    cudaGetSymbolAddress((void**)&kh, g_k_hi);
    cudaGetSymbolAddress((void**)&vt, g_vt);

    cudaFuncSetAttribute(gemm_t<2, 3, 4>, cudaFuncAttributeMaxDynamicSharedMemorySize, GEMM1_SMEM);
    cudaFuncSetAttribute(gemm_t<1, 2, 4>, cudaFuncAttributeMaxDynamicSharedMemorySize, GEMM2_SMEM);
    cudaFuncSetAttribute(attn_mma, cudaFuncAttributeMaxDynamicSharedMemorySize, ATTN_SMEM);

    // 1. round x -> a plane, w_in -> b plane (fp16)
    tohalf_kernel<<<(ROWS * HID / 4 + 255) / 256, 256>>>(x, ah, ROWS * HID / 4);
    tohalf_kernel<<<(QKV_W * HID / 4 + 255) / 256, 256>>>(w_in, bhp, QKV_W * HID / 4);

    // 2. QKV = x @ w_in^T  (1-term fp16, 128x192 tiles, 1024 CTAs)
    gemm_t<2, 3, 4><<<(ROWS / 128) * (QKV_W / 192), 512, GEMM1_SMEM>>>(
        ah, bhp, qkv, ROWS, QKV_W, ROWS / 128);

    // 3. tables + norm/rope; V transpose
    rope_table_kernel<<<(S_ * HALF + 255) / 256, 256>>>();
    normrope_kernel<<<ROWS, 256>>>(qkv, qnw, knw, qh, ql, kh);
    vtrans_kernel<<<dim3(ROWS / 32, HID / 32), 256>>>(qkv, vt);

    // 4. attention (QK 2-term fp16, PV 1-term) -> fp16 O plane
    //    64-row tiles, 128 thr, 96KB smem -> 2 CTAs/SM
    attn_mma<<<dim3(S_ / 64, B_ * NH), 128, ATTN_SMEM>>>(qh, ql, kh, vt, ah);

    // 5. round w_out -> b plane; out = O @ w_out^T  (1-term, 64x128 tiles)
    tohalf_kernel<<<(HID * HID / 4 + 255) / 256, 256>>>(w_out, bhp, HID * HID / 4);
    gemm_t<1, 2, 4><<<(ROWS / 64) * (HID / 128), 512, GEMM2_SMEM>>>(
        ah, bhp, out, ROWS, HID, ROWS / 64);
}

// round 14
// speedup vs baseline: 2.3977x; 1.0692x over previous
#include <cuda_runtime.h>
#include <cuda_bf16.h>
#include <cuda_fp16.h>
#include <cstdint>
#include <math.h>

// Problem constants
#define B_  2
#define S_  2048
#define HID 2048
#define NH  16
#define HD  128
#define HALF 64
#define ROWS (B_ * S_)            // 4096
#define QKV_W (3 * HID)           // 6144
#define EPS 1e-5f
#define SCALE 0.08838834764831845f   // 1/sqrt(128)
#define LOG2E 1.4426950408889634f

// Scratch (device-global; no runtime allocation allowed)
__device__ float g_qkv[(size_t)ROWS * QKV_W];            // gemm1 out (fp32)
__device__ float g_cos[S_ * HALF];
__device__ float g_sin[S_ * HALF];
__device__ __half g_a_hi[(size_t)ROWS * HID];            // gemm A plane (x; then O)
__device__ __half g_b_hi[(size_t)QKV_W * HID];           // gemm B plane (w_in; then w_out)
__device__ __half g_q_hi[(size_t)ROWS * HID];            // Q plane (scaled by log2e/sqrt(HD))
__device__ __half g_k_hi[(size_t)ROWS * HID];
__device__ __half g_vt[(size_t)ROWS * HID];              // [b][h][d][s]

__device__ __forceinline__ uint32_t smem_u32(const void* p) {
    uint32_t a;
    asm("{ .reg .u64 t; cvta.to.shared.u64 t, %1; cvt.u32.u64 %0, t; }" : "=r"(a) : "l"(p));
    return a;
}
#define SWZ(x) ((x) ^ (((x) >> 3) & 0x70))

__device__ __forceinline__ void ldsm_x4(uint32_t* r, uint32_t addr) {
    asm volatile("ldmatrix.sync.aligned.m8n8.x4.shared.b16 {%0,%1,%2,%3}, [%4];"
                 : "=r"(r[0]), "=r"(r[1]), "=r"(r[2]), "=r"(r[3]) : "r"(addr));
}
// fp16 in, f32 acc
__device__ __forceinline__ void mma_f16f32(float* c, const uint32_t* a,
                                           uint32_t b0, uint32_t b1) {
    asm volatile(
        "mma.sync.aligned.m16n8k16.row.col.f32.f16.f16.f32 "
        "{%0,%1,%2,%3}, {%4,%5,%6,%7}, {%8,%9}, {%0,%1,%2,%3};"
        : "+f"(c[0]), "+f"(c[1]), "+f"(c[2]), "+f"(c[3])
        : "r"(a[0]), "r"(a[1]), "r"(a[2]), "r"(a[3]), "r"(b0), "r"(b1));
}
__device__ __forceinline__ uint32_t pack_h2(float lo, float hi) {
    __half2 h = __floats2half2_rn(lo, hi);
    return *(uint32_t*)&h;
}

// ---------------------------------------------------------------------------
// RoPE table
// ---------------------------------------------------------------------------
__global__ void rope_table_kernel() {
    int idx = blockIdx.x * blockDim.x + threadIdx.x;
    if (idx >= S_ * HALF) return;
    int s = idx >> 6;
    int j = idx & 63;
    float freq = powf(10000.0f, -(float)j * (1.0f / 64.0f));
    float sn, cs;
    sincosf((float)s * freq, &sn, &cs);
    g_cos[idx] = cs;
    g_sin[idx] = sn;
}

// fp32 -> fp16 single-plane round
__global__ void __launch_bounds__(256) tohalf_kernel(
    const float* __restrict__ src, __half* __restrict__ dst, int n4)
{
    int i = blockIdx.x * blockDim.x + threadIdx.x;
    if (i >= n4) return;
    float4 v = ((const float4*)src)[i];
    uint64_t hp = 0;
    hp |= (uint64_t)__half_as_ushort(__float2half_rn(v.x));
    hp |= (uint64_t)__half_as_ushort(__float2half_rn(v.y)) << 16;
    hp |= (uint64_t)__half_as_ushort(__float2half_rn(v.z)) << 32;
    hp |= (uint64_t)__half_as_ushort(__float2half_rn(v.w)) << 48;
    *(uint64_t*)(dst + (size_t)i * 4) = hp;
}

// ---------------------------------------------------------------------------
// 1-term fp16 GEMM (f32 acc):  C = A*B^T   (unchanged from R12/R13)
// ---------------------------------------------------------------------------
template<int MT, int NP, int NSTG>
__global__ void __launch_bounds__(512, 1) gemm_t(
    const __half* __restrict__ A, const __half* __restrict__ B,
    float* __restrict__ C, int M, int N, int tiles_m)
{
    constexpr int BM = MT * 64;
    constexpr int BN = NP * 64;
    constexpr int A_PLANE = BM * 128;
    constexpr int B_PLANE = BN * 128;
    constexpr int SA = 0, SB = A_PLANE;
    constexpr int STG = A_PLANE + B_PLANE;
    constexpr int ACH = BM * 8;
    constexpr int BCH = BN * 8;
    constexpr int NLD = (ACH + BCH) / 512;
    static_assert((ACH + BCH) % 512 == 0, "loader divisibility");
    constexpr int NKT = HID / 64;

    extern __shared__ char smem[];
    const uint32_t sb = smem_u32(smem);
    const int tid = threadIdx.x;
    const int wid = tid >> 5, lid = tid & 31;
    const int m0 = (blockIdx.x % tiles_m) * BM;
    const int n0 = (blockIdx.x / tiles_m) * BN;
    const int wm = (wid & 3) * (MT * 16);
    const int wn = (wid >> 2) * (NP * 16);
    const int lrow = lid & 15;
    const int lhi = (lid >> 4) * 16;

    auto load_stage = [&](int st, int kt) {
        uint32_t sbase = sb + st * STG;
#pragma unroll
        for (int u = 0; u < NLD; u++) {
            int c = tid + u * 512;
            const __half* gp;
            uint32_t dst;
            if (c < ACH) {
                int r = c >> 3, c16 = c & 7;
                gp = A + (size_t)(m0 + r) * HID + kt * 64 + c16 * 8;
                dst = sbase + SA + SWZ(r * 128 + c16 * 16);
            } else {
                int cc = c - ACH;
                int r = cc >> 3, c16 = cc & 7;
                gp = B + (size_t)(n0 + r) * HID + kt * 64 + c16 * 8;
                dst = sbase + SB + SWZ(r * 128 + c16 * 16);
            }
            asm volatile("cp.async.cg.shared.global [%0], [%1], 16;"
                         :: "r"(dst), "l"(gp) : "memory");
        }
    };

#pragma unroll
    for (int s = 0; s < NSTG - 1; s++) {
        load_stage(s, s);
        asm volatile("cp.async.commit_group;" ::: "memory");
    }

    float acc[MT][NP * 2][4];
#pragma unroll
    for (int mt = 0; mt < MT; mt++)
#pragma unroll
        for (int nt = 0; nt < NP * 2; nt++)
#pragma unroll
            for (int q = 0; q < 4; q++) acc[mt][nt][q] = 0.0f;

    for (int kt = 0; kt < NKT; kt++) {
        if (kt + NSTG - 1 < NKT) load_stage((kt + NSTG - 1) % NSTG, kt + NSTG - 1);
        asm volatile("cp.async.commit_group;" ::: "memory");
        asm volatile("cp.async.wait_group %0;" :: "n"(NSTG - 1) : "memory");
        __syncthreads();

        const uint32_t sbase = sb + (kt % NSTG) * STG;

#pragma unroll
        for (int ks = 0; ks < 4; ks++) {
            const int cb = ks * 32 + lhi;
            uint32_t af[MT][4];
#pragma unroll
            for (int mt = 0; mt < MT; mt++) {
                int row = wm + mt * 16 + lrow;
                ldsm_x4(af[mt], sbase + SA + row * 128 + (cb ^ ((row & 7) * 16)));
            }
#pragma unroll
            for (int np = 0; np < NP; np++) {
                int brow = wn + np * 16 + lrow;
                uint32_t bh4[4];
                ldsm_x4(bh4, sbase + SB + brow * 128 + (cb ^ ((brow & 7) * 16)));
#pragma unroll
                for (int mt = 0; mt < MT; mt++) {
                    mma_f16f32(acc[mt][np * 2 + 0], af[mt], bh4[0], bh4[2]);
                    mma_f16f32(acc[mt][np * 2 + 1], af[mt], bh4[1], bh4[3]);
                }
            }
        }
        __syncthreads();
    }

    const int er = m0 + wm + (lid >> 2);
    const int ec = n0 + wn + (lid & 3) * 2;
#pragma unroll
    for (int mt = 0; mt < MT; mt++)
#pragma unroll
        for (int nt = 0; nt < NP * 2; nt++) {
            float* c0 = C + (size_t)(er + mt * 16) * N + ec + nt * 8;
            *(float2*)c0 = make_float2(acc[mt][nt][0], acc[mt][nt][1]);
            float* c1 = c0 + 8 * N;
            *(float2*)c1 = make_float2(acc[mt][nt][2], acc[mt][nt][3]);
        }
}

#define GEMM1_SMEM (4 * (128 * 128 + 192 * 128))   // 163840
#define GEMM2_SMEM (4 * (64 * 128 + 128 * 128))    // 98304

// ---------------------------------------------------------------------------
// Fused qk RMSNorm + RoPE: Q,K -> single fp16 planes.
// Q scaled by log2e/sqrt(HD) (base-2 softmax downstream).
// ---------------------------------------------------------------------------
__global__ void __launch_bounds__(256) normrope_kernel(
    const float* __restrict__ qkv,
    const float* __restrict__ nw_q, const float* __restrict__ nw_k,
    __half* __restrict__ qh, __half* __restrict__ kh)
{
    __shared__ float buf[HID];
    __shared__ float warpred[8];

    const int row = blockIdx.x;
    const int s = row & (S_ - 1);
    const int tid = threadIdx.x;

#pragma unroll
    for (int part = 0; part < 2; part++) {
        const float* src = qkv + (size_t)row * QKV_W + part * HID;
        const float* w = (part == 0) ? nw_q : nw_k;
        __half* dst = (part == 0) ? qh : kh;

        float ss = 0.0f;
#pragma unroll
        for (int u = 0; u < 8; u++) {
            int idx = tid + u * 256;
            float v = src[idx];
            buf[idx] = v;
            ss += v * v;
        }
#pragma unroll
        for (int o = 16; o; o >>= 1) ss += __shfl_xor_sync(0xffffffffu, ss, o);
        if ((tid & 31) == 0) warpred[tid >> 5] = ss;
        __syncthreads();
        float tot = 0.0f;
#pragma unroll
        for (int wi = 0; wi < 8; wi++) tot += warpred[wi];
        float rn = rsqrtf(tot * (1.0f / (float)HID) + EPS);
        if (part == 0) rn *= SCALE * LOG2E;

#pragma unroll
        for (int u = 0; u < 4; u++) {
            int p = tid + u * 256;
            int hh = p >> 6;
            int j = p & 63;
            int i1 = hh * HD + j;
            int i2 = i1 + HALF;
            float x1 = buf[i1] * rn * w[i1];
            float x2 = buf[i2] * rn * w[i2];
            float cs = g_cos[s * HALF + j];
            float sn = g_sin[s * HALF + j];
            size_t base = (size_t)row * HID;
            dst[base + i1] = __float2half_rn(x1 * cs - x2 * sn);
            dst[base + i2] = __float2half_rn(x2 * cs + x1 * sn);
        }
        __syncthreads();
    }
}

// ---------------------------------------------------------------------------
// V transpose: g_qkv v cols -> single fp16 plane vt [b][h][d][s]
// ---------------------------------------------------------------------------
__global__ void __launch_bounds__(256) vtrans_kernel(
    const float* __restrict__ qkv, __half* __restrict__ vt)
{
    __shared__ float t[32][33];
    const int row0 = blockIdx.x * 32;
    const int col0 = blockIdx.y * 32;
    const int tx = threadIdx.x & 31;
    const int ty = threadIdx.x >> 5;
#pragma unroll
    for (int i = 0; i < 4; i++) {
        int r = ty + i * 8;
        t[r][tx] = qkv[(size_t)(row0 + r) * QKV_W + 2 * HID + col0 + tx];
    }
    __syncthreads();
    const int b = row0 >> 11;
    const int s0 = row0 & 2047;
#pragma unroll
    for (int i = 0; i < 4; i++) {
        int c = ty + i * 8;
        float v = t[tx][c];
        size_t o = ((size_t)(b * 2048 + col0 + c)) * 2048 + s0 + tx;
        vt[o] = __float2half_rn(v);
    }
}

// ---------------------------------------------------------------------------
// Flash attention, fp16 mma.sync: QK 1-term, PV 1-term, base-2 softmax.
// 64 q rows x (b,h), 128 threads / 4 warps, 2-stage KV, smem 80KB -> 2 CTAs/SM.
// Q fragments hoisted to registers. Output -> fp16 O plane.
// ---------------------------------------------------------------------------
#define SQ 0
#define KVSTG 32768
#define SK(s) (16384 + (s) * KVSTG)
#define SV(s) (SK(s) + 16384)
#define ATTN_SMEM (16384 + 2 * KVSTG)   // 81920

__global__ void __launch_bounds__(128) attn_mma(
    const __half* __restrict__ qh, const __half* __restrict__ kh,
    const __half* __restrict__ vt, __half* __restrict__ ohi)
{
    extern __shared__ char smem[];
    const uint32_t sb = smem_u32(smem);
    const int tid = threadIdx.x;
    const int wid = tid >> 5, lid = tid & 31;
    const int lrow = lid & 15;
    const int lhi = (lid >> 4) * 16;
    const int bh = blockIdx.y;
    const int b = bh >> 4, h = bh & 15;
    const int qt = gridDim.x - 1 - blockIdx.x;   // heavy tiles first
    const int q0 = qt * 64;
    const int nkb = qt + 1;
    const int wm = wid * 16;

    // ---- load Q (64 rows, single plane): 1024 16B-chunks ----
#pragma unroll
    for (int u = 0; u < 8; u++) {
        int c = tid + u * 128;
        int r = c >> 4, ch = c & 15;
        int p = ch >> 3, c8 = ch & 7;
        const __half* src = qh + ((size_t)(b * 2048 + q0 + r) * HID + h * HD + ch * 8);
        uint32_t dst = sb + SQ + p * 8192 + SWZ(r * 128 + c8 * 16);
        asm volatile("cp.async.cg.shared.global [%0], [%1], 16;"
                     :: "r"(dst), "l"(src) : "memory");
    }
    asm volatile("cp.async.commit_group;" ::: "memory");

// 2048 16B-chunks per stage: K (1024) + V (1024)
#define LOAD_KV(s, kt) do {                                                    \
    int k0 = (kt) * 64;                                                        \
    _Pragma("unroll")                                                          \
    for (int u = 0; u < 16; u++) {                                             \
        int c = tid + u * 128;                                                 \
        if (c < 1024) {                                                        \
            int r = c >> 4, ch = c & 15;                                       \
            int p = ch >> 3, c8 = ch & 7;                                      \
            const __half* src = kh +                                           \
                ((size_t)(b * 2048 + k0 + r) * HID + h * HD + ch * 8);         \
            uint32_t dst = sb + SK(s) + p * 8192 + SWZ(r * 128 + c8 * 16);     \
            asm volatile("cp.async.cg.shared.global [%0], [%1], 16;"           \
                         :: "r"(dst), "l"(src) : "memory");                    \
        } else {                                                               \
            int cc = c - 1024;                                                 \
            int d = cc >> 3, c8 = cc & 7;                                      \
            const __half* src = vt +                                           \
                ((size_t)(b * 2048 + h * HD + d) * 2048 + k0 + c8 * 8);        \
            uint32_t dst = sb + SV(s) + SWZ(d * 128 + c8 * 16);                \
            asm volatile("cp.async.cg.shared.global [%0], [%1], 16;"           \
                         :: "r"(dst), "l"(src) : "memory");                    \
        }                                                                      \
    }                                                                          \
} while (0)

    LOAD_KV(0, 0);
    asm volatile("cp.async.commit_group;" ::: "memory");

    // ---- hoist Q fragments into registers ----
    asm volatile("cp.async.wait_group 1;" ::: "memory");
    __syncthreads();
    uint32_t qr[8][4];
#pragma unroll
    for (int kk = 0; kk < 8; kk++) {
        int p = kk >> 2;
        int cb = (kk & 3) * 32 + lhi;
        int arow = wm + lrow;
        ldsm_x4(qr[kk], sb + SQ + p * 8192 + arow * 128 + (cb ^ ((arow & 7) * 16)));
    }

    float accO[16][4];
#pragma unroll
    for (int nt = 0; nt < 16; nt++)
#pragma unroll
        for (int q = 0; q < 4; q++) accO[nt][q] = 0.0f;
    float m0v = -1e30f, m1v = -1e30f, l0v = 0.0f, l1v = 0.0f;

    const int grow0 = q0 + wm + (lid >> 2);
    const int grow1 = grow0 + 8;

    for (int kt = 0; kt < nkb; kt++) {
        __syncthreads();
        if (kt + 1 < nkb) LOAD_KV((kt + 1) & 1, kt + 1);
        asm volatile("cp.async.commit_group;" ::: "memory");
        asm volatile("cp.async.wait_group 1;" ::: "memory");
        __syncthreads();

        // fully-masked ktile for this warp?
        if (kt * 64 > q0 + wm + 15) continue;

        const int s = kt & 1;

        // ---- S = Q*K  (1-term fp16, Q frags from regs; logits in log2 units) ----
        float sa[8][4];
#pragma unroll
        for (int nt = 0; nt < 8; nt++)
#pragma unroll
            for (int q = 0; q < 4; q++) sa[nt][q] = 0.0f;

#pragma unroll
        for (int kk = 0; kk < 8; kk++) {
            int p = kk >> 2;
            int cb = (kk & 3) * 32 + lhi;
#pragma unroll
            for (int np = 0; np < 4; np++) {
                int brow = np * 16 + lrow;
                uint32_t boff = p * 8192 + brow * 128 + (cb ^ ((brow & 7) * 16));
                uint32_t khf[4];
                ldsm_x4(khf, sb + SK(s) + boff);
                mma_f16f32(sa[np * 2 + 0], qr[kk], khf[0], khf[2]);
                mma_f16f32(sa[np * 2 + 1], qr[kk], khf[1], khf[3]);
            }
        }

        // ---- causal mask ----
        if ((kt + 1) * 64 - 1 > q0 + wm) {
            const int colb = kt * 64 + (lid & 3) * 2;
#pragma unroll
            for (int nt = 0; nt < 8; nt++) {
                int col = colb + nt * 8;
                if (col > grow0)     sa[nt][0] = -1e30f;
                if (col + 1 > grow0) sa[nt][1] = -1e30f;
                if (col > grow1)     sa[nt][2] = -1e30f;
                if (col + 1 > grow1) sa[nt][3] = -1e30f;
            }
        }

        // ---- online softmax (base 2) ----
        float mx0 = m0v, mx1 = m1v;
#pragma unroll
        for (int nt = 0; nt < 8; nt++) {
            mx0 = fmaxf(mx0, fmaxf(sa[nt][0], sa[nt][1]));
            mx1 = fmaxf(mx1, fmaxf(sa[nt][2], sa[nt][3]));
        }
        mx0 = fmaxf(mx0, __shfl_xor_sync(0xffffffffu, mx0, 1));
        mx0 = fmaxf(mx0, __shfl_xor_sync(0xffffffffu, mx0, 2));
        mx1 = fmaxf(mx1, __shfl_xor_sync(0xffffffffu, mx1, 1));
        mx1 = fmaxf(mx1, __shfl_xor_sync(0xffffffffu, mx1, 2));
        float alpha0 = exp2f(m0v - mx0);
        float alpha1 = exp2f(m1v - mx1);
        m0v = mx0; m1v = mx1;

        float ls0 = 0.0f, ls1 = 0.0f;
#pragma unroll
        for (int nt = 0; nt < 8; nt++) {
            sa[nt][0] = exp2f(sa[nt][0] - mx0);
            sa[nt][1] = exp2f(sa[nt][1] - mx0);
            sa[nt][2] = exp2f(sa[nt][2] - mx1);
            sa[nt][3] = exp2f(sa[nt][3] - mx1);
            ls0 += sa[nt][0] + sa[nt][1];
            ls1 += sa[nt][2] + sa[nt][3];
        }
        ls0 += __shfl_xor_sync(0xffffffffu, ls0, 1);
        ls0 += __shfl_xor_sync(0xffffffffu, ls0, 2);
        ls1 += __shfl_xor_sync(0xffffffffu, ls1, 1);
        ls1 += __shfl_xor_sync(0xffffffffu, ls1, 2);
        l0v = l0v * alpha0 + ls0;
        l1v = l1v * alpha1 + ls1;

#pragma unroll
        for (int nt = 0; nt < 16; nt++) {
            accO[nt][0] *= alpha0; accO[nt][1] *= alpha0;
            accO[nt][2] *= alpha1; accO[nt][3] *= alpha1;
        }

        // ---- P -> fp16 A-fragments ----
        uint32_t phA[8], phB[8];
#pragma unroll
        for (int nt = 0; nt < 8; nt++) {
            phA[nt] = pack_h2(sa[nt][0], sa[nt][1]);
            phB[nt] = pack_h2(sa[nt][2], sa[nt][3]);
        }

        // ---- O += P*V ----
#pragma unroll
        for (int ki = 0; ki < 4; ki++) {
            uint32_t aH[4] = {phA[2 * ki], phB[2 * ki], phA[2 * ki + 1], phB[2 * ki + 1]};
            int cb = ki * 32 + lhi;
#pragma unroll
            for (int np = 0; np < 8; np++) {
                int brow = np * 16 + lrow;
                uint32_t boff = brow * 128 + (cb ^ ((brow & 7) * 16));
                uint32_t vhf[4];
                ldsm_x4(vhf, sb + SV(s) + boff);
                mma_f16f32(accO[np * 2 + 0], aH, vhf[0], vhf[2]);
                mma_f16f32(accO[np * 2 + 1], aH, vhf[1], vhf[3]);
            }
        }
    }

    // ---- epilogue: O/l -> single fp16 plane ----
    float inv0 = 1.0f / l0v, inv1 = 1.0f / l1v;
#pragma unroll
    for (int nt = 0; nt < 16; nt++) {
        int col = h * HD + nt * 8 + (lid & 3) * 2;
        size_t r0 = (size_t)(b * 2048 + grow0) * HID + col;
        size_t r1 = (size_t)(b * 2048 + grow1) * HID + col;
        *(uint32_t*)(ohi + r0) = pack_h2(accO[nt][0] * inv0, accO[nt][1] * inv0);
        *(uint32_t*)(ohi + r1) = pack_h2(accO[nt][2] * inv1, accO[nt][3] * inv1);
    }
#undef LOAD_KV
}

// ---------------------------------------------------------------------------
// launch
// ---------------------------------------------------------------------------
extern "C" void kernel_launch(void* const* d_in, const int* in_sizes, int n_in,
                              void* d_out, int out_size)
{
    const float* x     = (const float*)d_in[0];
    const float* w_in  = (const float*)d_in[1];
    const float* w_out = (const float*)d_in[2];
    const float* qnw   = (const float*)d_in[3];
    const float* knw   = (const float*)d_in[4];
    float* out = (float*)d_out;

    float* qkv;  cudaGetSymbolAddress((void**)&qkv,  g_qkv);
    __half *ah, *bhp, *qh, *kh, *vt;
    cudaGetSymbolAddress((void**)&ah, g_a_hi);
    cudaGetSymbolAddress((void**)&bhp, g_b_hi);
    cudaGetSymbolAddress((void**)&qh, g_q_hi);
    cudaGetSymbolAddress((void**)&kh, g_k_hi);
    cudaGetSymbolAddress((void**)&vt, g_vt);

    cudaFuncSetAttribute(gemm_t<2, 3, 4>, cudaFuncAttributeMaxDynamicSharedMemorySize, GEMM1_SMEM);
    cudaFuncSetAttribute(gemm_t<1, 2, 4>, cudaFuncAttributeMaxDynamicSharedMemorySize, GEMM2_SMEM);
    cudaFuncSetAttribute(attn_mma, cudaFuncAttributeMaxDynamicSharedMemorySize, ATTN_SMEM);

    // 1. round x -> a plane, w_in -> b plane (fp16)
    tohalf_kernel<<<(ROWS * HID / 4 + 255) / 256, 256>>>(x, ah, ROWS * HID / 4);
    tohalf_kernel<<<(QKV_W * HID / 4 + 255) / 256, 256>>>(w_in, bhp, QKV_W * HID / 4);

    // 2. QKV = x @ w_in^T  (1-term fp16, 128x192 tiles, 1024 CTAs)
    gemm_t<2, 3, 4><<<(ROWS / 128) * (QKV_W / 192), 512, GEMM1_SMEM>>>(
        ah, bhp, qkv, ROWS, QKV_W, ROWS / 128);

    // 3. tables + norm/rope (single planes, Q pre-scaled by log2e); V transpose
    rope_table_kernel<<<(S_ * HALF + 255) / 256, 256>>>();
    normrope_kernel<<<ROWS, 256>>>(qkv, qnw, knw, qh, kh);
    vtrans_kernel<<<dim3(ROWS / 32, HID / 32), 256>>>(qkv, vt);

    // 4. attention (QK 1-term, PV 1-term, base-2 softmax) -> fp16 O plane
    attn_mma<<<dim3(S_ / 64, B_ * NH), 128, ATTN_SMEM>>>(qh, kh, vt, ah);

    // 5. round w_out -> b plane; out = O @ w_out^T
    tohalf_kernel<<<(HID * HID / 4 + 255) / 256, 256>>>(w_out, bhp, HID * HID / 4);
    gemm_t<1, 2, 4><<<(ROWS / 64) * (HID / 128), 512, GEMM2_SMEM>>>(
        ah, bhp, out, ROWS, HID, ROWS / 64);
}

// round 15
// speedup vs baseline: 2.4900x; 1.0385x over previous
#include <cuda_runtime.h>
#include <cuda_bf16.h>
#include <cuda_fp16.h>
#include <cstdint>
#include <math.h>

// Problem constants
#define B_  2
#define S_  2048
#define HID 2048
#define NH  16
#define HD  128
#define HALF 64
#define ROWS (B_ * S_)            // 4096
#define QKV_W (3 * HID)           // 6144
#define EPS 1e-5f
#define SCALE 0.08838834764831845f   // 1/sqrt(128)
#define LOG2E 1.4426950408889634f

// Scratch (device-global; no runtime allocation allowed)
__device__ __half g_qkvh[(size_t)ROWS * QKV_W];          // gemm1 out (fp16, 50MB)
__device__ float g_cos[S_ * HALF];
__device__ float g_sin[S_ * HALF];
__device__ __half g_a_hi[(size_t)ROWS * HID];            // gemm A plane (x; then O)
__device__ __half g_b_hi[(size_t)QKV_W * HID];           // gemm B plane (w_in; then w_out)
__device__ __half g_q_hi[(size_t)ROWS * HID];            // Q plane (scaled by log2e/sqrt(HD))
__device__ __half g_k_hi[(size_t)ROWS * HID];

__device__ __forceinline__ uint32_t smem_u32(const void* p) {
    uint32_t a;
    asm("{ .reg .u64 t; cvta.to.shared.u64 t, %1; cvt.u32.u64 %0, t; }" : "=r"(a) : "l"(p));
    return a;
}
#define SWZ(x) ((x) ^ (((x) >> 3) & 0x70))

__device__ __forceinline__ void ldsm_x4(uint32_t* r, uint32_t addr) {
    asm volatile("ldmatrix.sync.aligned.m8n8.x4.shared.b16 {%0,%1,%2,%3}, [%4];"
                 : "=r"(r[0]), "=r"(r[1]), "=r"(r[2]), "=r"(r[3]) : "r"(addr));
}
__device__ __forceinline__ void ldsm_x4_t(uint32_t* r, uint32_t addr) {
    asm volatile("ldmatrix.sync.aligned.m8n8.x4.trans.shared.b16 {%0,%1,%2,%3}, [%4];"
                 : "=r"(r[0]), "=r"(r[1]), "=r"(r[2]), "=r"(r[3]) : "r"(addr));
}
// fp16 in, f32 acc
__device__ __forceinline__ void mma_f16f32(float* c, const uint32_t* a,
                                           uint32_t b0, uint32_t b1) {
    asm volatile(
        "mma.sync.aligned.m16n8k16.row.col.f32.f16.f16.f32 "
        "{%0,%1,%2,%3}, {%4,%5,%6,%7}, {%8,%9}, {%0,%1,%2,%3};"
        : "+f"(c[0]), "+f"(c[1]), "+f"(c[2]), "+f"(c[3])
        : "r"(a[0]), "r"(a[1]), "r"(a[2]), "r"(a[3]), "r"(b0), "r"(b1));
}
__device__ __forceinline__ uint32_t pack_h2(float lo, float hi) {
    __half2 h = __floats2half2_rn(lo, hi);
    return *(uint32_t*)&h;
}

// ---------------------------------------------------------------------------
// RoPE table
// ---------------------------------------------------------------------------
__global__ void rope_table_kernel() {
    int idx = blockIdx.x * blockDim.x + threadIdx.x;
    if (idx >= S_ * HALF) return;
    int s = idx >> 6;
    int j = idx & 63;
    float freq = powf(10000.0f, -(float)j * (1.0f / 64.0f));
    float sn, cs;
    sincosf((float)s * freq, &sn, &cs);
    g_cos[idx] = cs;
    g_sin[idx] = sn;
}

// fp32 -> fp16 single-plane round
__global__ void __launch_bounds__(256) tohalf_kernel(
    const float* __restrict__ src, __half* __restrict__ dst, int n4)
{
    int i = blockIdx.x * blockDim.x + threadIdx.x;
    if (i >= n4) return;
    float4 v = ((const float4*)src)[i];
    uint64_t hp = 0;
    hp |= (uint64_t)__half_as_ushort(__float2half_rn(v.x));
    hp |= (uint64_t)__half_as_ushort(__float2half_rn(v.y)) << 16;
    hp |= (uint64_t)__half_as_ushort(__float2half_rn(v.z)) << 32;
    hp |= (uint64_t)__half_as_ushort(__float2half_rn(v.w)) << 48;
    *(uint64_t*)(dst + (size_t)i * 4) = hp;
}

// ---------------------------------------------------------------------------
// 1-term fp16 GEMM (f32 acc):  C = A*B^T.  H16OUT selects fp16/fp32 output.
// ---------------------------------------------------------------------------
template<int MT, int NP, int NSTG, bool H16OUT>
__global__ void __launch_bounds__(512, 1) gemm_t(
    const __half* __restrict__ A, const __half* __restrict__ B,
    void* __restrict__ Cv, int M, int N, int tiles_m)
{
    constexpr int BM = MT * 64;
    constexpr int BN = NP * 64;
    constexpr int A_PLANE = BM * 128;
    constexpr int B_PLANE = BN * 128;
    constexpr int SA = 0, SB = A_PLANE;
    constexpr int STG = A_PLANE + B_PLANE;
    constexpr int ACH = BM * 8;
    constexpr int BCH = BN * 8;
    constexpr int NLD = (ACH + BCH) / 512;
    static_assert((ACH + BCH) % 512 == 0, "loader divisibility");
    constexpr int NKT = HID / 64;

    extern __shared__ char smem[];
    const uint32_t sb = smem_u32(smem);
    const int tid = threadIdx.x;
    const int wid = tid >> 5, lid = tid & 31;
    const int m0 = (blockIdx.x % tiles_m) * BM;
    const int n0 = (blockIdx.x / tiles_m) * BN;
    const int wm = (wid & 3) * (MT * 16);
    const int wn = (wid >> 2) * (NP * 16);
    const int lrow = lid & 15;
    const int lhi = (lid >> 4) * 16;

    auto load_stage = [&](int st, int kt) {
        uint32_t sbase = sb + st * STG;
#pragma unroll
        for (int u = 0; u < NLD; u++) {
            int c = tid + u * 512;
            const __half* gp;
            uint32_t dst;
            if (c < ACH) {
                int r = c >> 3, c16 = c & 7;
                gp = A + (size_t)(m0 + r) * HID + kt * 64 + c16 * 8;
                dst = sbase + SA + SWZ(r * 128 + c16 * 16);
            } else {
                int cc = c - ACH;
                int r = cc >> 3, c16 = cc & 7;
                gp = B + (size_t)(n0 + r) * HID + kt * 64 + c16 * 8;
                dst = sbase + SB + SWZ(r * 128 + c16 * 16);
            }
            asm volatile("cp.async.cg.shared.global [%0], [%1], 16;"
                         :: "r"(dst), "l"(gp) : "memory");
        }
    };

#pragma unroll
    for (int s = 0; s < NSTG - 1; s++) {
        load_stage(s, s);
        asm volatile("cp.async.commit_group;" ::: "memory");
    }

    float acc[MT][NP * 2][4];
#pragma unroll
    for (int mt = 0; mt < MT; mt++)
#pragma unroll
        for (int nt = 0; nt < NP * 2; nt++)
#pragma unroll
            for (int q = 0; q < 4; q++) acc[mt][nt][q] = 0.0f;

    for (int kt = 0; kt < NKT; kt++) {
        if (kt + NSTG - 1 < NKT) load_stage((kt + NSTG - 1) % NSTG, kt + NSTG - 1);
        asm volatile("cp.async.commit_group;" ::: "memory");
        asm volatile("cp.async.wait_group %0;" :: "n"(NSTG - 1) : "memory");
        __syncthreads();

        const uint32_t sbase = sb + (kt % NSTG) * STG;

#pragma unroll
        for (int ks = 0; ks < 4; ks++) {
            const int cb = ks * 32 + lhi;
            uint32_t af[MT][4];
#pragma unroll
            for (int mt = 0; mt < MT; mt++) {
                int row = wm + mt * 16 + lrow;
                ldsm_x4(af[mt], sbase + SA + row * 128 + (cb ^ ((row & 7) * 16)));
            }
#pragma unroll
            for (int np = 0; np < NP; np++) {
                int brow = wn + np * 16 + lrow;
                uint32_t bh4[4];
                ldsm_x4(bh4, sbase + SB + brow * 128 + (cb ^ ((brow & 7) * 16)));
#pragma unroll
                for (int mt = 0; mt < MT; mt++) {
                    mma_f16f32(acc[mt][np * 2 + 0], af[mt], bh4[0], bh4[2]);
                    mma_f16f32(acc[mt][np * 2 + 1], af[mt], bh4[1], bh4[3]);
                }
            }
        }
        __syncthreads();
    }

    const int er = m0 + wm + (lid >> 2);
    const int ec = n0 + wn + (lid & 3) * 2;
#pragma unroll
    for (int mt = 0; mt < MT; mt++)
#pragma unroll
        for (int nt = 0; nt < NP * 2; nt++) {
            if (H16OUT) {
                __half* Ch = (__half*)Cv;
                *(uint32_t*)(Ch + (size_t)(er + mt * 16) * N + ec + nt * 8) =
                    pack_h2(acc[mt][nt][0], acc[mt][nt][1]);
                *(uint32_t*)(Ch + (size_t)(er + mt * 16 + 8) * N + ec + nt * 8) =
                    pack_h2(acc[mt][nt][2], acc[mt][nt][3]);
            } else {
                float* C = (float*)Cv;
                float* c0 = C + (size_t)(er + mt * 16) * N + ec + nt * 8;
                *(float2*)c0 = make_float2(acc[mt][nt][0], acc[mt][nt][1]);
                float* c1 = c0 + 8 * N;
                *(float2*)c1 = make_float2(acc[mt][nt][2], acc[mt][nt][3]);
            }
        }
}

#define GEMM1_SMEM (4 * (128 * 128 + 192 * 128))   // 163840
#define GEMM2_SMEM (4 * (64 * 128 + 128 * 128))    // 98304

// ---------------------------------------------------------------------------
// Fused qk RMSNorm + RoPE on fp16 QKV: Q,K -> single fp16 planes.
// Q scaled by log2e/sqrt(HD).
// ---------------------------------------------------------------------------
__global__ void __launch_bounds__(256) normrope_kernel(
    const __half* __restrict__ qkvh,
    const float* __restrict__ nw_q, const float* __restrict__ nw_k,
    __half* __restrict__ qh, __half* __restrict__ kh)
{
    __shared__ float buf[HID];
    __shared__ float warpred[8];

    const int row = blockIdx.x;
    const int s = row & (S_ - 1);
    const int tid = threadIdx.x;

#pragma unroll
    for (int part = 0; part < 2; part++) {
        const __half* src = qkvh + (size_t)row * QKV_W + part * HID;
        const float* w = (part == 0) ? nw_q : nw_k;
        __half* dst = (part == 0) ? qh : kh;

        // each thread loads 8 halves (one uint4)
        float ss = 0.0f;
        {
            uint4 v = *(const uint4*)(src + tid * 8);
            const __half2* hp = (const __half2*)&v;
#pragma unroll
            for (int q = 0; q < 4; q++) {
                float2 f = __half22float2(hp[q]);
                buf[tid * 8 + q * 2]     = f.x;
                buf[tid * 8 + q * 2 + 1] = f.y;
                ss += f.x * f.x + f.y * f.y;
            }
        }
#pragma unroll
        for (int o = 16; o; o >>= 1) ss += __shfl_xor_sync(0xffffffffu, ss, o);
        if ((tid & 31) == 0) warpred[tid >> 5] = ss;
        __syncthreads();
        float tot = 0.0f;
#pragma unroll
        for (int wi = 0; wi < 8; wi++) tot += warpred[wi];
        float rn = rsqrtf(tot * (1.0f / (float)HID) + EPS);
        if (part == 0) rn *= SCALE * LOG2E;

#pragma unroll
        for (int u = 0; u < 4; u++) {
            int p = tid + u * 256;
            int hh = p >> 6;
            int j = p & 63;
            int i1 = hh * HD + j;
            int i2 = i1 + HALF;
            float x1 = buf[i1] * rn * w[i1];
            float x2 = buf[i2] * rn * w[i2];
            float cs = g_cos[s * HALF + j];
            float sn = g_sin[s * HALF + j];
            size_t base = (size_t)row * HID;
            dst[base + i1] = __float2half_rn(x1 * cs - x2 * sn);
            dst[base + i2] = __float2half_rn(x2 * cs + x1 * sn);
        }
        __syncthreads();
    }
}

// ---------------------------------------------------------------------------
// Flash attention, fp16 mma.sync: QK 1-term, PV 1-term, base-2 softmax.
// V staged directly from fp16 QKV rows ([token][d]); PV B-frags via
// ldmatrix.trans (no separate V-transpose pass).
// 64 q rows x (b,h), 128 threads / 4 warps, 2-stage KV, smem 80KB -> 2 CTAs/SM.
// ---------------------------------------------------------------------------
#define SQ 0
#define KVSTG 32768
#define SK(s) (16384 + (s) * KVSTG)
#define SV(s) (SK(s) + 16384)
#define ATTN_SMEM (16384 + 2 * KVSTG)   // 81920

__global__ void __launch_bounds__(128) attn_mma(
    const __half* __restrict__ qh, const __half* __restrict__ kh,
    const __half* __restrict__ qkvh, __half* __restrict__ ohi)
{
    extern __shared__ char smem[];
    const uint32_t sb = smem_u32(smem);
    const int tid = threadIdx.x;
    const int wid = tid >> 5, lid = tid & 31;
    const int lrow = lid & 15;
    const int lhi = (lid >> 4) * 16;
    const int bh = blockIdx.y;
    const int b = bh >> 4, h = bh & 15;
    const int qt = gridDim.x - 1 - blockIdx.x;   // heavy tiles first
    const int q0 = qt * 64;
    const int nkb = qt + 1;
    const int wm = wid * 16;

    // trans-load lane geometry for V fragments
    const int vm = lid >> 3;                 // matrix index 0..3
    const int vrow_l = (vm & 1) * 8 + (lid & 7);   // token within 16-chunk
    const int vcol_l = (vm >> 1) * 8;              // d within 16-block

    // ---- load Q (64 rows, single plane): 1024 16B-chunks ----
#pragma unroll
    for (int u = 0; u < 8; u++) {
        int c = tid + u * 128;
        int r = c >> 4, ch = c & 15;
        int p = ch >> 3, c8 = ch & 7;
        const __half* src = qh + ((size_t)(b * 2048 + q0 + r) * HID + h * HD + ch * 8);
        uint32_t dst = sb + SQ + p * 8192 + SWZ(r * 128 + c8 * 16);
        asm volatile("cp.async.cg.shared.global [%0], [%1], 16;"
                     :: "r"(dst), "l"(src) : "memory");
    }
    asm volatile("cp.async.commit_group;" ::: "memory");

// 2048 16B-chunks per stage: K (1024 from kh) + V (1024 from qkvh rows)
#define LOAD_KV(s, kt) do {                                                    \
    int k0 = (kt) * 64;                                                        \
    _Pragma("unroll")                                                          \
    for (int u = 0; u < 16; u++) {                                             \
        int c = tid + u * 128;                                                 \
        if (c < 1024) {                                                        \
            int r = c >> 4, ch = c & 15;                                       \
            int p = ch >> 3, c8 = ch & 7;                                      \
            const __half* src = kh +                                           \
                ((size_t)(b * 2048 + k0 + r) * HID + h * HD + ch * 8);         \
            uint32_t dst = sb + SK(s) + p * 8192 + SWZ(r * 128 + c8 * 16);     \
            asm volatile("cp.async.cg.shared.global [%0], [%1], 16;"           \
                         :: "r"(dst), "l"(src) : "memory");                    \
        } else {                                                               \
            int cc = c - 1024;                                                 \
            int r = cc >> 4, ch = cc & 15;                                     \
            int p = ch >> 3, c8 = ch & 7;                                      \
            const __half* src = qkvh +                                         \
                ((size_t)(b * 2048 + k0 + r) * QKV_W + 2 * HID + h * HD + ch * 8); \
            uint32_t dst = sb + SV(s) + p * 8192 + SWZ(r * 128 + c8 * 16);     \
            asm volatile("cp.async.cg.shared.global [%0], [%1], 16;"           \
                         :: "r"(dst), "l"(src) : "memory");                    \
        }                                                                      \
    }                                                                          \
} while (0)

    LOAD_KV(0, 0);
    asm volatile("cp.async.commit_group;" ::: "memory");

    // ---- hoist Q fragments into registers ----
    asm volatile("cp.async.wait_group 1;" ::: "memory");
    __syncthreads();
    uint32_t qr[8][4];
#pragma unroll
    for (int kk = 0; kk < 8; kk++) {
        int p = kk >> 2;
        int cb = (kk & 3) * 32 + lhi;
        int arow = wm + lrow;
        ldsm_x4(qr[kk], sb + SQ + p * 8192 + arow * 128 + (cb ^ ((arow & 7) * 16)));
    }

    float accO[16][4];
#pragma unroll
    for (int nt = 0; nt < 16; nt++)
#pragma unroll
        for (int q = 0; q < 4; q++) accO[nt][q] = 0.0f;
    float m0v = -1e30f, m1v = -1e30f, l0v = 0.0f, l1v = 0.0f;

    const int grow0 = q0 + wm + (lid >> 2);
    const int grow1 = grow0 + 8;

    for (int kt = 0; kt < nkb; kt++) {
        __syncthreads();
        if (kt + 1 < nkb) LOAD_KV((kt + 1) & 1, kt + 1);
        asm volatile("cp.async.commit_group;" ::: "memory");
        asm volatile("cp.async.wait_group 1;" ::: "memory");
        __syncthreads();

        // fully-masked ktile for this warp?
        if (kt * 64 > q0 + wm + 15) continue;

        const int s = kt & 1;

        // ---- S = Q*K  (logits in log2 units) ----
        float sa[8][4];
#pragma unroll
        for (int nt = 0; nt < 8; nt++)
#pragma unroll
            for (int q = 0; q < 4; q++) sa[nt][q] = 0.0f;

#pragma unroll
        for (int kk = 0; kk < 8; kk++) {
            int p = kk >> 2;
            int cb = (kk & 3) * 32 + lhi;
#pragma unroll
            for (int np = 0; np < 4; np++) {
                int brow = np * 16 + lrow;
                uint32_t boff = p * 8192 + brow * 128 + (cb ^ ((brow & 7) * 16));
                uint32_t khf[4];
                ldsm_x4(khf, sb + SK(s) + boff);
                mma_f16f32(sa[np * 2 + 0], qr[kk], khf[0], khf[2]);
                mma_f16f32(sa[np * 2 + 1], qr[kk], khf[1], khf[3]);
            }
        }

        // ---- causal mask ----
        if ((kt + 1) * 64 - 1 > q0 + wm) {
            const int colb = kt * 64 + (lid & 3) * 2;
#pragma unroll
            for (int nt = 0; nt < 8; nt++) {
                int col = colb + nt * 8;
                if (col > grow0)     sa[nt][0] = -1e30f;
                if (col + 1 > grow0) sa[nt][1] = -1e30f;
                if (col > grow1)     sa[nt][2] = -1e30f;
                if (col + 1 > grow1) sa[nt][3] = -1e30f;
            }
        }

        // ---- online softmax (base 2) ----
        float mx0 = m0v, mx1 = m1v;
#pragma unroll
        for (int nt = 0; nt < 8; nt++) {
            mx0 = fmaxf(mx0, fmaxf(sa[nt][0], sa[nt][1]));
            mx1 = fmaxf(mx1, fmaxf(sa[nt][2], sa[nt][3]));
        }
        mx0 = fmaxf(mx0, __shfl_xor_sync(0xffffffffu, mx0, 1));
        mx0 = fmaxf(mx0, __shfl_xor_sync(0xffffffffu, mx0, 2));
        mx1 = fmaxf(mx1, __shfl_xor_sync(0xffffffffu, mx1, 1));
        mx1 = fmaxf(mx1, __shfl_xor_sync(0xffffffffu, mx1, 2));
        float alpha0 = exp2f(m0v - mx0);
        float alpha1 = exp2f(m1v - mx1);
        m0v = mx0; m1v = mx1;

        float ls0 = 0.0f, ls1 = 0.0f;
#pragma unroll
        for (int nt = 0; nt < 8; nt++) {
            sa[nt][0] = exp2f(sa[nt][0] - mx0);
            sa[nt][1] = exp2f(sa[nt][1] - mx0);
            sa[nt][2] = exp2f(sa[nt][2] - mx1);
            sa[nt][3] = exp2f(sa[nt][3] - mx1);
            ls0 += sa[nt][0] + sa[nt][1];
            ls1 += sa[nt][2] + sa[nt][3];
        }
        ls0 += __shfl_xor_sync(0xffffffffu, ls0, 1);
        ls0 += __shfl_xor_sync(0xffffffffu, ls0, 2);
        ls1 += __shfl_xor_sync(0xffffffffu, ls1, 1);
        ls1 += __shfl_xor_sync(0xffffffffu, ls1, 2);
        l0v = l0v * alpha0 + ls0;
        l1v = l1v * alpha1 + ls1;

#pragma unroll
        for (int nt = 0; nt < 16; nt++) {
            accO[nt][0] *= alpha0; accO[nt][1] *= alpha0;
            accO[nt][2] *= alpha1; accO[nt][3] *= alpha1;
        }

        // ---- P -> fp16 A-fragments ----
        uint32_t phA[8], phB[8];
#pragma unroll
        for (int nt = 0; nt < 8; nt++) {
            phA[nt] = pack_h2(sa[nt][0], sa[nt][1]);
            phB[nt] = pack_h2(sa[nt][2], sa[nt][3]);
        }

        // ---- O += P*V  (V fragments via ldmatrix.trans from [token][d]) ----
#pragma unroll
        for (int ki = 0; ki < 4; ki++) {
            uint32_t aH[4] = {phA[2 * ki], phB[2 * ki], phA[2 * ki + 1], phB[2 * ki + 1]};
            int token = ki * 16 + vrow_l;
#pragma unroll
            for (int np = 0; np < 8; np++) {
                int dcol = np * 16 + vcol_l;
                int p = dcol >> 6;
                int colb = (dcol & 63) * 2;
                uint32_t vhf[4];
                ldsm_x4_t(vhf, sb + SV(s) + p * 8192 + token * 128 +
                               (colb ^ ((token & 7) * 16)));
                mma_f16f32(accO[np * 2 + 0], aH, vhf[0], vhf[1]);
                mma_f16f32(accO[np * 2 + 1], aH, vhf[2], vhf[3]);
            }
        }
    }

    // ---- epilogue: O/l -> single fp16 plane ----
    float inv0 = 1.0f / l0v, inv1 = 1.0f / l1v;
#pragma unroll
    for (int nt = 0; nt < 16; nt++) {
        int col = h * HD + nt * 8 + (lid & 3) * 2;
        size_t r0 = (size_t)(b * 2048 + grow0) * HID + col;
        size_t r1 = (size_t)(b * 2048 + grow1) * HID + col;
        *(uint32_t*)(ohi + r0) = pack_h2(accO[nt][0] * inv0, accO[nt][1] * inv0);
        *(uint32_t*)(ohi + r1) = pack_h2(accO[nt][2] * inv1, accO[nt][3] * inv1);
    }
#undef LOAD_KV
}

// ---------------------------------------------------------------------------
// launch
// ---------------------------------------------------------------------------
extern "C" void kernel_launch(void* const* d_in, const int* in_sizes, int n_in,
                              void* d_out, int out_size)
{
    const float* x     = (const float*)d_in[0];
    const float* w_in  = (const float*)d_in[1];
    const float* w_out = (const float*)d_in[2];
    const float* qnw   = (const float*)d_in[3];
    const float* knw   = (const float*)d_in[4];
    float* out = (float*)d_out;

    __half *qkvh, *ah, *bhp, *qh, *kh;
    cudaGetSymbolAddress((void**)&qkvh, g_qkvh);
    cudaGetSymbolAddress((void**)&ah, g_a_hi);
    cudaGetSymbolAddress((void**)&bhp, g_b_hi);
    cudaGetSymbolAddress((void**)&qh, g_q_hi);
    cudaGetSymbolAddress((void**)&kh, g_k_hi);

    cudaFuncSetAttribute(gemm_t<2, 3, 4, true>, cudaFuncAttributeMaxDynamicSharedMemorySize, GEMM1_SMEM);
    cudaFuncSetAttribute(gemm_t<1, 2, 4, false>, cudaFuncAttributeMaxDynamicSharedMemorySize, GEMM2_SMEM);
    cudaFuncSetAttribute(attn_mma, cudaFuncAttributeMaxDynamicSharedMemorySize, ATTN_SMEM);

    // 1. round x -> a plane, w_in -> b plane (fp16)
    tohalf_kernel<<<(ROWS * HID / 4 + 255) / 256, 256>>>(x, ah, ROWS * HID / 4);
    tohalf_kernel<<<(QKV_W * HID / 4 + 255) / 256, 256>>>(w_in, bhp, QKV_W * HID / 4);

    // 2. QKV = x @ w_in^T  -> fp16 directly (128x192 tiles, 1024 CTAs)
    gemm_t<2, 3, 4, true><<<(ROWS / 128) * (QKV_W / 192), 512, GEMM1_SMEM>>>(
        ah, bhp, qkvh, ROWS, QKV_W, ROWS / 128);

    // 3. tables + norm/rope on fp16 QKV (Q pre-scaled by log2e)
    rope_table_kernel<<<(S_ * HALF + 255) / 256, 256>>>();
    normrope_kernel<<<ROWS, 256>>>(qkvh, qnw, knw, qh, kh);

    // 4. attention (V read straight from fp16 QKV, transposed via ldsm.trans)
    attn_mma<<<dim3(S_ / 64, B_ * NH), 128, ATTN_SMEM>>>(qh, kh, qkvh, ah);

    // 5. round w_out -> b plane; out = O @ w_out^T (fp32 out)
    tohalf_kernel<<<(HID * HID / 4 + 255) / 256, 256>>>(w_out, bhp, HID * HID / 4);
    gemm_t<1, 2, 4, false><<<(ROWS / 64) * (HID / 128), 512, GEMM2_SMEM>>>(
        ah, bhp, out, ROWS, HID, ROWS / 64);
}